// round 8
// baseline (speedup 1.0000x reference)
#include <cuda_runtime.h>
#include <cuda_bf16.h>
#include <math.h>
#include <stdint.h>

#define N_NODES  50000
#define N_EDGES  800000
#define N_GRAPHS 256
#define DMAX     512
#define GRUH     256
#define NPART    196   // ceil(50000/256)

// ---------------- scratch (device globals; no allocation allowed) ----------------
__device__ __align__(16) float g_h   [(size_t)N_NODES * DMAX];
__device__ __align__(16) float g_buf0[(size_t)N_NODES * DMAX];
__device__ __align__(16) float g_buf1[(size_t)N_NODES * DMAX];
__device__ float g_dinv[N_NODES];
__device__ int   g_counts[N_NODES];
__device__ int   g_cursor[N_NODES];
__device__ int   g_offs[N_NODES + 1];
__device__ int   g_part[NPART];
__device__ int   g_csrc[N_EDGES];
__device__ int   g_gcounts[N_GRAPHS];
__device__ int   g_goffs[N_GRAPHS + 1];
__device__ float g_gate[N_NODES];
__device__ __align__(16) float g_emb[N_GRAPHS * 512];
__device__ float g_h1[N_GRAPHS * GRUH];
__device__ float g_h2[N_GRAPHS * GRUH];
__device__ int   g_is64;

// ---------------- index-width detection (parallel: 1 warp, MLP=4/lane) ----------------
__global__ void detect_kernel(const int* __restrict__ ei_raw) {
    int lane = threadIdx.x;
    int bad = 0;
#pragma unroll
    for (int i = 0; i < 4; i++) bad |= ei_raw[2 * (lane + i * 32) + 1];
    unsigned m = __ballot_sync(0xffffffffu, bad != 0);
    if (lane == 0) g_is64 = (m == 0) ? 1 : 0;
}

__device__ __forceinline__ int load_idx(const void* p, long long i, int is64) {
    return is64 ? (int)((const long long*)p)[i] : ((const int*)p)[i];
}

// ---------------- init (also seeds g_gate with gate bias) ----------------
__global__ void init_kernel(const float* __restrict__ gb) {
    int i = blockIdx.x * blockDim.x + threadIdx.x;
    int stride = gridDim.x * blockDim.x;
    float gbias = gb[0];
    for (int k = i; k < N_NODES; k += stride) {
        g_counts[k] = 0; g_cursor[k] = 0; g_gate[k] = gbias;
    }
    for (int k = i; k < N_GRAPHS; k += stride) g_gcounts[k] = 0;
}

__global__ void count_kernel(const void* __restrict__ ei, const void* __restrict__ batch) {
    int is64 = g_is64;
    int i = blockIdx.x * blockDim.x + threadIdx.x;
    int stride = gridDim.x * blockDim.x;
    for (int e = i; e < N_EDGES; e += stride) {
        int d = load_idx(ei, (long long)N_EDGES + e, is64);   // dst = edge_index[1]
        atomicAdd(&g_counts[d], 1);
    }
    for (int v = i; v < N_NODES; v += stride) {
        int b = load_idx(batch, v, is64);
        atomicAdd(&g_gcounts[b], 1);
    }
}

// -------- hierarchical exclusive scan of g_counts -> g_offs (+ fused dinv) --------
__global__ void __launch_bounds__(256) part_sum_kernel() {
    __shared__ int red[8];
    int b = blockIdx.x, t = threadIdx.x;
    int i = b * 256 + t;
    int cnt = (i < N_NODES) ? g_counts[i] : 0;
    if (i < N_NODES) g_dinv[i] = rsqrtf((float)(cnt + 1));  // +1 self-loop
    int v = cnt;
#pragma unroll
    for (int o = 16; o > 0; o >>= 1) v += __shfl_xor_sync(0xffffffffu, v, o);
    if ((t & 31) == 0) red[t >> 5] = v;
    __syncthreads();
    if (t == 0) {
        int s = 0;
#pragma unroll
        for (int w = 0; w < 8; w++) s += red[w];
        g_part[b] = s;
    }
}

__global__ void __launch_bounds__(256) scan_parts_kernel() {
    __shared__ int sh[256];
    int t = threadIdx.x;
    int v = (t < NPART) ? g_part[t] : 0;
    sh[t] = v;
    __syncthreads();
    for (int d = 1; d < 256; d <<= 1) {
        int x = (t >= d) ? sh[t - d] : 0;
        __syncthreads();
        sh[t] += x;
        __syncthreads();
    }
    if (t < NPART) g_part[t] = sh[t] - v;
    __syncthreads();
    int gc = g_gcounts[t];
    sh[t] = gc;
    __syncthreads();
    for (int d = 1; d < 256; d <<= 1) {
        int x = (t >= d) ? sh[t - d] : 0;
        __syncthreads();
        sh[t] += x;
        __syncthreads();
    }
    g_goffs[t] = sh[t] - gc;
    if (t == 255) g_goffs[256] = sh[255];
}

__global__ void __launch_bounds__(256) final_scan_kernel() {
    __shared__ int sh[256];
    int b = blockIdx.x, t = threadIdx.x;
    int i = b * 256 + t;
    int v = (i < N_NODES) ? g_counts[i] : 0;
    sh[t] = v;
    __syncthreads();
    for (int d = 1; d < 256; d <<= 1) {
        int x = (t >= d) ? sh[t - d] : 0;
        __syncthreads();
        sh[t] += x;
        __syncthreads();
    }
    int base = g_part[b];
    if (i < N_NODES) g_offs[i] = base + sh[t] - v;
    if (i == N_NODES - 1) g_offs[N_NODES] = base + sh[t];
}

__global__ void fill_kernel(const void* __restrict__ ei) {
    int is64 = g_is64;
    int i = blockIdx.x * blockDim.x + threadIdx.x;
    int stride = gridDim.x * blockDim.x;
    for (int e = i; e < N_EDGES; e += stride) {
        int d = load_idx(ei, (long long)N_EDGES + e, is64);
        int s = load_idx(ei, e, is64);
        int pos = g_offs[d] + atomicAdd(&g_cursor[d], 1);
        g_csrc[pos] = s;
    }
}

// ------------- GCN aggregation BEFORE transform (Agg(X)·W == Agg(X·W)) -------------
__global__ void __launch_bounds__(256) agg64w_kernel(const float* __restrict__ h,
                                                     float* __restrict__ out)
{
    int node = blockIdx.x * 8 + (threadIdx.x >> 5);
    if (node >= N_NODES) return;
    int lane = threadIdx.x & 31;
    float wd = g_dinv[node];
    float2 acc = *(const float2*)(h + (size_t)node * 64 + lane * 2);
    float ws = wd * wd;
    acc.x *= ws; acc.y *= ws;
    int e = g_offs[node], e1 = g_offs[node + 1];
    for (; e + 2 <= e1; e += 2) {
        int s0 = g_csrc[e], s1 = g_csrc[e + 1];
        float w0 = g_dinv[s0] * wd, w1 = g_dinv[s1] * wd;
        float2 v0 = *(const float2*)(h + (size_t)s0 * 64 + lane * 2);
        float2 v1 = *(const float2*)(h + (size_t)s1 * 64 + lane * 2);
        acc.x += v0.x * w0 + v1.x * w1;
        acc.y += v0.y * w0 + v1.y * w1;
    }
    if (e < e1) {
        int s0 = g_csrc[e];
        float w0 = g_dinv[s0] * wd;
        float2 v0 = *(const float2*)(h + (size_t)s0 * 64 + lane * 2);
        acc.x += v0.x * w0; acc.y += v0.y * w0;
    }
    *(float2*)(out + (size_t)node * 64 + lane * 2) = acc;
}

__global__ void __launch_bounds__(256) agg128w_kernel(const float* __restrict__ h,
                                                      float* __restrict__ out)
{
    int node = blockIdx.x * 8 + (threadIdx.x >> 5);
    if (node >= N_NODES) return;
    int lane = threadIdx.x & 31;
    float wd = g_dinv[node];
    float4 acc = *(const float4*)(h + (size_t)node * 128 + lane * 4);
    float ws = wd * wd;
    acc.x *= ws; acc.y *= ws; acc.z *= ws; acc.w *= ws;
    int e = g_offs[node], e1 = g_offs[node + 1];
    for (; e + 2 <= e1; e += 2) {
        int s0 = g_csrc[e], s1 = g_csrc[e + 1];
        float w0 = g_dinv[s0] * wd, w1 = g_dinv[s1] * wd;
        float4 v0 = *(const float4*)(h + (size_t)s0 * 128 + lane * 4);
        float4 v1 = *(const float4*)(h + (size_t)s1 * 128 + lane * 4);
        acc.x += v0.x * w0 + v1.x * w1;
        acc.y += v0.y * w0 + v1.y * w1;
        acc.z += v0.z * w0 + v1.z * w1;
        acc.w += v0.w * w0 + v1.w * w1;
    }
    if (e < e1) {
        int s0 = g_csrc[e];
        float w0 = g_dinv[s0] * wd;
        float4 v0 = *(const float4*)(h + (size_t)s0 * 128 + lane * 4);
        acc.x += v0.x * w0; acc.y += v0.y * w0;
        acc.z += v0.z * w0; acc.w += v0.w * w0;
    }
    *(float4*)(out + (size_t)node * 128 + lane * 4) = acc;
}

__global__ void __launch_bounds__(256) agg256w_kernel(const float* __restrict__ h,
                                                      float* __restrict__ out)
{
    int node = blockIdx.x * 8 + (threadIdx.x >> 5);
    if (node >= N_NODES) return;
    int lane = threadIdx.x & 31;
    float wd = g_dinv[node];
    const float* rown = h + (size_t)node * 256;
    float4 a0 = *(const float4*)(rown + lane * 4);
    float4 a1 = *(const float4*)(rown + 128 + lane * 4);
    float ws = wd * wd;
    a0.x *= ws; a0.y *= ws; a0.z *= ws; a0.w *= ws;
    a1.x *= ws; a1.y *= ws; a1.z *= ws; a1.w *= ws;
    int e = g_offs[node], e1 = g_offs[node + 1];
    for (; e + 2 <= e1; e += 2) {
        int s0 = g_csrc[e], s1 = g_csrc[e + 1];
        float w0 = g_dinv[s0] * wd, w1 = g_dinv[s1] * wd;
        const float* r0 = h + (size_t)s0 * 256;
        const float* r1 = h + (size_t)s1 * 256;
        float4 u0 = *(const float4*)(r0 + lane * 4);
        float4 u1 = *(const float4*)(r0 + 128 + lane * 4);
        float4 v0 = *(const float4*)(r1 + lane * 4);
        float4 v1 = *(const float4*)(r1 + 128 + lane * 4);
        a0.x += u0.x * w0 + v0.x * w1; a0.y += u0.y * w0 + v0.y * w1;
        a0.z += u0.z * w0 + v0.z * w1; a0.w += u0.w * w0 + v0.w * w1;
        a1.x += u1.x * w0 + v1.x * w1; a1.y += u1.y * w0 + v1.y * w1;
        a1.z += u1.z * w0 + v1.z * w1; a1.w += u1.w * w0 + v1.w * w1;
    }
    if (e < e1) {
        int s0 = g_csrc[e];
        float w0 = g_dinv[s0] * wd;
        const float* r0 = h + (size_t)s0 * 256;
        float4 u0 = *(const float4*)(r0 + lane * 4);
        float4 u1 = *(const float4*)(r0 + 128 + lane * 4);
        a0.x += u0.x * w0; a0.y += u0.y * w0; a0.z += u0.z * w0; a0.w += u0.w * w0;
        a1.x += u1.x * w0; a1.y += u1.y * w0; a1.z += u1.z * w0; a1.w += u1.w * w0;
    }
    float* ro = out + (size_t)node * 256;
    *(float4*)(ro + lane * 4) = a0;
    *(float4*)(ro + 128 + lane * 4) = a1;
}

// ---------------- bf16 3-term split helpers ----------------
__device__ __forceinline__ void split_bf16(float x, __nv_bfloat16& h, __nv_bfloat16& l) {
    h = __float2bfloat16(x);
    l = __float2bfloat16(x - __bfloat162float(h));
}
__device__ __forceinline__ uint32_t pk_bf(__nv_bfloat16 a, __nv_bfloat16 b) {
    __nv_bfloat162 v(a, b);
    return *(uint32_t*)&v;
}
__device__ __forceinline__ void mma_bf16(float* c, const uint32_t* a, const uint32_t* b) {
    asm volatile(
        "mma.sync.aligned.m16n8k16.row.col.f32.bf16.bf16.f32 "
        "{%0,%1,%2,%3}, {%4,%5,%6,%7}, {%8,%9}, {%0,%1,%2,%3};"
        : "+f"(c[0]), "+f"(c[1]), "+f"(c[2]), "+f"(c[3])
        : "r"(a[0]), "r"(a[1]), "r"(a[2]), "r"(a[3]), "r"(b[0]), "r"(b[1]));
}

// ---- GEMM + bias + ReLU (+ optional fused gate dot) via bf16 tensor cores ----
// C = relu(A@B + bias); if gatew != nullptr also g_gate[row] += sum_col C[row,col]*gatew[col]
// CTA tile 128x128, BK=32, register double-buffered; 8 warps 2(M)x4(N).
#define ASTR2 40
#define BSTR 132

__global__ void __launch_bounds__(256) gemm_tc_kernel(
    const float* __restrict__ A, const float* __restrict__ B,
    const float* __restrict__ bias, float* __restrict__ C,
    const float* __restrict__ gatew,
    int M, int N, int K)
{
    __shared__ __align__(16) __nv_bfloat16 Ah[128 * ASTR2];
    __shared__ __align__(16) __nv_bfloat16 Al[128 * ASTR2];
    __shared__ __align__(16) float Bs[32 * BSTR];
    __shared__ float sgate[128];

    int tid = threadIdx.x;
    int lane = tid & 31;
    int wid = tid >> 5;
    int warp_m = wid >> 2;         // 0..1
    int warp_n = wid & 3;          // 0..3
    int g = lane >> 2;             // group 0..7
    int t = lane & 3;              // thread-in-group 0..3
    int row0 = blockIdx.x * 128;
    int col0 = blockIdx.y * 128;

    if (gatew && tid < 128) sgate[tid] = 0.f;

    float acc[4][4][4];
#pragma unroll
    for (int i = 0; i < 4; i++)
#pragma unroll
        for (int j = 0; j < 4; j++)
#pragma unroll
            for (int r = 0; r < 4; r++) acc[i][j][r] = 0.f;

    // register prefetch buffers
    float4 pa[4], pb[4];

    // prefetch k0 = 0
#pragma unroll
    for (int l = 0; l < 4; l++) {
        int f = tid + l * 256;
        int r = f >> 3, c4 = f & 7;
        int grow = row0 + r;
        pa[l] = make_float4(0.f, 0.f, 0.f, 0.f);
        if (grow < M) pa[l] = *(const float4*)(A + (size_t)grow * K + c4 * 4);
    }
#pragma unroll
    for (int l = 0; l < 4; l++) {
        int f = tid + l * 256;
        int kk = f >> 5, c4 = f & 31;
        pb[l] = *(const float4*)(B + (size_t)kk * N + col0 + c4 * 4);
    }

    for (int k0 = 0; k0 < K; k0 += 32) {
        // store prefetched tiles to smem (A split to bf16 hi/lo)
#pragma unroll
        for (int l = 0; l < 4; l++) {
            int f = tid + l * 256;
            int r = f >> 3, c4 = f & 7;
            float4 v = pa[l];
            __nv_bfloat16 h0, l0, h1, l1, h2, l2, h3, l3;
            split_bf16(v.x, h0, l0); split_bf16(v.y, h1, l1);
            split_bf16(v.z, h2, l2); split_bf16(v.w, h3, l3);
            int base = r * ASTR2 + c4 * 4;
            *(uint32_t*)&Ah[base]     = pk_bf(h0, h1);
            *(uint32_t*)&Ah[base + 2] = pk_bf(h2, h3);
            *(uint32_t*)&Al[base]     = pk_bf(l0, l1);
            *(uint32_t*)&Al[base + 2] = pk_bf(l2, l3);
        }
#pragma unroll
        for (int l = 0; l < 4; l++) {
            int f = tid + l * 256;
            int kk = f >> 5, c4 = f & 31;
            *(float4*)&Bs[kk * BSTR + c4 * 4] = pb[l];
        }
        __syncthreads();

        // prefetch next iteration's tiles while computing on smem
        int kn = k0 + 32;
        if (kn < K) {
#pragma unroll
            for (int l = 0; l < 4; l++) {
                int f = tid + l * 256;
                int r = f >> 3, c4 = f & 7;
                int grow = row0 + r;
                pa[l] = make_float4(0.f, 0.f, 0.f, 0.f);
                if (grow < M) pa[l] = *(const float4*)(A + (size_t)grow * K + kn + c4 * 4);
            }
#pragma unroll
            for (int l = 0; l < 4; l++) {
                int f = tid + l * 256;
                int kk = f >> 5, c4 = f & 31;
                pb[l] = *(const float4*)(B + (size_t)(kn + kk) * N + col0 + c4 * 4);
            }
        }

#pragma unroll
        for (int kc = 0; kc < 2; kc++) {       // two k16 chunks per BK=32
            uint32_t bh[4][2], bl[4][2];
#pragma unroll
            for (int tn = 0; tn < 4; tn++) {
                int n = warp_n * 32 + tn * 8 + g;
                const float* bp = &Bs[(kc * 16 + 2 * t) * BSTR + n];
                float b0 = bp[0];
                float b1 = bp[BSTR];
                float b2 = bp[8 * BSTR];
                float b3 = bp[9 * BSTR];
                __nv_bfloat16 h0, l0, h1, l1, h2, l2, h3, l3;
                split_bf16(b0, h0, l0); split_bf16(b1, h1, l1);
                split_bf16(b2, h2, l2); split_bf16(b3, h3, l3);
                bh[tn][0] = pk_bf(h0, h1); bh[tn][1] = pk_bf(h2, h3);
                bl[tn][0] = pk_bf(l0, l1); bl[tn][1] = pk_bf(l2, l3);
            }
#pragma unroll
            for (int tm = 0; tm < 4; tm++) {
                int row = warp_m * 64 + tm * 16 + g;
                int base = row * ASTR2 + kc * 16 + 2 * t;
                uint32_t ah[4], al[4];
                ah[0] = *(const uint32_t*)&Ah[base];
                ah[1] = *(const uint32_t*)&Ah[base + 8 * ASTR2];
                ah[2] = *(const uint32_t*)&Ah[base + 8];
                ah[3] = *(const uint32_t*)&Ah[base + 8 * ASTR2 + 8];
                al[0] = *(const uint32_t*)&Al[base];
                al[1] = *(const uint32_t*)&Al[base + 8 * ASTR2];
                al[2] = *(const uint32_t*)&Al[base + 8];
                al[3] = *(const uint32_t*)&Al[base + 8 * ASTR2 + 8];
#pragma unroll
                for (int tn = 0; tn < 4; tn++) {
                    mma_bf16(acc[tm][tn], al, bh[tn]);
                    mma_bf16(acc[tm][tn], ah, bl[tn]);
                    mma_bf16(acc[tm][tn], ah, bh[tn]);
                }
            }
        }
        __syncthreads();
    }

    // epilogue: bias + relu store (+ gate partial dot)
    float bv[4][2], gwv[4][2];
#pragma unroll
    for (int tn = 0; tn < 4; tn++) {
        int col = col0 + warp_n * 32 + tn * 8 + 2 * t;
        bv[tn][0] = bias[col];
        bv[tn][1] = bias[col + 1];
        if (gatew) { gwv[tn][0] = gatew[col]; gwv[tn][1] = gatew[col + 1]; }
    }
#pragma unroll
    for (int tm = 0; tm < 4; tm++) {
        int row = row0 + warp_m * 64 + tm * 16 + g;
        float p0 = 0.f, p1 = 0.f;
#pragma unroll
        for (int tn = 0; tn < 4; tn++) {
            int col = col0 + warp_n * 32 + tn * 8 + 2 * t;
            float v0 = fmaxf(acc[tm][tn][0] + bv[tn][0], 0.f);
            float v1 = fmaxf(acc[tm][tn][1] + bv[tn][1], 0.f);
            float v2 = fmaxf(acc[tm][tn][2] + bv[tn][0], 0.f);
            float v3 = fmaxf(acc[tm][tn][3] + bv[tn][1], 0.f);
            if (row < M)     *(float2*)(C + (size_t)row * N + col)       = make_float2(v0, v1);
            if (row + 8 < M) *(float2*)(C + (size_t)(row + 8) * N + col) = make_float2(v2, v3);
            if (gatew) {
                p0 += v0 * gwv[tn][0] + v1 * gwv[tn][1];
                p1 += v2 * gwv[tn][0] + v3 * gwv[tn][1];
            }
        }
        if (gatew) {
            // reduce across the 4 lanes (t = 0..3) sharing this row
            p0 += __shfl_xor_sync(0xffffffffu, p0, 1);
            p0 += __shfl_xor_sync(0xffffffffu, p0, 2);
            p1 += __shfl_xor_sync(0xffffffffu, p1, 1);
            p1 += __shfl_xor_sync(0xffffffffu, p1, 2);
            if (t == 0) {
                int rl = warp_m * 64 + tm * 16 + g;
                atomicAdd(&sgate[rl], p0);
                atomicAdd(&sgate[rl + 8], p1);
            }
        }
    }
    if (gatew) {
        __syncthreads();
        if (tid < 128 && row0 + tid < M) atomicAdd(&g_gate[row0 + tid], sgate[tid]);
    }
}

// ---------------- segment softmax + weighted sum -> graph embeddings [G, 512] ----------------
__global__ void __launch_bounds__(256) softmax_emb_kernel()
{
    __shared__ float red[8];
    __shared__ float salpha[256];
    __shared__ float bcast;
    int g = blockIdx.x, tid = threadIdx.x;
    int lane = tid & 31, wid = tid >> 5;
    int s = g_goffs[g], e = g_goffs[g + 1];

    float m = -INFINITY;
    for (int i = s + tid; i < e; i += 256) m = fmaxf(m, g_gate[i]);
#pragma unroll
    for (int o = 16; o > 0; o >>= 1) m = fmaxf(m, __shfl_xor_sync(0xffffffffu, m, o));
    if (lane == 0) red[wid] = m;
    __syncthreads();
    if (wid == 0) {
        float x = (lane < 8) ? red[lane] : -INFINITY;
#pragma unroll
        for (int o = 4; o > 0; o >>= 1) x = fmaxf(x, __shfl_xor_sync(0xffffffffu, x, o));
        if (lane == 0) bcast = x;
    }
    __syncthreads();
    m = bcast;

    float sum = 0.f;
    for (int i = s + tid; i < e; i += 256) sum += expf(g_gate[i] - m);
#pragma unroll
    for (int o = 16; o > 0; o >>= 1) sum += __shfl_xor_sync(0xffffffffu, sum, o);
    if (lane == 0) red[wid] = sum;
    __syncthreads();
    if (wid == 0) {
        float x = (lane < 8) ? red[lane] : 0.f;
#pragma unroll
        for (int o = 4; o > 0; o >>= 1) x += __shfl_xor_sync(0xffffffffu, x, o);
        if (lane == 0) bcast = x;
    }
    __syncthreads();
    float inv = (e > s) ? 1.f / bcast : 0.f;

    float acc0 = 0.f, acc1 = 0.f;
    for (int start = s; start < e; start += 256) {
        int i = start + tid;
        salpha[tid] = (i < e) ? expf(g_gate[i] - m) * inv : 0.f;
        __syncthreads();
        int cnt = min(256, e - start);
        for (int k = 0; k < cnt; k++) {
            float a = salpha[k];
            const float* xr = g_buf0 + (size_t)(start + k) * 512;
            acc0 += xr[tid] * a;
            acc1 += xr[tid + 256] * a;
        }
        __syncthreads();
    }
    g_emb[g * 512 + tid] = acc0;
    g_emb[g * 512 + 256 + tid] = acc1;
}

// ---------------- GRU cell with h=0: out = (1-z)*n ; gh = bhh (whh unused) ----------------
__global__ void __launch_bounds__(256) gru_cell_kernel(
    const float* __restrict__ xin, const float* __restrict__ wih,
    const float* __restrict__ bih, const float* __restrict__ bhh,
    float* __restrict__ hout, int K)
{
    int warp = (blockIdx.x * blockDim.x + threadIdx.x) >> 5;
    int lane = threadIdx.x & 31;
    if (warp >= N_GRAPHS * GRUH) return;
    int g = warp >> 8;
    int j = warp & 255;
    const float* xg = xin + (size_t)g * K;
    const float* wr = wih + (size_t)j * K;
    const float* wz = wih + (size_t)(j + 256) * K;
    const float* wn = wih + (size_t)(j + 512) * K;
    float sr = 0.f, sz = 0.f, sn = 0.f;
    for (int k = lane; k < K; k += 32) {
        float xv = xg[k];
        sr += xv * wr[k];
        sz += xv * wz[k];
        sn += xv * wn[k];
    }
#pragma unroll
    for (int o = 16; o > 0; o >>= 1) {
        sr += __shfl_xor_sync(0xffffffffu, sr, o);
        sz += __shfl_xor_sync(0xffffffffu, sz, o);
        sn += __shfl_xor_sync(0xffffffffu, sn, o);
    }
    if (lane == 0) {
        float r = 1.f / (1.f + expf(-(sr + bih[j] + bhh[j])));
        float z = 1.f / (1.f + expf(-(sz + bih[j + 256] + bhh[j + 256])));
        float n = tanhf(sn + bih[j + 512] + r * bhh[j + 512]);
        hout[g * GRUH + j] = (1.f - z) * n;
    }
}

// ---------------- output projection ----------------
__global__ void __launch_bounds__(256) proj_kernel(
    const float* __restrict__ h2, const float* __restrict__ pw,
    const float* __restrict__ pb, float* __restrict__ out)
{
    int warp = (blockIdx.x * blockDim.x + threadIdx.x) >> 5;
    int lane = threadIdx.x & 31;
    if (warp >= N_GRAPHS * 512) return;
    int g = warp >> 9;
    int o = warp & 511;
    const float* hr = h2 + (size_t)g * 256;
    const float* wr = pw + (size_t)o * 256;
    float s = 0.f;
#pragma unroll 4
    for (int k = lane; k < 256; k += 32) s += hr[k] * wr[k];
#pragma unroll
    for (int d = 16; d > 0; d >>= 1) s += __shfl_xor_sync(0xffffffffu, s, d);
    if (lane == 0) out[g * 512 + o] = s + pb[o];
}

// ---------------- launch ----------------
extern "C" void kernel_launch(void* const* d_in, const int* in_sizes, int n_in,
                              void* d_out, int out_size)
{
    const float* x       = (const float*)d_in[0];
    const void*  ei      = d_in[1];
    const void*  batch   = d_in[2];
    const float* w0 = (const float*)d_in[3];  const float* b0 = (const float*)d_in[4];
    const float* w1 = (const float*)d_in[5];  const float* b1 = (const float*)d_in[6];
    const float* w2 = (const float*)d_in[7];  const float* b2 = (const float*)d_in[8];
    const float* gate_w = (const float*)d_in[9];
    const float* gate_b = (const float*)d_in[10];
    const float* wih0 = (const float*)d_in[11];
    const float* bih0 = (const float*)d_in[13];
    const float* bhh0 = (const float*)d_in[14];
    const float* wih1 = (const float*)d_in[15];
    const float* bih1 = (const float*)d_in[17];
    const float* bhh1 = (const float*)d_in[18];
    const float* proj_w = (const float*)d_in[19];
    const float* proj_b = (const float*)d_in[20];
    float* out = (float*)d_out;

    float *pH, *pB0, *pB1, *pEmb, *pH1, *pH2;
    cudaGetSymbolAddress((void**)&pH,   g_h);
    cudaGetSymbolAddress((void**)&pB0,  g_buf0);
    cudaGetSymbolAddress((void**)&pB1,  g_buf1);
    cudaGetSymbolAddress((void**)&pEmb, g_emb);
    cudaGetSymbolAddress((void**)&pH1,  g_h1);
    cudaGetSymbolAddress((void**)&pH2,  g_h2);

    // preprocessing: index width, degrees+dinv, CSR offsets (hierarchical scan)
    detect_kernel<<<1, 32>>>((const int*)ei);
    init_kernel<<<256, 256>>>(gate_b);
    count_kernel<<<1024, 256>>>(ei, batch);
    part_sum_kernel<<<NPART, 256>>>();
    scan_parts_kernel<<<1, 256>>>();
    final_scan_kernel<<<NPART, 256>>>();
    fill_kernel<<<1024, 256>>>(ei);

    int gM = (N_NODES + 127) / 128;
    int gAgg = (N_NODES + 7) / 8;

    // layer 0: Agg(x)[64] -> GEMM 64->128 + b0 + relu
    agg64w_kernel<<<gAgg, 256>>>(x, pB1);
    gemm_tc_kernel<<<dim3(gM, 1), 256>>>(pB1, w0, b0, pH, nullptr, N_NODES, 128, 64);
    // layer 1: Agg[128] -> GEMM 128->256 + b1 + relu
    agg128w_kernel<<<gAgg, 256>>>(pH, pB1);
    gemm_tc_kernel<<<dim3(gM, 2), 256>>>(pB1, w1, b1, pH, nullptr, N_NODES, 256, 128);
    // layer 2: Agg[256] -> GEMM 256->512 + b2 + relu, fused gate dot
    agg256w_kernel<<<gAgg, 256>>>(pH, pB1);
    gemm_tc_kernel<<<dim3(gM, 4), 256>>>(pB1, w2, b2, pB0, gate_w, N_NODES, 512, 256);

    // attentional aggregation (gate scores already in g_gate)
    softmax_emb_kernel<<<N_GRAPHS, 256>>>();

    // GRU (seq_len=1, h0=0 for both cells) + projection
    gru_cell_kernel<<<(N_GRAPHS * GRUH * 32) / 256, 256>>>(pEmb, wih0, bih0, bhh0, pH1, 512);
    gru_cell_kernel<<<(N_GRAPHS * GRUH * 32) / 256, 256>>>(pH1, wih1, bih1, bhh1, pH2, 256);
    proj_kernel<<<(N_GRAPHS * 512 * 32) / 256, 256>>>(pH2, proj_w, proj_b, out);
}

// round 9
// speedup vs baseline: 1.0681x; 1.0681x over previous
#include <cuda_runtime.h>
#include <cuda_bf16.h>
#include <cuda_fp16.h>
#include <math.h>
#include <stdint.h>

#define N_NODES  50000
#define N_EDGES  800000
#define N_GRAPHS 256
#define DMAX     512
#define GRUH     256
#define NPART    196   // ceil(50000/256)

// ---------------- scratch (device globals; no allocation allowed) ----------------
__device__ __align__(16) float g_h   [(size_t)N_NODES * DMAX];   // also used as fp16 buffer (cast)
__device__ __align__(16) float g_buf0[(size_t)N_NODES * DMAX];
__device__ __align__(16) float g_buf1[(size_t)N_NODES * DMAX];
__device__ float g_dinv[N_NODES];
__device__ int   g_counts[N_NODES];
__device__ int   g_cursor[N_NODES];
__device__ int   g_offs[N_NODES + 1];
__device__ int   g_part[NPART];
__device__ int   g_csrc[N_EDGES];
__device__ int   g_gcounts[N_GRAPHS];
__device__ int   g_goffs[N_GRAPHS + 1];
__device__ float g_gate[N_NODES];
__device__ __align__(16) float g_emb[N_GRAPHS * 512];
__device__ float g_h1[N_GRAPHS * GRUH];
__device__ float g_h2[N_GRAPHS * GRUH];
__device__ int   g_is64;

__device__ __forceinline__ int load_idx(const void* p, long long i, int is64) {
    return is64 ? (int)((const long long*)p)[i] : ((const int*)p)[i];
}

// ---------------- init (+ fused index-width detect, + seeds g_gate with bias) ----------------
__global__ void init_kernel(const int* __restrict__ ei_raw, const float* __restrict__ gb) {
    int i = blockIdx.x * blockDim.x + threadIdx.x;
    int stride = gridDim.x * blockDim.x;
    if (blockIdx.x == 0 && threadIdx.x < 32) {
        int lane = threadIdx.x;
        int bad = 0;
#pragma unroll
        for (int k = 0; k < 4; k++) bad |= ei_raw[2 * (lane + k * 32) + 1];
        unsigned m = __ballot_sync(0xffffffffu, bad != 0);
        if (lane == 0) g_is64 = (m == 0) ? 1 : 0;
    }
    float gbias = gb[0];
    for (int k = i; k < N_NODES; k += stride) {
        g_counts[k] = 0; g_cursor[k] = 0; g_gate[k] = gbias;
    }
    for (int k = i; k < N_GRAPHS; k += stride) g_gcounts[k] = 0;
}

__global__ void count_kernel(const void* __restrict__ ei, const void* __restrict__ batch) {
    int is64 = g_is64;
    int i = blockIdx.x * blockDim.x + threadIdx.x;
    int stride = gridDim.x * blockDim.x;
    for (int e = i; e < N_EDGES; e += stride) {
        int d = load_idx(ei, (long long)N_EDGES + e, is64);   // dst = edge_index[1]
        atomicAdd(&g_counts[d], 1);
    }
    for (int v = i; v < N_NODES; v += stride) {
        int b = load_idx(batch, v, is64);
        atomicAdd(&g_gcounts[b], 1);
    }
}

// -------- hierarchical exclusive scan of g_counts -> g_offs (+ fused dinv) --------
__global__ void __launch_bounds__(256) part_sum_kernel() {
    __shared__ int red[8];
    int b = blockIdx.x, t = threadIdx.x;
    int i = b * 256 + t;
    int cnt = (i < N_NODES) ? g_counts[i] : 0;
    if (i < N_NODES) g_dinv[i] = rsqrtf((float)(cnt + 1));  // +1 self-loop
    int v = cnt;
#pragma unroll
    for (int o = 16; o > 0; o >>= 1) v += __shfl_xor_sync(0xffffffffu, v, o);
    if ((t & 31) == 0) red[t >> 5] = v;
    __syncthreads();
    if (t == 0) {
        int s = 0;
#pragma unroll
        for (int w = 0; w < 8; w++) s += red[w];
        g_part[b] = s;
    }
}

__global__ void __launch_bounds__(256) scan_parts_kernel() {
    __shared__ int sh[256];
    int t = threadIdx.x;
    int v = (t < NPART) ? g_part[t] : 0;
    sh[t] = v;
    __syncthreads();
    for (int d = 1; d < 256; d <<= 1) {
        int x = (t >= d) ? sh[t - d] : 0;
        __syncthreads();
        sh[t] += x;
        __syncthreads();
    }
    if (t < NPART) g_part[t] = sh[t] - v;
    __syncthreads();
    int gc = g_gcounts[t];
    sh[t] = gc;
    __syncthreads();
    for (int d = 1; d < 256; d <<= 1) {
        int x = (t >= d) ? sh[t - d] : 0;
        __syncthreads();
        sh[t] += x;
        __syncthreads();
    }
    g_goffs[t] = sh[t] - gc;
    if (t == 255) g_goffs[256] = sh[255];
}

__global__ void __launch_bounds__(256) final_scan_kernel() {
    __shared__ int sh[256];
    int b = blockIdx.x, t = threadIdx.x;
    int i = b * 256 + t;
    int v = (i < N_NODES) ? g_counts[i] : 0;
    sh[t] = v;
    __syncthreads();
    for (int d = 1; d < 256; d <<= 1) {
        int x = (t >= d) ? sh[t - d] : 0;
        __syncthreads();
        sh[t] += x;
        __syncthreads();
    }
    int base = g_part[b];
    if (i < N_NODES) g_offs[i] = base + sh[t] - v;
    if (i == N_NODES - 1) g_offs[N_NODES] = base + sh[t];
}

__global__ void fill_kernel(const void* __restrict__ ei) {
    int is64 = g_is64;
    int i = blockIdx.x * blockDim.x + threadIdx.x;
    int stride = gridDim.x * blockDim.x;
    for (int e = i; e < N_EDGES; e += stride) {
        int d = load_idx(ei, (long long)N_EDGES + e, is64);
        int s = load_idx(ei, e, is64);
        int pos = g_offs[d] + atomicAdd(&g_cursor[d], 1);
        g_csrc[pos] = s;
    }
}

// ------------- GCN aggregation BEFORE transform (Agg(X)·W == Agg(X·W)) -------------
// layer 0: fp32 source (raw x)
__global__ void __launch_bounds__(256) agg64w_kernel(const float* __restrict__ h,
                                                     float* __restrict__ out)
{
    int node = blockIdx.x * 8 + (threadIdx.x >> 5);
    if (node >= N_NODES) return;
    int lane = threadIdx.x & 31;
    float wd = g_dinv[node];
    float2 acc = *(const float2*)(h + (size_t)node * 64 + lane * 2);
    float ws = wd * wd;
    acc.x *= ws; acc.y *= ws;
    int e = g_offs[node], e1 = g_offs[node + 1];
    for (; e + 2 <= e1; e += 2) {
        int s0 = g_csrc[e], s1 = g_csrc[e + 1];
        float w0 = g_dinv[s0] * wd, w1 = g_dinv[s1] * wd;
        float2 v0 = *(const float2*)(h + (size_t)s0 * 64 + lane * 2);
        float2 v1 = *(const float2*)(h + (size_t)s1 * 64 + lane * 2);
        acc.x += v0.x * w0 + v1.x * w1;
        acc.y += v0.y * w0 + v1.y * w1;
    }
    if (e < e1) {
        int s0 = g_csrc[e];
        float w0 = g_dinv[s0] * wd;
        float2 v0 = *(const float2*)(h + (size_t)s0 * 64 + lane * 2);
        acc.x += v0.x * w0; acc.y += v0.y * w0;
    }
    *(float2*)(out + (size_t)node * 64 + lane * 2) = acc;
}

// layers 1/2: fp16 gather source (half the L2 traffic), fp32 accumulation + output
__global__ void __launch_bounds__(256) agg128h_kernel(const __half* __restrict__ h,
                                                      float* __restrict__ out)
{
    int node = blockIdx.x * 8 + (threadIdx.x >> 5);
    if (node >= N_NODES) return;
    int lane = threadIdx.x & 31;
    float wd = g_dinv[node];
    // lane covers 4 consecutive halves = 8B
    const __half2* selfp = (const __half2*)(h + (size_t)node * 128 + lane * 4);
    float2 s0f = __half22float2(selfp[0]);
    float2 s1f = __half22float2(selfp[1]);
    float ws = wd * wd;
    float4 acc = make_float4(s0f.x * ws, s0f.y * ws, s1f.x * ws, s1f.y * ws);
    int e = g_offs[node], e1 = g_offs[node + 1];
    for (; e + 2 <= e1; e += 2) {
        int n0 = g_csrc[e], n1 = g_csrc[e + 1];
        float w0 = g_dinv[n0] * wd, w1 = g_dinv[n1] * wd;
        const __half2* p0 = (const __half2*)(h + (size_t)n0 * 128 + lane * 4);
        const __half2* p1 = (const __half2*)(h + (size_t)n1 * 128 + lane * 4);
        __half2 a0 = p0[0], a1 = p0[1];
        __half2 b0 = p1[0], b1 = p1[1];
        float2 fa0 = __half22float2(a0), fa1 = __half22float2(a1);
        float2 fb0 = __half22float2(b0), fb1 = __half22float2(b1);
        acc.x += fa0.x * w0 + fb0.x * w1;
        acc.y += fa0.y * w0 + fb0.y * w1;
        acc.z += fa1.x * w0 + fb1.x * w1;
        acc.w += fa1.y * w0 + fb1.y * w1;
    }
    if (e < e1) {
        int n0 = g_csrc[e];
        float w0 = g_dinv[n0] * wd;
        const __half2* p0 = (const __half2*)(h + (size_t)n0 * 128 + lane * 4);
        float2 fa0 = __half22float2(p0[0]), fa1 = __half22float2(p0[1]);
        acc.x += fa0.x * w0; acc.y += fa0.y * w0;
        acc.z += fa1.x * w0; acc.w += fa1.y * w0;
    }
    *(float4*)(out + (size_t)node * 128 + lane * 4) = acc;
}

__global__ void __launch_bounds__(256) agg256h_kernel(const __half* __restrict__ h,
                                                      float* __restrict__ out)
{
    int node = blockIdx.x * 8 + (threadIdx.x >> 5);
    if (node >= N_NODES) return;
    int lane = threadIdx.x & 31;
    float wd = g_dinv[node];
    // lane covers 8 consecutive halves = 16B (one uint4)
    float acc[8];
    {
        uint4 sv = *(const uint4*)(h + (size_t)node * 256 + lane * 8);
        const __half2* hp = (const __half2*)&sv;
        float ws = wd * wd;
#pragma unroll
        for (int q = 0; q < 4; q++) {
            float2 f = __half22float2(hp[q]);
            acc[2 * q] = f.x * ws;
            acc[2 * q + 1] = f.y * ws;
        }
    }
    int e = g_offs[node], e1 = g_offs[node + 1];
    for (; e + 2 <= e1; e += 2) {
        int n0 = g_csrc[e], n1 = g_csrc[e + 1];
        float w0 = g_dinv[n0] * wd, w1 = g_dinv[n1] * wd;
        uint4 v0 = *(const uint4*)(h + (size_t)n0 * 256 + lane * 8);
        uint4 v1 = *(const uint4*)(h + (size_t)n1 * 256 + lane * 8);
        const __half2* p0 = (const __half2*)&v0;
        const __half2* p1 = (const __half2*)&v1;
#pragma unroll
        for (int q = 0; q < 4; q++) {
            float2 f0 = __half22float2(p0[q]);
            float2 f1 = __half22float2(p1[q]);
            acc[2 * q]     += f0.x * w0 + f1.x * w1;
            acc[2 * q + 1] += f0.y * w0 + f1.y * w1;
        }
    }
    if (e < e1) {
        int n0 = g_csrc[e];
        float w0 = g_dinv[n0] * wd;
        uint4 v0 = *(const uint4*)(h + (size_t)n0 * 256 + lane * 8);
        const __half2* p0 = (const __half2*)&v0;
#pragma unroll
        for (int q = 0; q < 4; q++) {
            float2 f0 = __half22float2(p0[q]);
            acc[2 * q]     += f0.x * w0;
            acc[2 * q + 1] += f0.y * w0;
        }
    }
    float* ro = out + (size_t)node * 256 + lane * 8;
    *(float4*)(ro)     = make_float4(acc[0], acc[1], acc[2], acc[3]);
    *(float4*)(ro + 4) = make_float4(acc[4], acc[5], acc[6], acc[7]);
}

// ---------------- bf16 3-term split helpers ----------------
__device__ __forceinline__ void split_bf16(float x, __nv_bfloat16& h, __nv_bfloat16& l) {
    h = __float2bfloat16(x);
    l = __float2bfloat16(x - __bfloat162float(h));
}
__device__ __forceinline__ uint32_t pk_bf(__nv_bfloat16 a, __nv_bfloat16 b) {
    __nv_bfloat162 v(a, b);
    return *(uint32_t*)&v;
}
__device__ __forceinline__ void mma_bf16(float* c, const uint32_t* a, const uint32_t* b) {
    asm volatile(
        "mma.sync.aligned.m16n8k16.row.col.f32.bf16.bf16.f32 "
        "{%0,%1,%2,%3}, {%4,%5,%6,%7}, {%8,%9}, {%0,%1,%2,%3};"
        : "+f"(c[0]), "+f"(c[1]), "+f"(c[2]), "+f"(c[3])
        : "r"(a[0]), "r"(a[1]), "r"(a[2]), "r"(a[3]), "r"(b[0]), "r"(b[1]));
}

// ---- GEMM + bias + ReLU via bf16 tensor cores (3-term split) ----
// Output: fp32 to C (if non-null) and/or fp16 to Ch (if non-null).
// If gatew non-null: g_gate[row] += sum_col relu(...)[row,col]*gatew[col].
// CTA tile 128x128, BK=32 (R7 structure: no register prefetch); 8 warps 2(M)x4(N).
#define ASTR2 40
#define BSTR 132

__global__ void __launch_bounds__(256) gemm_tc_kernel(
    const float* __restrict__ A, const float* __restrict__ B,
    const float* __restrict__ bias, float* __restrict__ C,
    __half* __restrict__ Ch, const float* __restrict__ gatew,
    int M, int N, int K)
{
    __shared__ __align__(16) __nv_bfloat16 Ah[128 * ASTR2];
    __shared__ __align__(16) __nv_bfloat16 Al[128 * ASTR2];
    __shared__ __align__(16) float Bs[32 * BSTR];
    __shared__ float sgate[128];

    int tid = threadIdx.x;
    int lane = tid & 31;
    int wid = tid >> 5;
    int warp_m = wid >> 2;         // 0..1
    int warp_n = wid & 3;          // 0..3
    int g = lane >> 2;             // group 0..7
    int t = lane & 3;              // thread-in-group 0..3
    int row0 = blockIdx.x * 128;
    int col0 = blockIdx.y * 128;

    if (gatew && tid < 128) sgate[tid] = 0.f;

    float acc[4][4][4];
#pragma unroll
    for (int i = 0; i < 4; i++)
#pragma unroll
        for (int j = 0; j < 4; j++)
#pragma unroll
            for (int r = 0; r < 4; r++) acc[i][j][r] = 0.f;

    for (int k0 = 0; k0 < K; k0 += 32) {
        // load + split A tile [128 x 32] into bf16 hi/lo (guarded on M)
#pragma unroll
        for (int l = 0; l < 4; l++) {
            int f = tid + l * 256;
            int r = f >> 3;
            int c4 = f & 7;
            int grow = row0 + r;
            float4 v = make_float4(0.f, 0.f, 0.f, 0.f);
            if (grow < M) v = *(const float4*)(A + (size_t)grow * K + k0 + c4 * 4);
            __nv_bfloat16 h0, l0, h1, l1, h2, l2, h3, l3;
            split_bf16(v.x, h0, l0); split_bf16(v.y, h1, l1);
            split_bf16(v.z, h2, l2); split_bf16(v.w, h3, l3);
            int base = r * ASTR2 + c4 * 4;
            *(uint32_t*)&Ah[base]     = pk_bf(h0, h1);
            *(uint32_t*)&Ah[base + 2] = pk_bf(h2, h3);
            *(uint32_t*)&Al[base]     = pk_bf(l0, l1);
            *(uint32_t*)&Al[base + 2] = pk_bf(l2, l3);
        }
        // load B tile [32 x 128] fp32
#pragma unroll
        for (int l = 0; l < 4; l++) {
            int f = tid + l * 256;
            int kk = f >> 5;
            int c4 = f & 31;
            float4 v = *(const float4*)(B + (size_t)(k0 + kk) * N + col0 + c4 * 4);
            *(float4*)&Bs[kk * BSTR + c4 * 4] = v;
        }
        __syncthreads();

#pragma unroll
        for (int kc = 0; kc < 2; kc++) {       // two k16 chunks per BK=32
            uint32_t bh[4][2], bl[4][2];
#pragma unroll
            for (int tn = 0; tn < 4; tn++) {
                int n = warp_n * 32 + tn * 8 + g;
                const float* bp = &Bs[(kc * 16 + 2 * t) * BSTR + n];
                float b0 = bp[0];
                float b1 = bp[BSTR];
                float b2 = bp[8 * BSTR];
                float b3 = bp[9 * BSTR];
                __nv_bfloat16 h0, l0, h1, l1, h2, l2, h3, l3;
                split_bf16(b0, h0, l0); split_bf16(b1, h1, l1);
                split_bf16(b2, h2, l2); split_bf16(b3, h3, l3);
                bh[tn][0] = pk_bf(h0, h1); bh[tn][1] = pk_bf(h2, h3);
                bl[tn][0] = pk_bf(l0, l1); bl[tn][1] = pk_bf(l2, l3);
            }
#pragma unroll
            for (int tm = 0; tm < 4; tm++) {
                int row = warp_m * 64 + tm * 16 + g;
                int base = row * ASTR2 + kc * 16 + 2 * t;
                uint32_t ah[4], al[4];
                ah[0] = *(const uint32_t*)&Ah[base];
                ah[1] = *(const uint32_t*)&Ah[base + 8 * ASTR2];
                ah[2] = *(const uint32_t*)&Ah[base + 8];
                ah[3] = *(const uint32_t*)&Ah[base + 8 * ASTR2 + 8];
                al[0] = *(const uint32_t*)&Al[base];
                al[1] = *(const uint32_t*)&Al[base + 8 * ASTR2];
                al[2] = *(const uint32_t*)&Al[base + 8];
                al[3] = *(const uint32_t*)&Al[base + 8 * ASTR2 + 8];
#pragma unroll
                for (int tn = 0; tn < 4; tn++) {
                    mma_bf16(acc[tm][tn], al, bh[tn]);
                    mma_bf16(acc[tm][tn], ah, bl[tn]);
                    mma_bf16(acc[tm][tn], ah, bh[tn]);
                }
            }
        }
        __syncthreads();
    }

    // epilogue: bias + relu store (fp32 and/or fp16) + optional gate partial dot
    float bv[4][2], gwv[4][2];
#pragma unroll
    for (int tn = 0; tn < 4; tn++) {
        int col = col0 + warp_n * 32 + tn * 8 + 2 * t;
        bv[tn][0] = bias[col];
        bv[tn][1] = bias[col + 1];
        if (gatew) { gwv[tn][0] = gatew[col]; gwv[tn][1] = gatew[col + 1]; }
    }
#pragma unroll
    for (int tm = 0; tm < 4; tm++) {
        int row = row0 + warp_m * 64 + tm * 16 + g;
        float p0 = 0.f, p1 = 0.f;
#pragma unroll
        for (int tn = 0; tn < 4; tn++) {
            int col = col0 + warp_n * 32 + tn * 8 + 2 * t;
            float v0 = fmaxf(acc[tm][tn][0] + bv[tn][0], 0.f);
            float v1 = fmaxf(acc[tm][tn][1] + bv[tn][1], 0.f);
            float v2 = fmaxf(acc[tm][tn][2] + bv[tn][0], 0.f);
            float v3 = fmaxf(acc[tm][tn][3] + bv[tn][1], 0.f);
            if (C) {
                if (row < M)     *(float2*)(C + (size_t)row * N + col)       = make_float2(v0, v1);
                if (row + 8 < M) *(float2*)(C + (size_t)(row + 8) * N + col) = make_float2(v2, v3);
            }
            if (Ch) {
                if (row < M)     *(__half2*)(Ch + (size_t)row * N + col)       = __floats2half2_rn(v0, v1);
                if (row + 8 < M) *(__half2*)(Ch + (size_t)(row + 8) * N + col) = __floats2half2_rn(v2, v3);
            }
            if (gatew) {
                p0 += v0 * gwv[tn][0] + v1 * gwv[tn][1];
                p1 += v2 * gwv[tn][0] + v3 * gwv[tn][1];
            }
        }
        if (gatew) {
            p0 += __shfl_xor_sync(0xffffffffu, p0, 1);
            p0 += __shfl_xor_sync(0xffffffffu, p0, 2);
            p1 += __shfl_xor_sync(0xffffffffu, p1, 1);
            p1 += __shfl_xor_sync(0xffffffffu, p1, 2);
            if (t == 0) {
                int rl = warp_m * 64 + tm * 16 + g;
                atomicAdd(&sgate[rl], p0);
                atomicAdd(&sgate[rl + 8], p1);
            }
        }
    }
    if (gatew) {
        __syncthreads();
        if (tid < 128 && row0 + tid < M) atomicAdd(&g_gate[row0 + tid], sgate[tid]);
    }
}

// ---------------- segment softmax + weighted sum -> graph embeddings [G, 512] ----------------
__global__ void __launch_bounds__(256) softmax_emb_kernel()
{
    __shared__ float red[8];
    __shared__ float salpha[256];
    __shared__ float bcast;
    int g = blockIdx.x, tid = threadIdx.x;
    int lane = tid & 31, wid = tid >> 5;
    int s = g_goffs[g], e = g_goffs[g + 1];

    float m = -INFINITY;
    for (int i = s + tid; i < e; i += 256) m = fmaxf(m, g_gate[i]);
#pragma unroll
    for (int o = 16; o > 0; o >>= 1) m = fmaxf(m, __shfl_xor_sync(0xffffffffu, m, o));
    if (lane == 0) red[wid] = m;
    __syncthreads();
    if (wid == 0) {
        float x = (lane < 8) ? red[lane] : -INFINITY;
#pragma unroll
        for (int o = 4; o > 0; o >>= 1) x = fmaxf(x, __shfl_xor_sync(0xffffffffu, x, o));
        if (lane == 0) bcast = x;
    }
    __syncthreads();
    m = bcast;

    float sum = 0.f;
    for (int i = s + tid; i < e; i += 256) sum += expf(g_gate[i] - m);
#pragma unroll
    for (int o = 16; o > 0; o >>= 1) sum += __shfl_xor_sync(0xffffffffu, sum, o);
    if (lane == 0) red[wid] = sum;
    __syncthreads();
    if (wid == 0) {
        float x = (lane < 8) ? red[lane] : 0.f;
#pragma unroll
        for (int o = 4; o > 0; o >>= 1) x += __shfl_xor_sync(0xffffffffu, x, o);
        if (lane == 0) bcast = x;
    }
    __syncthreads();
    float inv = (e > s) ? 1.f / bcast : 0.f;

    float acc0 = 0.f, acc1 = 0.f;
    for (int start = s; start < e; start += 256) {
        int i = start + tid;
        salpha[tid] = (i < e) ? expf(g_gate[i] - m) * inv : 0.f;
        __syncthreads();
        int cnt = min(256, e - start);
        for (int k = 0; k < cnt; k++) {
            float a = salpha[k];
            const float* xr = g_buf0 + (size_t)(start + k) * 512;
            acc0 += xr[tid] * a;
            acc1 += xr[tid + 256] * a;
        }
        __syncthreads();
    }
    g_emb[g * 512 + tid] = acc0;
    g_emb[g * 512 + 256 + tid] = acc1;
}

// ---------------- GRU cell with h=0: out = (1-z)*n ; gh = bhh (whh unused) ----------------
__global__ void __launch_bounds__(256) gru_cell_kernel(
    const float* __restrict__ xin, const float* __restrict__ wih,
    const float* __restrict__ bih, const float* __restrict__ bhh,
    float* __restrict__ hout, int K)
{
    int warp = (blockIdx.x * blockDim.x + threadIdx.x) >> 5;
    int lane = threadIdx.x & 31;
    if (warp >= N_GRAPHS * GRUH) return;
    int g = warp >> 8;
    int j = warp & 255;
    const float* xg = xin + (size_t)g * K;
    const float* wr = wih + (size_t)j * K;
    const float* wz = wih + (size_t)(j + 256) * K;
    const float* wn = wih + (size_t)(j + 512) * K;
    float sr = 0.f, sz = 0.f, sn = 0.f;
    for (int k = lane; k < K; k += 32) {
        float xv = xg[k];
        sr += xv * wr[k];
        sz += xv * wz[k];
        sn += xv * wn[k];
    }
#pragma unroll
    for (int o = 16; o > 0; o >>= 1) {
        sr += __shfl_xor_sync(0xffffffffu, sr, o);
        sz += __shfl_xor_sync(0xffffffffu, sz, o);
        sn += __shfl_xor_sync(0xffffffffu, sn, o);
    }
    if (lane == 0) {
        float r = 1.f / (1.f + expf(-(sr + bih[j] + bhh[j])));
        float z = 1.f / (1.f + expf(-(sz + bih[j + 256] + bhh[j + 256])));
        float n = tanhf(sn + bih[j + 512] + r * bhh[j + 512]);
        hout[g * GRUH + j] = (1.f - z) * n;
    }
}

// ---------------- output projection ----------------
__global__ void __launch_bounds__(256) proj_kernel(
    const float* __restrict__ h2, const float* __restrict__ pw,
    const float* __restrict__ pb, float* __restrict__ out)
{
    int warp = (blockIdx.x * blockDim.x + threadIdx.x) >> 5;
    int lane = threadIdx.x & 31;
    if (warp >= N_GRAPHS * 512) return;
    int g = warp >> 9;
    int o = warp & 511;
    const float* hr = h2 + (size_t)g * 256;
    const float* wr = pw + (size_t)o * 256;
    float s = 0.f;
#pragma unroll 4
    for (int k = lane; k < 256; k += 32) s += hr[k] * wr[k];
#pragma unroll
    for (int d = 16; d > 0; d >>= 1) s += __shfl_xor_sync(0xffffffffu, s, d);
    if (lane == 0) out[g * 512 + o] = s + pb[o];
}

// ---------------- launch ----------------
extern "C" void kernel_launch(void* const* d_in, const int* in_sizes, int n_in,
                              void* d_out, int out_size)
{
    const float* x       = (const float*)d_in[0];
    const void*  ei      = d_in[1];
    const void*  batch   = d_in[2];
    const float* w0 = (const float*)d_in[3];  const float* b0 = (const float*)d_in[4];
    const float* w1 = (const float*)d_in[5];  const float* b1 = (const float*)d_in[6];
    const float* w2 = (const float*)d_in[7];  const float* b2 = (const float*)d_in[8];
    const float* gate_w = (const float*)d_in[9];
    const float* gate_b = (const float*)d_in[10];
    const float* wih0 = (const float*)d_in[11];
    const float* bih0 = (const float*)d_in[13];
    const float* bhh0 = (const float*)d_in[14];
    const float* wih1 = (const float*)d_in[15];
    const float* bih1 = (const float*)d_in[17];
    const float* bhh1 = (const float*)d_in[18];
    const float* proj_w = (const float*)d_in[19];
    const float* proj_b = (const float*)d_in[20];
    float* out = (float*)d_out;

    float *pH, *pB0, *pB1, *pEmb, *pH1, *pH2;
    cudaGetSymbolAddress((void**)&pH,   g_h);
    cudaGetSymbolAddress((void**)&pB0,  g_buf0);
    cudaGetSymbolAddress((void**)&pB1,  g_buf1);
    cudaGetSymbolAddress((void**)&pEmb, g_emb);
    cudaGetSymbolAddress((void**)&pH1,  g_h1);
    cudaGetSymbolAddress((void**)&pH2,  g_h2);
    __half* pHh = (__half*)pH;   // fp16 view of g_h for gather buffers

    // preprocessing: detect+init fused, degrees+dinv, CSR offsets, CSR fill
    init_kernel<<<256, 256>>>((const int*)ei, gate_b);
    count_kernel<<<1024, 256>>>(ei, batch);
    part_sum_kernel<<<NPART, 256>>>();
    scan_parts_kernel<<<1, 256>>>();
    final_scan_kernel<<<NPART, 256>>>();
    fill_kernel<<<1024, 256>>>(ei);

    int gM = (N_NODES + 127) / 128;
    int gAgg = (N_NODES + 7) / 8;

    // layer 0: Agg(x)[64] fp32 -> GEMM 64->128 + b0 + relu -> fp16 h
    agg64w_kernel<<<gAgg, 256>>>(x, pB1);
    gemm_tc_kernel<<<dim3(gM, 1), 256>>>(pB1, w0, b0, nullptr, pHh, nullptr, N_NODES, 128, 64);
    // layer 1: Agg[128] fp16-gather -> GEMM 128->256 + b1 + relu -> fp16 h
    agg128h_kernel<<<gAgg, 256>>>(pHh, pB1);
    gemm_tc_kernel<<<dim3(gM, 2), 256>>>(pB1, w1, b1, nullptr, pHh, nullptr, N_NODES, 256, 128);
    // layer 2: Agg[256] fp16-gather -> GEMM 256->512 + b2 + relu (fp32 out) + fused gate dot
    agg256h_kernel<<<gAgg, 256>>>(pHh, pB1);
    gemm_tc_kernel<<<dim3(gM, 4), 256>>>(pB1, w2, b2, pB0, nullptr, gate_w, N_NODES, 512, 256);

    // attentional aggregation (gate scores already in g_gate)
    softmax_emb_kernel<<<N_GRAPHS, 256>>>();

    // GRU (seq_len=1, h0=0 for both cells) + projection
    gru_cell_kernel<<<(N_GRAPHS * GRUH * 32) / 256, 256>>>(pEmb, wih0, bih0, bhh0, pH1, 512);
    gru_cell_kernel<<<(N_GRAPHS * GRUH * 32) / 256, 256>>>(pH1, wih1, bih1, bhh1, pH2, 256);
    proj_kernel<<<(N_GRAPHS * 512 * 32) / 256, 256>>>(pH2, proj_w, proj_b, out);
}

// round 10
// speedup vs baseline: 1.2593x; 1.1790x over previous
#include <cuda_runtime.h>
#include <cuda_fp16.h>
#include <math.h>
#include <stdint.h>

#define N_NODES  50000
#define N_EDGES  800000
#define N_GRAPHS 256
#define DMAX     512
#define GRUH     256
#define NPART    196   // ceil(50000/256)

// weight split segments (halves): L0 64x128, L1 128x256, L2 256x512
#define WOFF0 0
#define WOFF1 8192
#define WOFF2 40960
#define WTOT  172032

// ---------------- scratch (device globals; no allocation allowed) ----------------
__device__ __align__(16) __half g_hbuf[(size_t)N_NODES * DMAX];   // layer outputs (fp16)
__device__ __align__(16) __half g_abuf[(size_t)N_NODES * 256];    // agg outputs / GEMM A (fp16)
__device__ __align__(16) __half g_bwh[WTOT];                      // weights hi, [n][k] fp16
__device__ __align__(16) __half g_bwl[WTOT];                      // weights lo, [n][k] fp16
__device__ float g_dinv[N_NODES];
__device__ int   g_counts[N_NODES];
__device__ int   g_cursor[N_NODES];
__device__ int   g_offs[N_NODES + 1];
__device__ int   g_part[NPART];
__device__ int   g_csrc[N_EDGES];
__device__ int   g_gcounts[N_GRAPHS];
__device__ int   g_goffs[N_GRAPHS + 1];
__device__ float g_gate[N_NODES];
__device__ __align__(16) float g_emb[N_GRAPHS * 512];
__device__ float g_h1[N_GRAPHS * GRUH];
__device__ float g_h2[N_GRAPHS * GRUH];
__device__ int   g_is64;

__device__ __forceinline__ int load_idx(const void* p, long long i, int is64) {
    return is64 ? (int)((const long long*)p)[i] : ((const int*)p)[i];
}

// ---------------- init (+ fused index-width detect, + seeds g_gate with bias) ----------------
__global__ void init_kernel(const int* __restrict__ ei_raw, const float* __restrict__ gb) {
    int i = blockIdx.x * blockDim.x + threadIdx.x;
    int stride = gridDim.x * blockDim.x;
    if (blockIdx.x == 0 && threadIdx.x < 32) {
        int lane = threadIdx.x;
        int bad = 0;
#pragma unroll
        for (int k = 0; k < 4; k++) bad |= ei_raw[2 * (lane + k * 32) + 1];
        unsigned m = __ballot_sync(0xffffffffu, bad != 0);
        if (lane == 0) g_is64 = (m == 0) ? 1 : 0;
    }
    float gbias = gb[0];
    for (int k = i; k < N_NODES; k += stride) {
        g_counts[k] = 0; g_cursor[k] = 0; g_gate[k] = gbias;
    }
    for (int k = i; k < N_GRAPHS; k += stride) g_gcounts[k] = 0;
}

// -------- pre-split all 3 weight matrices to fp16 hi/lo, transposed [n][k] --------
__global__ void split_weights_kernel(const float* __restrict__ w0,
                                     const float* __restrict__ w1,
                                     const float* __restrict__ w2) {
    int i = blockIdx.x * blockDim.x + threadIdx.x;
    if (i >= WTOT) return;
    const float* B; int K, N, idx;
    if (i < WOFF1)      { B = w0; K = 64;  N = 128; idx = i - WOFF0; }
    else if (i < WOFF2) { B = w1; K = 128; N = 256; idx = i - WOFF1; }
    else                { B = w2; K = 256; N = 512; idx = i - WOFF2; }
    int n = idx / K, k = idx - n * K;
    float v = B[(size_t)k * N + n];
    __half h = __float2half_rn(v);
    __half l = __float2half_rn(v - __half2float(h));
    g_bwh[i] = h;
    g_bwl[i] = l;
}

__global__ void count_kernel(const void* __restrict__ ei, const void* __restrict__ batch) {
    int is64 = g_is64;
    int i = blockIdx.x * blockDim.x + threadIdx.x;
    int stride = gridDim.x * blockDim.x;
    for (int e = i; e < N_EDGES; e += stride) {
        int d = load_idx(ei, (long long)N_EDGES + e, is64);   // dst = edge_index[1]
        atomicAdd(&g_counts[d], 1);
    }
    for (int v = i; v < N_NODES; v += stride) {
        int b = load_idx(batch, v, is64);
        atomicAdd(&g_gcounts[b], 1);
    }
}

// -------- hierarchical exclusive scan of g_counts -> g_offs (+ fused dinv) --------
__global__ void __launch_bounds__(256) part_sum_kernel() {
    __shared__ int red[8];
    int b = blockIdx.x, t = threadIdx.x;
    int i = b * 256 + t;
    int cnt = (i < N_NODES) ? g_counts[i] : 0;
    if (i < N_NODES) g_dinv[i] = rsqrtf((float)(cnt + 1));  // +1 self-loop
    int v = cnt;
#pragma unroll
    for (int o = 16; o > 0; o >>= 1) v += __shfl_xor_sync(0xffffffffu, v, o);
    if ((t & 31) == 0) red[t >> 5] = v;
    __syncthreads();
    if (t == 0) {
        int s = 0;
#pragma unroll
        for (int w = 0; w < 8; w++) s += red[w];
        g_part[b] = s;
    }
}

__global__ void __launch_bounds__(256) scan_parts_kernel() {
    __shared__ int sh[256];
    int t = threadIdx.x;
    int v = (t < NPART) ? g_part[t] : 0;
    sh[t] = v;
    __syncthreads();
    for (int d = 1; d < 256; d <<= 1) {
        int x = (t >= d) ? sh[t - d] : 0;
        __syncthreads();
        sh[t] += x;
        __syncthreads();
    }
    if (t < NPART) g_part[t] = sh[t] - v;
    __syncthreads();
    int gc = g_gcounts[t];
    sh[t] = gc;
    __syncthreads();
    for (int d = 1; d < 256; d <<= 1) {
        int x = (t >= d) ? sh[t - d] : 0;
        __syncthreads();
        sh[t] += x;
        __syncthreads();
    }
    g_goffs[t] = sh[t] - gc;
    if (t == 255) g_goffs[256] = sh[255];
}

__global__ void __launch_bounds__(256) final_scan_kernel() {
    __shared__ int sh[256];
    int b = blockIdx.x, t = threadIdx.x;
    int i = b * 256 + t;
    int v = (i < N_NODES) ? g_counts[i] : 0;
    sh[t] = v;
    __syncthreads();
    for (int d = 1; d < 256; d <<= 1) {
        int x = (t >= d) ? sh[t - d] : 0;
        __syncthreads();
        sh[t] += x;
        __syncthreads();
    }
    int base = g_part[b];
    if (i < N_NODES) g_offs[i] = base + sh[t] - v;
    if (i == N_NODES - 1) g_offs[N_NODES] = base + sh[t];
}

__global__ void fill_kernel(const void* __restrict__ ei) {
    int is64 = g_is64;
    int i = blockIdx.x * blockDim.x + threadIdx.x;
    int stride = gridDim.x * blockDim.x;
    for (int e = i; e < N_EDGES; e += stride) {
        int d = load_idx(ei, (long long)N_EDGES + e, is64);
        int s = load_idx(ei, e, is64);
        int pos = g_offs[d] + atomicAdd(&g_cursor[d], 1);
        g_csrc[pos] = s;
    }
}

// ------------- GCN aggregation BEFORE transform; outputs fp16 A directly -------------
// layer 0: fp32 source (raw x) -> fp16 out
__global__ void __launch_bounds__(256) agg64w_kernel(const float* __restrict__ h,
                                                     __half* __restrict__ out)
{
    int node = blockIdx.x * 8 + (threadIdx.x >> 5);
    if (node >= N_NODES) return;
    int lane = threadIdx.x & 31;
    float wd = g_dinv[node];
    float2 acc = *(const float2*)(h + (size_t)node * 64 + lane * 2);
    float ws = wd * wd;
    acc.x *= ws; acc.y *= ws;
    int e = g_offs[node], e1 = g_offs[node + 1];
    for (; e + 2 <= e1; e += 2) {
        int s0 = g_csrc[e], s1 = g_csrc[e + 1];
        float w0 = g_dinv[s0] * wd, w1 = g_dinv[s1] * wd;
        float2 v0 = *(const float2*)(h + (size_t)s0 * 64 + lane * 2);
        float2 v1 = *(const float2*)(h + (size_t)s1 * 64 + lane * 2);
        acc.x += v0.x * w0 + v1.x * w1;
        acc.y += v0.y * w0 + v1.y * w1;
    }
    if (e < e1) {
        int s0 = g_csrc[e];
        float w0 = g_dinv[s0] * wd;
        float2 v0 = *(const float2*)(h + (size_t)s0 * 64 + lane * 2);
        acc.x += v0.x * w0; acc.y += v0.y * w0;
    }
    *(__half2*)(out + (size_t)node * 64 + lane * 2) = __floats2half2_rn(acc.x, acc.y);
}

// layers 1/2: fp16 gather + fp32 accumulate -> fp16 out
__global__ void __launch_bounds__(256) agg128h_kernel(const __half* __restrict__ h,
                                                      __half* __restrict__ out)
{
    int node = blockIdx.x * 8 + (threadIdx.x >> 5);
    if (node >= N_NODES) return;
    int lane = threadIdx.x & 31;
    float wd = g_dinv[node];
    const __half2* selfp = (const __half2*)(h + (size_t)node * 128 + lane * 4);
    float2 s0f = __half22float2(selfp[0]);
    float2 s1f = __half22float2(selfp[1]);
    float ws = wd * wd;
    float4 acc = make_float4(s0f.x * ws, s0f.y * ws, s1f.x * ws, s1f.y * ws);
    int e = g_offs[node], e1 = g_offs[node + 1];
    for (; e + 2 <= e1; e += 2) {
        int n0 = g_csrc[e], n1 = g_csrc[e + 1];
        float w0 = g_dinv[n0] * wd, w1 = g_dinv[n1] * wd;
        const __half2* p0 = (const __half2*)(h + (size_t)n0 * 128 + lane * 4);
        const __half2* p1 = (const __half2*)(h + (size_t)n1 * 128 + lane * 4);
        float2 fa0 = __half22float2(p0[0]), fa1 = __half22float2(p0[1]);
        float2 fb0 = __half22float2(p1[0]), fb1 = __half22float2(p1[1]);
        acc.x += fa0.x * w0 + fb0.x * w1;
        acc.y += fa0.y * w0 + fb0.y * w1;
        acc.z += fa1.x * w0 + fb1.x * w1;
        acc.w += fa1.y * w0 + fb1.y * w1;
    }
    if (e < e1) {
        int n0 = g_csrc[e];
        float w0 = g_dinv[n0] * wd;
        const __half2* p0 = (const __half2*)(h + (size_t)n0 * 128 + lane * 4);
        float2 fa0 = __half22float2(p0[0]), fa1 = __half22float2(p0[1]);
        acc.x += fa0.x * w0; acc.y += fa0.y * w0;
        acc.z += fa1.x * w0; acc.w += fa1.y * w0;
    }
    __half2 o0 = __floats2half2_rn(acc.x, acc.y);
    __half2 o1 = __floats2half2_rn(acc.z, acc.w);
    uint2 ov = make_uint2(*(uint32_t*)&o0, *(uint32_t*)&o1);
    *(uint2*)(out + (size_t)node * 128 + lane * 4) = ov;
}

__global__ void __launch_bounds__(256) agg256h_kernel(const __half* __restrict__ h,
                                                      __half* __restrict__ out)
{
    int node = blockIdx.x * 8 + (threadIdx.x >> 5);
    if (node >= N_NODES) return;
    int lane = threadIdx.x & 31;
    float wd = g_dinv[node];
    float acc[8];
    {
        uint4 sv = *(const uint4*)(h + (size_t)node * 256 + lane * 8);
        const __half2* hp = (const __half2*)&sv;
        float ws = wd * wd;
#pragma unroll
        for (int q = 0; q < 4; q++) {
            float2 f = __half22float2(hp[q]);
            acc[2 * q] = f.x * ws;
            acc[2 * q + 1] = f.y * ws;
        }
    }
    int e = g_offs[node], e1 = g_offs[node + 1];
    for (; e + 2 <= e1; e += 2) {
        int n0 = g_csrc[e], n1 = g_csrc[e + 1];
        float w0 = g_dinv[n0] * wd, w1 = g_dinv[n1] * wd;
        uint4 v0 = *(const uint4*)(h + (size_t)n0 * 256 + lane * 8);
        uint4 v1 = *(const uint4*)(h + (size_t)n1 * 256 + lane * 8);
        const __half2* p0 = (const __half2*)&v0;
        const __half2* p1 = (const __half2*)&v1;
#pragma unroll
        for (int q = 0; q < 4; q++) {
            float2 f0 = __half22float2(p0[q]);
            float2 f1 = __half22float2(p1[q]);
            acc[2 * q]     += f0.x * w0 + f1.x * w1;
            acc[2 * q + 1] += f0.y * w0 + f1.y * w1;
        }
    }
    if (e < e1) {
        int n0 = g_csrc[e];
        float w0 = g_dinv[n0] * wd;
        uint4 v0 = *(const uint4*)(h + (size_t)n0 * 256 + lane * 8);
        const __half2* p0 = (const __half2*)&v0;
#pragma unroll
        for (int q = 0; q < 4; q++) {
            float2 f0 = __half22float2(p0[q]);
            acc[2 * q]     += f0.x * w0;
            acc[2 * q + 1] += f0.y * w0;
        }
    }
    __half2 o0 = __floats2half2_rn(acc[0], acc[1]);
    __half2 o1 = __floats2half2_rn(acc[2], acc[3]);
    __half2 o2 = __floats2half2_rn(acc[4], acc[5]);
    __half2 o3 = __floats2half2_rn(acc[6], acc[7]);
    uint4 ov = make_uint4(*(uint32_t*)&o0, *(uint32_t*)&o1, *(uint32_t*)&o2, *(uint32_t*)&o3);
    *(uint4*)(out + (size_t)node * 256 + lane * 8) = ov;
}

// ---------------- fp16 mma (A exact fp16; B = Bh + Bl split) ----------------
__device__ __forceinline__ void mma_f16(float* c, const uint32_t* a, const uint32_t* b) {
    asm volatile(
        "mma.sync.aligned.m16n8k16.row.col.f32.f16.f16.f32 "
        "{%0,%1,%2,%3}, {%4,%5,%6,%7}, {%8,%9}, {%0,%1,%2,%3};"
        : "+f"(c[0]), "+f"(c[1]), "+f"(c[2]), "+f"(c[3])
        : "r"(a[0]), "r"(a[1]), "r"(a[2]), "r"(a[3]), "r"(b[0]), "r"(b[1]));
}

// ---- GEMM + bias + ReLU, all-fp16 operands, fp32 accum; fp16 output ----
// A [M×K] fp16 row-major; Bh/Bl [N×K] fp16 row-major (pre-split, transposed).
// If gatew non-null: g_gate[row] += sum_col relu(...)[row,col]*gatew[col].
// CTA tile 128x128, BK=32; 8 warps 2(M)x4(N); 2 mma per k16 chunk.
#define HSTR 40   // fp16 stride (halves); word stride 20 -> conflict-free frags

__global__ void __launch_bounds__(256) gemm_f16_kernel(
    const __half* __restrict__ A, const __half* __restrict__ Bh,
    const __half* __restrict__ Bl, const float* __restrict__ bias,
    __half* __restrict__ Ch, const float* __restrict__ gatew,
    int M, int N, int K)
{
    __shared__ __align__(16) __half As[128 * HSTR];
    __shared__ __align__(16) __half Bhs[128 * HSTR];
    __shared__ __align__(16) __half Bls[128 * HSTR];
    __shared__ float sgate[128];

    int tid = threadIdx.x;
    int lane = tid & 31;
    int wid = tid >> 5;
    int warp_m = wid >> 2;         // 0..1
    int warp_n = wid & 3;          // 0..3
    int g = lane >> 2;             // group 0..7
    int t = lane & 3;              // thread-in-group 0..3
    int row0 = blockIdx.x * 128;
    int col0 = blockIdx.y * 128;

    if (gatew && tid < 128) sgate[tid] = 0.f;

    float acc[4][4][4];
#pragma unroll
    for (int i = 0; i < 4; i++)
#pragma unroll
        for (int j = 0; j < 4; j++)
#pragma unroll
            for (int r = 0; r < 4; r++) acc[i][j][r] = 0.f;

    for (int k0 = 0; k0 < K; k0 += 32) {
        // A tile [128 x 32] fp16, uint4 = 8 halves; 2 loads/thread (guarded on M)
#pragma unroll
        for (int l = 0; l < 2; l++) {
            int f = tid + l * 256;
            int r = f >> 2, c8 = f & 3;
            int grow = row0 + r;
            uint4 v = make_uint4(0u, 0u, 0u, 0u);
            if (grow < M) v = *(const uint4*)(A + (size_t)grow * K + k0 + c8 * 8);
            *(uint4*)&As[r * HSTR + c8 * 8] = v;
        }
        // Bh/Bl tiles [128 n x 32 k] fp16 (N multiple of 128, no guard)
#pragma unroll
        for (int l = 0; l < 2; l++) {
            int f = tid + l * 256;
            int r = f >> 2, c8 = f & 3;
            size_t go = (size_t)(col0 + r) * K + k0 + c8 * 8;
            *(uint4*)&Bhs[r * HSTR + c8 * 8] = *(const uint4*)(Bh + go);
            *(uint4*)&Bls[r * HSTR + c8 * 8] = *(const uint4*)(Bl + go);
        }
        __syncthreads();

#pragma unroll
        for (int kc = 0; kc < 2; kc++) {       // two k16 chunks per BK=32
            uint32_t bh[4][2], bl[4][2];
#pragma unroll
            for (int tn = 0; tn < 4; tn++) {
                int n = warp_n * 32 + tn * 8 + g;
                int base = n * HSTR + kc * 16 + 2 * t;
                bh[tn][0] = *(const uint32_t*)&Bhs[base];
                bh[tn][1] = *(const uint32_t*)&Bhs[base + 8];
                bl[tn][0] = *(const uint32_t*)&Bls[base];
                bl[tn][1] = *(const uint32_t*)&Bls[base + 8];
            }
#pragma unroll
            for (int tm = 0; tm < 4; tm++) {
                int row = warp_m * 64 + tm * 16 + g;
                int base = row * HSTR + kc * 16 + 2 * t;
                uint32_t a[4];
                a[0] = *(const uint32_t*)&As[base];
                a[1] = *(const uint32_t*)&As[base + 8 * HSTR];
                a[2] = *(const uint32_t*)&As[base + 8];
                a[3] = *(const uint32_t*)&As[base + 8 * HSTR + 8];
#pragma unroll
                for (int tn = 0; tn < 4; tn++) {
                    mma_f16(acc[tm][tn], a, bh[tn]);
                    mma_f16(acc[tm][tn], a, bl[tn]);
                }
            }
        }
        __syncthreads();
    }

    // epilogue: bias + relu -> fp16 store (+ optional fused gate dot, fp32)
    float bv[4][2], gwv[4][2];
#pragma unroll
    for (int tn = 0; tn < 4; tn++) {
        int col = col0 + warp_n * 32 + tn * 8 + 2 * t;
        bv[tn][0] = bias[col];
        bv[tn][1] = bias[col + 1];
        if (gatew) { gwv[tn][0] = gatew[col]; gwv[tn][1] = gatew[col + 1]; }
    }
#pragma unroll
    for (int tm = 0; tm < 4; tm++) {
        int row = row0 + warp_m * 64 + tm * 16 + g;
        float p0 = 0.f, p1 = 0.f;
#pragma unroll
        for (int tn = 0; tn < 4; tn++) {
            int col = col0 + warp_n * 32 + tn * 8 + 2 * t;
            float v0 = fmaxf(acc[tm][tn][0] + bv[tn][0], 0.f);
            float v1 = fmaxf(acc[tm][tn][1] + bv[tn][1], 0.f);
            float v2 = fmaxf(acc[tm][tn][2] + bv[tn][0], 0.f);
            float v3 = fmaxf(acc[tm][tn][3] + bv[tn][1], 0.f);
            if (row < M)     *(__half2*)(Ch + (size_t)row * N + col)       = __floats2half2_rn(v0, v1);
            if (row + 8 < M) *(__half2*)(Ch + (size_t)(row + 8) * N + col) = __floats2half2_rn(v2, v3);
            if (gatew) {
                p0 += v0 * gwv[tn][0] + v1 * gwv[tn][1];
                p1 += v2 * gwv[tn][0] + v3 * gwv[tn][1];
            }
        }
        if (gatew) {
            p0 += __shfl_xor_sync(0xffffffffu, p0, 1);
            p0 += __shfl_xor_sync(0xffffffffu, p0, 2);
            p1 += __shfl_xor_sync(0xffffffffu, p1, 1);
            p1 += __shfl_xor_sync(0xffffffffu, p1, 2);
            if (t == 0) {
                int rl = warp_m * 64 + tm * 16 + g;
                atomicAdd(&sgate[rl], p0);
                atomicAdd(&sgate[rl + 8], p1);
            }
        }
    }
    if (gatew) {
        __syncthreads();
        if (tid < 128 && row0 + tid < M) atomicAdd(&g_gate[row0 + tid], sgate[tid]);
    }
}

// ------- segment softmax + weighted sum over fp16 x -> graph embeddings [G, 512] -------
__global__ void __launch_bounds__(256) softmax_emb_kernel(const __half* __restrict__ xh)
{
    __shared__ float red[8];
    __shared__ float salpha[256];
    __shared__ float bcast;
    int g = blockIdx.x, tid = threadIdx.x;
    int lane = tid & 31, wid = tid >> 5;
    int s = g_goffs[g], e = g_goffs[g + 1];

    float m = -INFINITY;
    for (int i = s + tid; i < e; i += 256) m = fmaxf(m, g_gate[i]);
#pragma unroll
    for (int o = 16; o > 0; o >>= 1) m = fmaxf(m, __shfl_xor_sync(0xffffffffu, m, o));
    if (lane == 0) red[wid] = m;
    __syncthreads();
    if (wid == 0) {
        float x = (lane < 8) ? red[lane] : -INFINITY;
#pragma unroll
        for (int o = 4; o > 0; o >>= 1) x = fmaxf(x, __shfl_xor_sync(0xffffffffu, x, o));
        if (lane == 0) bcast = x;
    }
    __syncthreads();
    m = bcast;

    float sum = 0.f;
    for (int i = s + tid; i < e; i += 256) sum += expf(g_gate[i] - m);
#pragma unroll
    for (int o = 16; o > 0; o >>= 1) sum += __shfl_xor_sync(0xffffffffu, sum, o);
    if (lane == 0) red[wid] = sum;
    __syncthreads();
    if (wid == 0) {
        float x = (lane < 8) ? red[lane] : 0.f;
#pragma unroll
        for (int o = 4; o > 0; o >>= 1) x += __shfl_xor_sync(0xffffffffu, x, o);
        if (lane == 0) bcast = x;
    }
    __syncthreads();
    float inv = (e > s) ? 1.f / bcast : 0.f;

    float acc0 = 0.f, acc1 = 0.f;
    for (int start = s; start < e; start += 256) {
        int i = start + tid;
        salpha[tid] = (i < e) ? expf(g_gate[i] - m) * inv : 0.f;
        __syncthreads();
        int cnt = min(256, e - start);
        for (int k = 0; k < cnt; k++) {
            float a = salpha[k];
            const __half* xr = xh + (size_t)(start + k) * 512;
            acc0 += __half2float(xr[tid]) * a;
            acc1 += __half2float(xr[tid + 256]) * a;
        }
        __syncthreads();
    }
    g_emb[g * 512 + tid] = acc0;
    g_emb[g * 512 + 256 + tid] = acc1;
}

// ---------------- GRU cell with h=0: out = (1-z)*n ; gh = bhh (whh unused) ----------------
__global__ void __launch_bounds__(256) gru_cell_kernel(
    const float* __restrict__ xin, const float* __restrict__ wih,
    const float* __restrict__ bih, const float* __restrict__ bhh,
    float* __restrict__ hout, int K)
{
    int warp = (blockIdx.x * blockDim.x + threadIdx.x) >> 5;
    int lane = threadIdx.x & 31;
    if (warp >= N_GRAPHS * GRUH) return;
    int g = warp >> 8;
    int j = warp & 255;
    const float* xg = xin + (size_t)g * K;
    const float* wr = wih + (size_t)j * K;
    const float* wz = wih + (size_t)(j + 256) * K;
    const float* wn = wih + (size_t)(j + 512) * K;
    float sr = 0.f, sz = 0.f, sn = 0.f;
    for (int k = lane; k < K; k += 32) {
        float xv = xg[k];
        sr += xv * wr[k];
        sz += xv * wz[k];
        sn += xv * wn[k];
    }
#pragma unroll
    for (int o = 16; o > 0; o >>= 1) {
        sr += __shfl_xor_sync(0xffffffffu, sr, o);
        sz += __shfl_xor_sync(0xffffffffu, sz, o);
        sn += __shfl_xor_sync(0xffffffffu, sn, o);
    }
    if (lane == 0) {
        float r = 1.f / (1.f + expf(-(sr + bih[j] + bhh[j])));
        float z = 1.f / (1.f + expf(-(sz + bih[j + 256] + bhh[j + 256])));
        float n = tanhf(sn + bih[j + 512] + r * bhh[j + 512]);
        hout[g * GRUH + j] = (1.f - z) * n;
    }
}

// ---------------- output projection ----------------
__global__ void __launch_bounds__(256) proj_kernel(
    const float* __restrict__ h2, const float* __restrict__ pw,
    const float* __restrict__ pb, float* __restrict__ out)
{
    int warp = (blockIdx.x * blockDim.x + threadIdx.x) >> 5;
    int lane = threadIdx.x & 31;
    if (warp >= N_GRAPHS * 512) return;
    int g = warp >> 9;
    int o = warp & 511;
    const float* hr = h2 + (size_t)g * 256;
    const float* wr = pw + (size_t)o * 256;
    float s = 0.f;
#pragma unroll 4
    for (int k = lane; k < 256; k += 32) s += hr[k] * wr[k];
#pragma unroll
    for (int d = 16; d > 0; d >>= 1) s += __shfl_xor_sync(0xffffffffu, s, d);
    if (lane == 0) out[g * 512 + o] = s + pb[o];
}

// ---------------- launch ----------------
extern "C" void kernel_launch(void* const* d_in, const int* in_sizes, int n_in,
                              void* d_out, int out_size)
{
    const float* x       = (const float*)d_in[0];
    const void*  ei      = d_in[1];
    const void*  batch   = d_in[2];
    const float* w0 = (const float*)d_in[3];  const float* b0 = (const float*)d_in[4];
    const float* w1 = (const float*)d_in[5];  const float* b1 = (const float*)d_in[6];
    const float* w2 = (const float*)d_in[7];  const float* b2 = (const float*)d_in[8];
    const float* gate_w = (const float*)d_in[9];
    const float* gate_b = (const float*)d_in[10];
    const float* wih0 = (const float*)d_in[11];
    const float* bih0 = (const float*)d_in[13];
    const float* bhh0 = (const float*)d_in[14];
    const float* wih1 = (const float*)d_in[15];
    const float* bih1 = (const float*)d_in[17];
    const float* bhh1 = (const float*)d_in[18];
    const float* proj_w = (const float*)d_in[19];
    const float* proj_b = (const float*)d_in[20];
    float* out = (float*)d_out;

    __half *pH, *pA, *pWh, *pWl;
    float *pEmb, *pH1, *pH2;
    cudaGetSymbolAddress((void**)&pH,   g_hbuf);
    cudaGetSymbolAddress((void**)&pA,   g_abuf);
    cudaGetSymbolAddress((void**)&pWh,  g_bwh);
    cudaGetSymbolAddress((void**)&pWl,  g_bwl);
    cudaGetSymbolAddress((void**)&pEmb, g_emb);
    cudaGetSymbolAddress((void**)&pH1,  g_h1);
    cudaGetSymbolAddress((void**)&pH2,  g_h2);

    // preprocessing: detect+init, weight pre-split, degrees+dinv, CSR offsets, CSR fill
    init_kernel<<<256, 256>>>((const int*)ei, gate_b);
    split_weights_kernel<<<(WTOT + 255) / 256, 256>>>(w0, w1, w2);
    count_kernel<<<1024, 256>>>(ei, batch);
    part_sum_kernel<<<NPART, 256>>>();
    scan_parts_kernel<<<1, 256>>>();
    final_scan_kernel<<<NPART, 256>>>();
    fill_kernel<<<1024, 256>>>(ei);

    int gM = (N_NODES + 127) / 128;
    int gAgg = (N_NODES + 7) / 8;

    // layer 0: Agg(x)[64] -> fp16 A -> GEMM 64->128 + b0 + relu -> fp16 h
    agg64w_kernel<<<gAgg, 256>>>(x, pA);
    gemm_f16_kernel<<<dim3(gM, 1), 256>>>(pA, pWh + WOFF0, pWl + WOFF0, b0, pH, nullptr,
                                          N_NODES, 128, 64);
    // layer 1: Agg[128] -> fp16 A -> GEMM 128->256 + b1 + relu -> fp16 h
    agg128h_kernel<<<gAgg, 256>>>(pH, pA);
    gemm_f16_kernel<<<dim3(gM, 2), 256>>>(pA, pWh + WOFF1, pWl + WOFF1, b1, pH, nullptr,
                                          N_NODES, 256, 128);
    // layer 2: Agg[256] -> fp16 A -> GEMM 256->512 + b2 + relu -> fp16 h + fused gate dot
    agg256h_kernel<<<gAgg, 256>>>(pH, pA);
    gemm_f16_kernel<<<dim3(gM, 4), 256>>>(pA, pWh + WOFF2, pWl + WOFF2, b2, pH, gate_w,
                                          N_NODES, 512, 256);

    // attentional aggregation over fp16 x (gate scores already in g_gate, fp32)
    softmax_emb_kernel<<<N_GRAPHS, 256>>>(pH);

    // GRU (seq_len=1, h0=0 for both cells) + projection
    gru_cell_kernel<<<(N_GRAPHS * GRUH * 32) / 256, 256>>>(pEmb, wih0, bih0, bhh0, pH1, 512);
    gru_cell_kernel<<<(N_GRAPHS * GRUH * 32) / 256, 256>>>(pH1, wih1, bih1, bhh1, pH2, 256);
    proj_kernel<<<(N_GRAPHS * 512 * 32) / 256, 256>>>(pH2, proj_w, proj_b, out);
}

// round 11
// speedup vs baseline: 1.2915x; 1.0256x over previous
#include <cuda_runtime.h>
#include <cuda_fp16.h>
#include <math.h>
#include <stdint.h>

#define N_NODES  50000
#define N_EDGES  800000
#define N_GRAPHS 256
#define DMAX     512
#define GRUH     256
#define NPART    196   // ceil(50000/256)

// weight split segments (halves): L0 64x128, L1 128x256, L2 256x512
#define WOFF0 0
#define WOFF1 8192
#define WOFF2 40960
#define WTOT  172032

// ---------------- scratch (device globals; no allocation allowed) ----------------
__device__ __align__(16) __half g_hbuf[(size_t)N_NODES * DMAX];   // layer outputs (fp16)
__device__ __align__(16) __half g_abuf[(size_t)N_NODES * 256];    // agg outputs / GEMM A (fp16)
__device__ __align__(16) __half g_bwh[WTOT];                      // weights hi, [n][k] fp16
__device__ __align__(16) __half g_bwl[WTOT];                      // weights lo, [n][k] fp16
__device__ float g_dinv[N_NODES];
__device__ int   g_counts[N_NODES];
__device__ int   g_rank[N_EDGES];
__device__ int   g_offs[N_NODES + 1];
__device__ int   g_part[NPART];
__device__ int   g_csrc[N_EDGES];
__device__ int   g_gcounts[N_GRAPHS];
__device__ int   g_goffs[N_GRAPHS + 1];
__device__ float g_gate[N_NODES];
__device__ __align__(16) float g_emb[N_GRAPHS * 512];
__device__ __align__(16) float g_gi[N_GRAPHS * 3 * GRUH];
__device__ float g_h1[N_GRAPHS * GRUH];
__device__ float g_h2[N_GRAPHS * GRUH];
__device__ int   g_is64;

__device__ __forceinline__ int load_idx(const void* p, long long i, int is64) {
    return is64 ? (int)((const long long*)p)[i] : ((const int*)p)[i];
}

// ---------------- init (+ fused index-width detect, + seeds g_gate with bias) ----------------
__global__ void init_kernel(const int* __restrict__ ei_raw, const float* __restrict__ gb) {
    int i = blockIdx.x * blockDim.x + threadIdx.x;
    int stride = gridDim.x * blockDim.x;
    if (blockIdx.x == 0 && threadIdx.x < 32) {
        int lane = threadIdx.x;
        int bad = 0;
#pragma unroll
        for (int k = 0; k < 4; k++) bad |= ei_raw[2 * (lane + k * 32) + 1];
        unsigned m = __ballot_sync(0xffffffffu, bad != 0);
        if (lane == 0) g_is64 = (m == 0) ? 1 : 0;
    }
    float gbias = gb[0];
    for (int k = i; k < N_NODES; k += stride) {
        g_counts[k] = 0; g_gate[k] = gbias;
    }
    for (int k = i; k < N_GRAPHS; k += stride) g_gcounts[k] = 0;
}

// -------- pre-split all 3 weight matrices to fp16 hi/lo, transposed [n][k] --------
__global__ void split_weights_kernel(const float* __restrict__ w0,
                                     const float* __restrict__ w1,
                                     const float* __restrict__ w2) {
    int i = blockIdx.x * blockDim.x + threadIdx.x;
    if (i >= WTOT) return;
    const float* B; int K, N, idx;
    if (i < WOFF1)      { B = w0; K = 64;  N = 128; idx = i - WOFF0; }
    else if (i < WOFF2) { B = w1; K = 128; N = 256; idx = i - WOFF1; }
    else                { B = w2; K = 256; N = 512; idx = i - WOFF2; }
    int n = idx / K, k = idx - n * K;
    float v = B[(size_t)k * N + n];
    __half h = __float2half_rn(v);
    __half l = __float2half_rn(v - __half2float(h));
    g_bwh[i] = h;
    g_bwl[i] = l;
}

// ---------- count degrees; also record each edge's rank within its dst bucket ----------
__global__ void count_kernel(const void* __restrict__ ei, const void* __restrict__ batch) {
    int is64 = g_is64;
    int i = blockIdx.x * blockDim.x + threadIdx.x;
    int stride = gridDim.x * blockDim.x;
    for (int e = i; e < N_EDGES; e += stride) {
        int d = load_idx(ei, (long long)N_EDGES + e, is64);   // dst = edge_index[1]
        g_rank[e] = atomicAdd(&g_counts[d], 1);
    }
    for (int v = i; v < N_NODES; v += stride) {
        int b = load_idx(batch, v, is64);
        atomicAdd(&g_gcounts[b], 1);
    }
}

// -------- hierarchical exclusive scan of g_counts -> g_offs (+ fused dinv) --------
__global__ void __launch_bounds__(256) part_sum_kernel() {
    __shared__ int red[8];
    int b = blockIdx.x, t = threadIdx.x;
    int i = b * 256 + t;
    int cnt = (i < N_NODES) ? g_counts[i] : 0;
    if (i < N_NODES) g_dinv[i] = rsqrtf((float)(cnt + 1));  // +1 self-loop
    int v = cnt;
#pragma unroll
    for (int o = 16; o > 0; o >>= 1) v += __shfl_xor_sync(0xffffffffu, v, o);
    if ((t & 31) == 0) red[t >> 5] = v;
    __syncthreads();
    if (t == 0) {
        int s = 0;
#pragma unroll
        for (int w = 0; w < 8; w++) s += red[w];
        g_part[b] = s;
    }
}

__global__ void __launch_bounds__(256) scan_parts_kernel() {
    __shared__ int sh[256];
    int t = threadIdx.x;
    int v = (t < NPART) ? g_part[t] : 0;
    sh[t] = v;
    __syncthreads();
    for (int d = 1; d < 256; d <<= 1) {
        int x = (t >= d) ? sh[t - d] : 0;
        __syncthreads();
        sh[t] += x;
        __syncthreads();
    }
    if (t < NPART) g_part[t] = sh[t] - v;
    __syncthreads();
    int gc = g_gcounts[t];
    sh[t] = gc;
    __syncthreads();
    for (int d = 1; d < 256; d <<= 1) {
        int x = (t >= d) ? sh[t - d] : 0;
        __syncthreads();
        sh[t] += x;
        __syncthreads();
    }
    g_goffs[t] = sh[t] - gc;
    if (t == 255) g_goffs[256] = sh[255];
}

__global__ void __launch_bounds__(256) final_scan_kernel() {
    __shared__ int sh[256];
    int b = blockIdx.x, t = threadIdx.x;
    int i = b * 256 + t;
    int v = (i < N_NODES) ? g_counts[i] : 0;
    sh[t] = v;
    __syncthreads();
    for (int d = 1; d < 256; d <<= 1) {
        int x = (t >= d) ? sh[t - d] : 0;
        __syncthreads();
        sh[t] += x;
        __syncthreads();
    }
    int base = g_part[b];
    if (i < N_NODES) g_offs[i] = base + sh[t] - v;
    if (i == N_NODES - 1) g_offs[N_NODES] = base + sh[t];
}

// ---------- CSR fill: atomic-free (uses precomputed ranks) ----------
__global__ void fill_kernel(const void* __restrict__ ei) {
    int is64 = g_is64;
    int i = blockIdx.x * blockDim.x + threadIdx.x;
    int stride = gridDim.x * blockDim.x;
    for (int e = i; e < N_EDGES; e += stride) {
        int d = load_idx(ei, (long long)N_EDGES + e, is64);
        int s = load_idx(ei, e, is64);
        g_csrc[g_offs[d] + g_rank[e]] = s;
    }
}

// ------------- GCN aggregation BEFORE transform; outputs fp16 A directly -------------
__global__ void __launch_bounds__(256) agg64w_kernel(const float* __restrict__ h,
                                                     __half* __restrict__ out)
{
    int node = blockIdx.x * 8 + (threadIdx.x >> 5);
    if (node >= N_NODES) return;
    int lane = threadIdx.x & 31;
    float wd = g_dinv[node];
    float2 acc = *(const float2*)(h + (size_t)node * 64 + lane * 2);
    float ws = wd * wd;
    acc.x *= ws; acc.y *= ws;
    int e = g_offs[node], e1 = g_offs[node + 1];
    for (; e + 2 <= e1; e += 2) {
        int s0 = g_csrc[e], s1 = g_csrc[e + 1];
        float w0 = g_dinv[s0] * wd, w1 = g_dinv[s1] * wd;
        float2 v0 = *(const float2*)(h + (size_t)s0 * 64 + lane * 2);
        float2 v1 = *(const float2*)(h + (size_t)s1 * 64 + lane * 2);
        acc.x += v0.x * w0 + v1.x * w1;
        acc.y += v0.y * w0 + v1.y * w1;
    }
    if (e < e1) {
        int s0 = g_csrc[e];
        float w0 = g_dinv[s0] * wd;
        float2 v0 = *(const float2*)(h + (size_t)s0 * 64 + lane * 2);
        acc.x += v0.x * w0; acc.y += v0.y * w0;
    }
    *(__half2*)(out + (size_t)node * 64 + lane * 2) = __floats2half2_rn(acc.x, acc.y);
}

__global__ void __launch_bounds__(256) agg128h_kernel(const __half* __restrict__ h,
                                                      __half* __restrict__ out)
{
    int node = blockIdx.x * 8 + (threadIdx.x >> 5);
    if (node >= N_NODES) return;
    int lane = threadIdx.x & 31;
    float wd = g_dinv[node];
    const __half2* selfp = (const __half2*)(h + (size_t)node * 128 + lane * 4);
    float2 s0f = __half22float2(selfp[0]);
    float2 s1f = __half22float2(selfp[1]);
    float ws = wd * wd;
    float4 acc = make_float4(s0f.x * ws, s0f.y * ws, s1f.x * ws, s1f.y * ws);
    int e = g_offs[node], e1 = g_offs[node + 1];
    for (; e + 2 <= e1; e += 2) {
        int n0 = g_csrc[e], n1 = g_csrc[e + 1];
        float w0 = g_dinv[n0] * wd, w1 = g_dinv[n1] * wd;
        const __half2* p0 = (const __half2*)(h + (size_t)n0 * 128 + lane * 4);
        const __half2* p1 = (const __half2*)(h + (size_t)n1 * 128 + lane * 4);
        float2 fa0 = __half22float2(p0[0]), fa1 = __half22float2(p0[1]);
        float2 fb0 = __half22float2(p1[0]), fb1 = __half22float2(p1[1]);
        acc.x += fa0.x * w0 + fb0.x * w1;
        acc.y += fa0.y * w0 + fb0.y * w1;
        acc.z += fa1.x * w0 + fb1.x * w1;
        acc.w += fa1.y * w0 + fb1.y * w1;
    }
    if (e < e1) {
        int n0 = g_csrc[e];
        float w0 = g_dinv[n0] * wd;
        const __half2* p0 = (const __half2*)(h + (size_t)n0 * 128 + lane * 4);
        float2 fa0 = __half22float2(p0[0]), fa1 = __half22float2(p0[1]);
        acc.x += fa0.x * w0; acc.y += fa0.y * w0;
        acc.z += fa1.x * w0; acc.w += fa1.y * w0;
    }
    __half2 o0 = __floats2half2_rn(acc.x, acc.y);
    __half2 o1 = __floats2half2_rn(acc.z, acc.w);
    uint2 ov = make_uint2(*(uint32_t*)&o0, *(uint32_t*)&o1);
    *(uint2*)(out + (size_t)node * 128 + lane * 4) = ov;
}

__global__ void __launch_bounds__(256) agg256h_kernel(const __half* __restrict__ h,
                                                      __half* __restrict__ out)
{
    int node = blockIdx.x * 8 + (threadIdx.x >> 5);
    if (node >= N_NODES) return;
    int lane = threadIdx.x & 31;
    float wd = g_dinv[node];
    float acc[8];
    {
        uint4 sv = *(const uint4*)(h + (size_t)node * 256 + lane * 8);
        const __half2* hp = (const __half2*)&sv;
        float ws = wd * wd;
#pragma unroll
        for (int q = 0; q < 4; q++) {
            float2 f = __half22float2(hp[q]);
            acc[2 * q] = f.x * ws;
            acc[2 * q + 1] = f.y * ws;
        }
    }
    int e = g_offs[node], e1 = g_offs[node + 1];
    for (; e + 2 <= e1; e += 2) {
        int n0 = g_csrc[e], n1 = g_csrc[e + 1];
        float w0 = g_dinv[n0] * wd, w1 = g_dinv[n1] * wd;
        uint4 v0 = *(const uint4*)(h + (size_t)n0 * 256 + lane * 8);
        uint4 v1 = *(const uint4*)(h + (size_t)n1 * 256 + lane * 8);
        const __half2* p0 = (const __half2*)&v0;
        const __half2* p1 = (const __half2*)&v1;
#pragma unroll
        for (int q = 0; q < 4; q++) {
            float2 f0 = __half22float2(p0[q]);
            float2 f1 = __half22float2(p1[q]);
            acc[2 * q]     += f0.x * w0 + f1.x * w1;
            acc[2 * q + 1] += f0.y * w0 + f1.y * w1;
        }
    }
    if (e < e1) {
        int n0 = g_csrc[e];
        float w0 = g_dinv[n0] * wd;
        uint4 v0 = *(const uint4*)(h + (size_t)n0 * 256 + lane * 8);
        const __half2* p0 = (const __half2*)&v0;
#pragma unroll
        for (int q = 0; q < 4; q++) {
            float2 f0 = __half22float2(p0[q]);
            acc[2 * q]     += f0.x * w0;
            acc[2 * q + 1] += f0.y * w0;
        }
    }
    __half2 o0 = __floats2half2_rn(acc[0], acc[1]);
    __half2 o1 = __floats2half2_rn(acc[2], acc[3]);
    __half2 o2 = __floats2half2_rn(acc[4], acc[5]);
    __half2 o3 = __floats2half2_rn(acc[6], acc[7]);
    uint4 ov = make_uint4(*(uint32_t*)&o0, *(uint32_t*)&o1, *(uint32_t*)&o2, *(uint32_t*)&o3);
    *(uint4*)(out + (size_t)node * 256 + lane * 8) = ov;
}

// ---------------- fp16 mma (A exact fp16; B = Bh + Bl split) ----------------
__device__ __forceinline__ void mma_f16(float* c, const uint32_t* a, const uint32_t* b) {
    asm volatile(
        "mma.sync.aligned.m16n8k16.row.col.f32.f16.f16.f32 "
        "{%0,%1,%2,%3}, {%4,%5,%6,%7}, {%8,%9}, {%0,%1,%2,%3};"
        : "+f"(c[0]), "+f"(c[1]), "+f"(c[2]), "+f"(c[3])
        : "r"(a[0]), "r"(a[1]), "r"(a[2]), "r"(a[3]), "r"(b[0]), "r"(b[1]));
}

// ---- GEMM + bias + ReLU, all-fp16 operands, fp32 accum; fp16 output ----
#define HSTR 40   // fp16 stride (halves); word stride 20 -> conflict-free frags

__global__ void __launch_bounds__(256) gemm_f16_kernel(
    const __half* __restrict__ A, const __half* __restrict__ Bh,
    const __half* __restrict__ Bl, const float* __restrict__ bias,
    __half* __restrict__ Ch, const float* __restrict__ gatew,
    int M, int N, int K)
{
    __shared__ __align__(16) __half As[128 * HSTR];
    __shared__ __align__(16) __half Bhs[128 * HSTR];
    __shared__ __align__(16) __half Bls[128 * HSTR];
    __shared__ float sgate[128];

    int tid = threadIdx.x;
    int lane = tid & 31;
    int wid = tid >> 5;
    int warp_m = wid >> 2;         // 0..1
    int warp_n = wid & 3;          // 0..3
    int g = lane >> 2;             // group 0..7
    int t = lane & 3;              // thread-in-group 0..3
    int row0 = blockIdx.x * 128;
    int col0 = blockIdx.y * 128;

    if (gatew && tid < 128) sgate[tid] = 0.f;

    float acc[4][4][4];
#pragma unroll
    for (int i = 0; i < 4; i++)
#pragma unroll
        for (int j = 0; j < 4; j++)
#pragma unroll
            for (int r = 0; r < 4; r++) acc[i][j][r] = 0.f;

    for (int k0 = 0; k0 < K; k0 += 32) {
#pragma unroll
        for (int l = 0; l < 2; l++) {
            int f = tid + l * 256;
            int r = f >> 2, c8 = f & 3;
            int grow = row0 + r;
            uint4 v = make_uint4(0u, 0u, 0u, 0u);
            if (grow < M) v = *(const uint4*)(A + (size_t)grow * K + k0 + c8 * 8);
            *(uint4*)&As[r * HSTR + c8 * 8] = v;
        }
#pragma unroll
        for (int l = 0; l < 2; l++) {
            int f = tid + l * 256;
            int r = f >> 2, c8 = f & 3;
            size_t go = (size_t)(col0 + r) * K + k0 + c8 * 8;
            *(uint4*)&Bhs[r * HSTR + c8 * 8] = *(const uint4*)(Bh + go);
            *(uint4*)&Bls[r * HSTR + c8 * 8] = *(const uint4*)(Bl + go);
        }
        __syncthreads();

#pragma unroll
        for (int kc = 0; kc < 2; kc++) {
            uint32_t bh[4][2], bl[4][2];
#pragma unroll
            for (int tn = 0; tn < 4; tn++) {
                int n = warp_n * 32 + tn * 8 + g;
                int base = n * HSTR + kc * 16 + 2 * t;
                bh[tn][0] = *(const uint32_t*)&Bhs[base];
                bh[tn][1] = *(const uint32_t*)&Bhs[base + 8];
                bl[tn][0] = *(const uint32_t*)&Bls[base];
                bl[tn][1] = *(const uint32_t*)&Bls[base + 8];
            }
#pragma unroll
            for (int tm = 0; tm < 4; tm++) {
                int row = warp_m * 64 + tm * 16 + g;
                int base = row * HSTR + kc * 16 + 2 * t;
                uint32_t a[4];
                a[0] = *(const uint32_t*)&As[base];
                a[1] = *(const uint32_t*)&As[base + 8 * HSTR];
                a[2] = *(const uint32_t*)&As[base + 8];
                a[3] = *(const uint32_t*)&As[base + 8 * HSTR + 8];
#pragma unroll
                for (int tn = 0; tn < 4; tn++) {
                    mma_f16(acc[tm][tn], a, bh[tn]);
                    mma_f16(acc[tm][tn], a, bl[tn]);
                }
            }
        }
        __syncthreads();
    }

    float bv[4][2], gwv[4][2];
#pragma unroll
    for (int tn = 0; tn < 4; tn++) {
        int col = col0 + warp_n * 32 + tn * 8 + 2 * t;
        bv[tn][0] = bias[col];
        bv[tn][1] = bias[col + 1];
        if (gatew) { gwv[tn][0] = gatew[col]; gwv[tn][1] = gatew[col + 1]; }
    }
#pragma unroll
    for (int tm = 0; tm < 4; tm++) {
        int row = row0 + warp_m * 64 + tm * 16 + g;
        float p0 = 0.f, p1 = 0.f;
#pragma unroll
        for (int tn = 0; tn < 4; tn++) {
            int col = col0 + warp_n * 32 + tn * 8 + 2 * t;
            float v0 = fmaxf(acc[tm][tn][0] + bv[tn][0], 0.f);
            float v1 = fmaxf(acc[tm][tn][1] + bv[tn][1], 0.f);
            float v2 = fmaxf(acc[tm][tn][2] + bv[tn][0], 0.f);
            float v3 = fmaxf(acc[tm][tn][3] + bv[tn][1], 0.f);
            if (row < M)     *(__half2*)(Ch + (size_t)row * N + col)       = __floats2half2_rn(v0, v1);
            if (row + 8 < M) *(__half2*)(Ch + (size_t)(row + 8) * N + col) = __floats2half2_rn(v2, v3);
            if (gatew) {
                p0 += v0 * gwv[tn][0] + v1 * gwv[tn][1];
                p1 += v2 * gwv[tn][0] + v3 * gwv[tn][1];
            }
        }
        if (gatew) {
            p0 += __shfl_xor_sync(0xffffffffu, p0, 1);
            p0 += __shfl_xor_sync(0xffffffffu, p0, 2);
            p1 += __shfl_xor_sync(0xffffffffu, p1, 1);
            p1 += __shfl_xor_sync(0xffffffffu, p1, 2);
            if (t == 0) {
                int rl = warp_m * 64 + tm * 16 + g;
                atomicAdd(&sgate[rl], p0);
                atomicAdd(&sgate[rl + 8], p1);
            }
        }
    }
    if (gatew) {
        __syncthreads();
        if (tid < 128 && row0 + tid < M) atomicAdd(&g_gate[row0 + tid], sgate[tid]);
    }
}

// ------- segment softmax + weighted sum over fp16 x -> graph embeddings [G, 512] -------
__global__ void __launch_bounds__(256) softmax_emb_kernel(const __half* __restrict__ xh)
{
    __shared__ float red[8];
    __shared__ float salpha[256];
    __shared__ float bcast;
    int g = blockIdx.x, tid = threadIdx.x;
    int lane = tid & 31, wid = tid >> 5;
    int s = g_goffs[g], e = g_goffs[g + 1];

    float m = -INFINITY;
    for (int i = s + tid; i < e; i += 256) m = fmaxf(m, g_gate[i]);
#pragma unroll
    for (int o = 16; o > 0; o >>= 1) m = fmaxf(m, __shfl_xor_sync(0xffffffffu, m, o));
    if (lane == 0) red[wid] = m;
    __syncthreads();
    if (wid == 0) {
        float x = (lane < 8) ? red[lane] : -INFINITY;
#pragma unroll
        for (int o = 4; o > 0; o >>= 1) x = fmaxf(x, __shfl_xor_sync(0xffffffffu, x, o));
        if (lane == 0) bcast = x;
    }
    __syncthreads();
    m = bcast;

    float sum = 0.f;
    for (int i = s + tid; i < e; i += 256) sum += expf(g_gate[i] - m);
#pragma unroll
    for (int o = 16; o > 0; o >>= 1) sum += __shfl_xor_sync(0xffffffffu, sum, o);
    if (lane == 0) red[wid] = sum;
    __syncthreads();
    if (wid == 0) {
        float x = (lane < 8) ? red[lane] : 0.f;
#pragma unroll
        for (int o = 4; o > 0; o >>= 1) x += __shfl_xor_sync(0xffffffffu, x, o);
        if (lane == 0) bcast = x;
    }
    __syncthreads();
    float inv = (e > s) ? 1.f / bcast : 0.f;

    float acc0 = 0.f, acc1 = 0.f;
    for (int start = s; start < e; start += 256) {
        int i = start + tid;
        salpha[tid] = (i < e) ? expf(g_gate[i] - m) * inv : 0.f;
        __syncthreads();
        int cnt = min(256, e - start);
        for (int k = 0; k < cnt; k++) {
            float a = salpha[k];
            const __half* xr = xh + (size_t)(start + k) * 512;
            acc0 += __half2float(xr[tid]) * a;
            acc1 += __half2float(xr[tid + 256]) * a;
        }
        __syncthreads();
    }
    g_emb[g * 512 + tid] = acc0;
    g_emb[g * 512 + 256 + tid] = acc1;
}

// ---- small fp32 tiled GEMM: C[G,N] = A[G,K] @ W[N,K]^T + bias ----
// tiles 32(G) x 64(N) x 16(K); 256 threads, each 2x4 outputs.
#define SG_BM 32
#define SG_BN 64
#define SG_BK 16

__global__ void __launch_bounds__(256) sgemm_small_kernel(
    const float* __restrict__ A, const float* __restrict__ W,
    const float* __restrict__ bias, float* __restrict__ C,
    int G, int N, int K)
{
    __shared__ float As[SG_BK][SG_BM + 1];
    __shared__ float Ws[SG_BN][SG_BK + 1];
    int tid = threadIdx.x;
    int row0 = blockIdx.x * SG_BM;
    int col0 = blockIdx.y * SG_BN;
    int tn = tid & 15;
    int tm = tid >> 4;
    float acc[2][4] = {};

    for (int k0 = 0; k0 < K; k0 += SG_BK) {
        // A tile: 32 x 16, coalesced (c fastest)
#pragma unroll
        for (int l = 0; l < 2; l++) {
            int f = tid + l * 256;
            int r = f >> 4, c = f & 15;
            As[c][r] = A[(size_t)(row0 + r) * K + k0 + c];
        }
        // W tile: 64 x 16, coalesced (c fastest), stored [n][k]
#pragma unroll
        for (int l = 0; l < 4; l++) {
            int f = tid + l * 256;
            int n = f >> 4, c = f & 15;
            Ws[n][c] = W[(size_t)(col0 + n) * K + k0 + c];
        }
        __syncthreads();
#pragma unroll
        for (int k = 0; k < SG_BK; k++) {
            float a0 = As[k][tm * 2];
            float a1 = As[k][tm * 2 + 1];
#pragma unroll
            for (int j = 0; j < 4; j++) {
                float b = Ws[tn * 4 + j][k];
                acc[0][j] += a0 * b;
                acc[1][j] += a1 * b;
            }
        }
        __syncthreads();
    }
#pragma unroll
    for (int i = 0; i < 2; i++) {
        int gg = row0 + tm * 2 + i;
#pragma unroll
        for (int j = 0; j < 4; j++) {
            int nn = col0 + tn * 4 + j;
            C[(size_t)gg * N + nn] = acc[i][j] + bias[nn];
        }
    }
}

// ---- GRU activation: h = (1-z)*n from gi (= x@wih^T + bih) and bhh; h0 = 0 ----
__global__ void gru_act_kernel(const float* __restrict__ gi,
                               const float* __restrict__ bhh,
                               float* __restrict__ h)
{
    int idx = blockIdx.x * blockDim.x + threadIdx.x;
    if (idx >= N_GRAPHS * GRUH) return;
    int g = idx >> 8, j = idx & 255;
    const float* row = gi + (size_t)g * 3 * GRUH;
    float r = 1.f / (1.f + expf(-(row[j] + bhh[j])));
    float z = 1.f / (1.f + expf(-(row[j + 256] + bhh[j + 256])));
    float n = tanhf(row[j + 512] + r * bhh[j + 512]);
    h[idx] = (1.f - z) * n;
}

// ---------------- launch ----------------
extern "C" void kernel_launch(void* const* d_in, const int* in_sizes, int n_in,
                              void* d_out, int out_size)
{
    const float* x       = (const float*)d_in[0];
    const void*  ei      = d_in[1];
    const void*  batch   = d_in[2];
    const float* w0 = (const float*)d_in[3];  const float* b0 = (const float*)d_in[4];
    const float* w1 = (const float*)d_in[5];  const float* b1 = (const float*)d_in[6];
    const float* w2 = (const float*)d_in[7];  const float* b2 = (const float*)d_in[8];
    const float* gate_w = (const float*)d_in[9];
    const float* gate_b = (const float*)d_in[10];
    const float* wih0 = (const float*)d_in[11];
    const float* bih0 = (const float*)d_in[13];
    const float* bhh0 = (const float*)d_in[14];
    const float* wih1 = (const float*)d_in[15];
    const float* bih1 = (const float*)d_in[17];
    const float* bhh1 = (const float*)d_in[18];
    const float* proj_w = (const float*)d_in[19];
    const float* proj_b = (const float*)d_in[20];
    float* out = (float*)d_out;

    __half *pH, *pA, *pWh, *pWl;
    float *pEmb, *pGi, *pH1, *pH2;
    cudaGetSymbolAddress((void**)&pH,   g_hbuf);
    cudaGetSymbolAddress((void**)&pA,   g_abuf);
    cudaGetSymbolAddress((void**)&pWh,  g_bwh);
    cudaGetSymbolAddress((void**)&pWl,  g_bwl);
    cudaGetSymbolAddress((void**)&pEmb, g_emb);
    cudaGetSymbolAddress((void**)&pGi,  g_gi);
    cudaGetSymbolAddress((void**)&pH1,  g_h1);
    cudaGetSymbolAddress((void**)&pH2,  g_h2);

    // preprocessing
    init_kernel<<<256, 256>>>((const int*)ei, gate_b);
    split_weights_kernel<<<(WTOT + 255) / 256, 256>>>(w0, w1, w2);
    count_kernel<<<1024, 256>>>(ei, batch);
    part_sum_kernel<<<NPART, 256>>>();
    scan_parts_kernel<<<1, 256>>>();
    final_scan_kernel<<<NPART, 256>>>();
    fill_kernel<<<1024, 256>>>(ei);

    int gM = (N_NODES + 127) / 128;
    int gAgg = (N_NODES + 7) / 8;

    // GCN layers (agg -> fp16 GEMM)
    agg64w_kernel<<<gAgg, 256>>>(x, pA);
    gemm_f16_kernel<<<dim3(gM, 1), 256>>>(pA, pWh + WOFF0, pWl + WOFF0, b0, pH, nullptr,
                                          N_NODES, 128, 64);
    agg128h_kernel<<<gAgg, 256>>>(pH, pA);
    gemm_f16_kernel<<<dim3(gM, 2), 256>>>(pA, pWh + WOFF1, pWl + WOFF1, b1, pH, nullptr,
                                          N_NODES, 256, 128);
    agg256h_kernel<<<gAgg, 256>>>(pH, pA);
    gemm_f16_kernel<<<dim3(gM, 4), 256>>>(pA, pWh + WOFF2, pWl + WOFF2, b2, pH, gate_w,
                                          N_NODES, 512, 256);

    // attentional aggregation
    softmax_emb_kernel<<<N_GRAPHS, 256>>>(pH);

    // GRU layer 0: gi = emb @ wih0^T + bih0  -> activation -> h1
    sgemm_small_kernel<<<dim3(N_GRAPHS / SG_BM, 768 / SG_BN), 256>>>(pEmb, wih0, bih0, pGi,
                                                                     N_GRAPHS, 768, 512);
    gru_act_kernel<<<(N_GRAPHS * GRUH + 255) / 256, 256>>>(pGi, bhh0, pH1);
    // GRU layer 1: gi = h1 @ wih1^T + bih1 -> activation -> h2
    sgemm_small_kernel<<<dim3(N_GRAPHS / SG_BM, 768 / SG_BN), 256>>>(pH1, wih1, bih1, pGi,
                                                                     N_GRAPHS, 768, 256);
    gru_act_kernel<<<(N_GRAPHS * GRUH + 255) / 256, 256>>>(pGi, bhh1, pH2);
    // projection: out = h2 @ proj_w^T + proj_b
    sgemm_small_kernel<<<dim3(N_GRAPHS / SG_BM, 512 / SG_BN), 256>>>(pH2, proj_w, proj_b, out,
                                                                     N_GRAPHS, 512, 256);
}

// round 12
// speedup vs baseline: 1.4470x; 1.1204x over previous
#include <cuda_runtime.h>
#include <cuda_fp16.h>
#include <math.h>
#include <stdint.h>

#define N_NODES  50000
#define N_EDGES  800000
#define N_GRAPHS 256
#define DMAX     512
#define GRUH     256
#define NPART    196   // ceil(50000/256)

// weight segments (halves): L0 64x128, L1 128x256, L2 256x512
#define WOFF0 0
#define WOFF1 8192
#define WOFF2 40960
#define WTOT  172032

// ---------------- scratch (device globals; no allocation allowed) ----------------
__device__ __align__(16) __half g_hbuf[(size_t)N_NODES * DMAX];   // layer outputs / xh (fp16)
__device__ __align__(16) __half g_abuf[(size_t)N_NODES * 256];    // agg outputs / GEMM A (fp16)
__device__ __align__(16) __half g_bwh[WTOT];                      // weights fp16, [n][k]
__device__ float g_dinv[N_NODES];
__device__ int   g_counts[N_NODES];
__device__ int   g_rank[N_EDGES];
__device__ int   g_offs[N_NODES + 1];
__device__ int   g_part[NPART];
__device__ int   g_csrc[N_EDGES];
__device__ int   g_gcounts[N_GRAPHS];
__device__ int   g_goffs[N_GRAPHS + 1];
__device__ float g_gate[N_NODES];
__device__ __align__(16) float g_emb[N_GRAPHS * 512];
__device__ __align__(16) float g_gi[N_GRAPHS * 3 * GRUH];
__device__ float g_h1[N_GRAPHS * GRUH];
__device__ float g_h2[N_GRAPHS * GRUH];
__device__ int   g_is64;

__device__ __forceinline__ int load_idx(const void* p, long long i, int is64) {
    return is64 ? (int)((const long long*)p)[i] : ((const int*)p)[i];
}

// ------- init: detect index width, zero counters, seed gate bias, x -> fp16 -------
__global__ void init_kernel(const int* __restrict__ ei_raw, const float* __restrict__ gb,
                            const float* __restrict__ x, __half* __restrict__ xh) {
    int i = blockIdx.x * blockDim.x + threadIdx.x;
    int stride = gridDim.x * blockDim.x;
    if (blockIdx.x == 0 && threadIdx.x < 32) {
        int lane = threadIdx.x;
        int bad = 0;
#pragma unroll
        for (int k = 0; k < 4; k++) bad |= ei_raw[2 * (lane + k * 32) + 1];
        unsigned m = __ballot_sync(0xffffffffu, bad != 0);
        if (lane == 0) g_is64 = (m == 0) ? 1 : 0;
    }
    float gbias = gb[0];
    for (int k = i; k < N_NODES; k += stride) {
        g_counts[k] = 0; g_gate[k] = gbias;
    }
    for (int k = i; k < N_GRAPHS; k += stride) g_gcounts[k] = 0;
    // x (50000x64 fp32) -> xh fp16, vectorized float2 -> half2
    int total2 = N_NODES * 32;   // pairs
    const float2* x2 = (const float2*)x;
    __half2* xh2 = (__half2*)xh;
    for (int k = i; k < total2; k += stride) {
        float2 v = x2[k];
        xh2[k] = __floats2half2_rn(v.x, v.y);
    }
}

// -------- pre-convert all 3 weight matrices to fp16, transposed [n][k] --------
__global__ void split_weights_kernel(const float* __restrict__ w0,
                                     const float* __restrict__ w1,
                                     const float* __restrict__ w2) {
    int i = blockIdx.x * blockDim.x + threadIdx.x;
    if (i >= WTOT) return;
    const float* B; int K, N, idx;
    if (i < WOFF1)      { B = w0; K = 64;  N = 128; idx = i - WOFF0; }
    else if (i < WOFF2) { B = w1; K = 128; N = 256; idx = i - WOFF1; }
    else                { B = w2; K = 256; N = 512; idx = i - WOFF2; }
    int n = idx / K, k = idx - n * K;
    g_bwh[i] = __float2half_rn(B[(size_t)k * N + n]);
}

// ---------- count degrees; record each edge's rank within its dst bucket ----------
__global__ void count_kernel(const void* __restrict__ ei, const void* __restrict__ batch) {
    int is64 = g_is64;
    int i = blockIdx.x * blockDim.x + threadIdx.x;
    int stride = gridDim.x * blockDim.x;
    for (int e = i; e < N_EDGES; e += stride) {
        int d = load_idx(ei, (long long)N_EDGES + e, is64);   // dst = edge_index[1]
        g_rank[e] = atomicAdd(&g_counts[d], 1);
    }
    for (int v = i; v < N_NODES; v += stride) {
        int b = load_idx(batch, v, is64);
        atomicAdd(&g_gcounts[b], 1);
    }
}

// -------- hierarchical exclusive scan of g_counts -> g_offs (+ fused dinv) --------
__global__ void __launch_bounds__(256) part_sum_kernel() {
    __shared__ int red[8];
    int b = blockIdx.x, t = threadIdx.x;
    int i = b * 256 + t;
    int cnt = (i < N_NODES) ? g_counts[i] : 0;
    if (i < N_NODES) g_dinv[i] = rsqrtf((float)(cnt + 1));  // +1 self-loop
    int v = cnt;
#pragma unroll
    for (int o = 16; o > 0; o >>= 1) v += __shfl_xor_sync(0xffffffffu, v, o);
    if ((t & 31) == 0) red[t >> 5] = v;
    __syncthreads();
    if (t == 0) {
        int s = 0;
#pragma unroll
        for (int w = 0; w < 8; w++) s += red[w];
        g_part[b] = s;
    }
}

__global__ void __launch_bounds__(256) scan_parts_kernel() {
    __shared__ int sh[256];
    int t = threadIdx.x;
    int v = (t < NPART) ? g_part[t] : 0;
    sh[t] = v;
    __syncthreads();
    for (int d = 1; d < 256; d <<= 1) {
        int x = (t >= d) ? sh[t - d] : 0;
        __syncthreads();
        sh[t] += x;
        __syncthreads();
    }
    if (t < NPART) g_part[t] = sh[t] - v;
    __syncthreads();
    int gc = g_gcounts[t];
    sh[t] = gc;
    __syncthreads();
    for (int d = 1; d < 256; d <<= 1) {
        int x = (t >= d) ? sh[t - d] : 0;
        __syncthreads();
        sh[t] += x;
        __syncthreads();
    }
    g_goffs[t] = sh[t] - gc;
    if (t == 255) g_goffs[256] = sh[255];
}

__global__ void __launch_bounds__(256) final_scan_kernel() {
    __shared__ int sh[256];
    int b = blockIdx.x, t = threadIdx.x;
    int i = b * 256 + t;
    int v = (i < N_NODES) ? g_counts[i] : 0;
    sh[t] = v;
    __syncthreads();
    for (int d = 1; d < 256; d <<= 1) {
        int x = (t >= d) ? sh[t - d] : 0;
        __syncthreads();
        sh[t] += x;
        __syncthreads();
    }
    int base = g_part[b];
    if (i < N_NODES) g_offs[i] = base + sh[t] - v;
    if (i == N_NODES - 1) g_offs[N_NODES] = base + sh[t];
}

// ---------- CSR fill: atomic-free (uses precomputed ranks) ----------
__global__ void fill_kernel(const void* __restrict__ ei) {
    int is64 = g_is64;
    int i = blockIdx.x * blockDim.x + threadIdx.x;
    int stride = gridDim.x * blockDim.x;
    for (int e = i; e < N_EDGES; e += stride) {
        int d = load_idx(ei, (long long)N_EDGES + e, is64);
        int s = load_idx(ei, e, is64);
        g_csrc[g_offs[d] + g_rank[e]] = s;
    }
}

// ------------- GCN aggregation BEFORE transform; fp16 in / fp16 out -------------
// layer 0: 64-wide fp16 gather (128B rows)
__global__ void __launch_bounds__(256) agg64h_kernel(const __half* __restrict__ h,
                                                     __half* __restrict__ out)
{
    int node = blockIdx.x * 8 + (threadIdx.x >> 5);
    if (node >= N_NODES) return;
    int lane = threadIdx.x & 31;
    float wd = g_dinv[node];
    float2 acc = __half22float2(*(const __half2*)(h + (size_t)node * 64 + lane * 2));
    float ws = wd * wd;
    acc.x *= ws; acc.y *= ws;
    int e = g_offs[node], e1 = g_offs[node + 1];
    for (; e + 2 <= e1; e += 2) {
        int s0 = g_csrc[e], s1 = g_csrc[e + 1];
        float w0 = g_dinv[s0] * wd, w1 = g_dinv[s1] * wd;
        float2 v0 = __half22float2(*(const __half2*)(h + (size_t)s0 * 64 + lane * 2));
        float2 v1 = __half22float2(*(const __half2*)(h + (size_t)s1 * 64 + lane * 2));
        acc.x += v0.x * w0 + v1.x * w1;
        acc.y += v0.y * w0 + v1.y * w1;
    }
    if (e < e1) {
        int s0 = g_csrc[e];
        float w0 = g_dinv[s0] * wd;
        float2 v0 = __half22float2(*(const __half2*)(h + (size_t)s0 * 64 + lane * 2));
        acc.x += v0.x * w0; acc.y += v0.y * w0;
    }
    *(__half2*)(out + (size_t)node * 64 + lane * 2) = __floats2half2_rn(acc.x, acc.y);
}

__global__ void __launch_bounds__(256) agg128h_kernel(const __half* __restrict__ h,
                                                      __half* __restrict__ out)
{
    int node = blockIdx.x * 8 + (threadIdx.x >> 5);
    if (node >= N_NODES) return;
    int lane = threadIdx.x & 31;
    float wd = g_dinv[node];
    const __half2* selfp = (const __half2*)(h + (size_t)node * 128 + lane * 4);
    float2 s0f = __half22float2(selfp[0]);
    float2 s1f = __half22float2(selfp[1]);
    float ws = wd * wd;
    float4 acc = make_float4(s0f.x * ws, s0f.y * ws, s1f.x * ws, s1f.y * ws);
    int e = g_offs[node], e1 = g_offs[node + 1];
    for (; e + 2 <= e1; e += 2) {
        int n0 = g_csrc[e], n1 = g_csrc[e + 1];
        float w0 = g_dinv[n0] * wd, w1 = g_dinv[n1] * wd;
        const __half2* p0 = (const __half2*)(h + (size_t)n0 * 128 + lane * 4);
        const __half2* p1 = (const __half2*)(h + (size_t)n1 * 128 + lane * 4);
        float2 fa0 = __half22float2(p0[0]), fa1 = __half22float2(p0[1]);
        float2 fb0 = __half22float2(p1[0]), fb1 = __half22float2(p1[1]);
        acc.x += fa0.x * w0 + fb0.x * w1;
        acc.y += fa0.y * w0 + fb0.y * w1;
        acc.z += fa1.x * w0 + fb1.x * w1;
        acc.w += fa1.y * w0 + fb1.y * w1;
    }
    if (e < e1) {
        int n0 = g_csrc[e];
        float w0 = g_dinv[n0] * wd;
        const __half2* p0 = (const __half2*)(h + (size_t)n0 * 128 + lane * 4);
        float2 fa0 = __half22float2(p0[0]), fa1 = __half22float2(p0[1]);
        acc.x += fa0.x * w0; acc.y += fa0.y * w0;
        acc.z += fa1.x * w0; acc.w += fa1.y * w0;
    }
    __half2 o0 = __floats2half2_rn(acc.x, acc.y);
    __half2 o1 = __floats2half2_rn(acc.z, acc.w);
    uint2 ov = make_uint2(*(uint32_t*)&o0, *(uint32_t*)&o1);
    *(uint2*)(out + (size_t)node * 128 + lane * 4) = ov;
}

__global__ void __launch_bounds__(256) agg256h_kernel(const __half* __restrict__ h,
                                                      __half* __restrict__ out)
{
    int node = blockIdx.x * 8 + (threadIdx.x >> 5);
    if (node >= N_NODES) return;
    int lane = threadIdx.x & 31;
    float wd = g_dinv[node];
    float acc[8];
    {
        uint4 sv = *(const uint4*)(h + (size_t)node * 256 + lane * 8);
        const __half2* hp = (const __half2*)&sv;
        float ws = wd * wd;
#pragma unroll
        for (int q = 0; q < 4; q++) {
            float2 f = __half22float2(hp[q]);
            acc[2 * q] = f.x * ws;
            acc[2 * q + 1] = f.y * ws;
        }
    }
    int e = g_offs[node], e1 = g_offs[node + 1];
    for (; e + 2 <= e1; e += 2) {
        int n0 = g_csrc[e], n1 = g_csrc[e + 1];
        float w0 = g_dinv[n0] * wd, w1 = g_dinv[n1] * wd;
        uint4 v0 = *(const uint4*)(h + (size_t)n0 * 256 + lane * 8);
        uint4 v1 = *(const uint4*)(h + (size_t)n1 * 256 + lane * 8);
        const __half2* p0 = (const __half2*)&v0;
        const __half2* p1 = (const __half2*)&v1;
#pragma unroll
        for (int q = 0; q < 4; q++) {
            float2 f0 = __half22float2(p0[q]);
            float2 f1 = __half22float2(p1[q]);
            acc[2 * q]     += f0.x * w0 + f1.x * w1;
            acc[2 * q + 1] += f0.y * w0 + f1.y * w1;
        }
    }
    if (e < e1) {
        int n0 = g_csrc[e];
        float w0 = g_dinv[n0] * wd;
        uint4 v0 = *(const uint4*)(h + (size_t)n0 * 256 + lane * 8);
        const __half2* p0 = (const __half2*)&v0;
#pragma unroll
        for (int q = 0; q < 4; q++) {
            float2 f0 = __half22float2(p0[q]);
            acc[2 * q]     += f0.x * w0;
            acc[2 * q + 1] += f0.y * w0;
        }
    }
    __half2 o0 = __floats2half2_rn(acc[0], acc[1]);
    __half2 o1 = __floats2half2_rn(acc[2], acc[3]);
    __half2 o2 = __floats2half2_rn(acc[4], acc[5]);
    __half2 o3 = __floats2half2_rn(acc[6], acc[7]);
    uint4 ov = make_uint4(*(uint32_t*)&o0, *(uint32_t*)&o1, *(uint32_t*)&o2, *(uint32_t*)&o3);
    *(uint4*)(out + (size_t)node * 256 + lane * 8) = ov;
}

// ---------------- fp16 mma ----------------
__device__ __forceinline__ void mma_f16(float* c, const uint32_t* a, const uint32_t* b) {
    asm volatile(
        "mma.sync.aligned.m16n8k16.row.col.f32.f16.f16.f32 "
        "{%0,%1,%2,%3}, {%4,%5,%6,%7}, {%8,%9}, {%0,%1,%2,%3};"
        : "+f"(c[0]), "+f"(c[1]), "+f"(c[2]), "+f"(c[3])
        : "r"(a[0]), "r"(a[1]), "r"(a[2]), "r"(a[3]), "r"(b[0]), "r"(b[1]));
}

// ---- GEMM + bias + ReLU, 1-term fp16 operands, fp32 accum; fp16 output ----
// A [M×K] fp16 row-major; Bh [N×K] fp16 row-major (pre-transposed).
#define HSTR 40   // fp16 stride (halves); word stride 20 -> conflict-free frags

__global__ void __launch_bounds__(256) gemm_f16_kernel(
    const __half* __restrict__ A, const __half* __restrict__ Bh,
    const float* __restrict__ bias,
    __half* __restrict__ Ch, const float* __restrict__ gatew,
    int M, int N, int K)
{
    __shared__ __align__(16) __half As[128 * HSTR];
    __shared__ __align__(16) __half Bhs[128 * HSTR];
    __shared__ float sgate[128];

    int tid = threadIdx.x;
    int lane = tid & 31;
    int wid = tid >> 5;
    int warp_m = wid >> 2;         // 0..1
    int warp_n = wid & 3;          // 0..3
    int g = lane >> 2;             // group 0..7
    int t = lane & 3;              // thread-in-group 0..3
    int row0 = blockIdx.x * 128;
    int col0 = blockIdx.y * 128;

    if (gatew && tid < 128) sgate[tid] = 0.f;

    float acc[4][4][4];
#pragma unroll
    for (int i = 0; i < 4; i++)
#pragma unroll
        for (int j = 0; j < 4; j++)
#pragma unroll
            for (int r = 0; r < 4; r++) acc[i][j][r] = 0.f;

    for (int k0 = 0; k0 < K; k0 += 32) {
#pragma unroll
        for (int l = 0; l < 2; l++) {
            int f = tid + l * 256;
            int r = f >> 2, c8 = f & 3;
            int grow = row0 + r;
            uint4 v = make_uint4(0u, 0u, 0u, 0u);
            if (grow < M) v = *(const uint4*)(A + (size_t)grow * K + k0 + c8 * 8);
            *(uint4*)&As[r * HSTR + c8 * 8] = v;
        }
#pragma unroll
        for (int l = 0; l < 2; l++) {
            int f = tid + l * 256;
            int r = f >> 2, c8 = f & 3;
            size_t go = (size_t)(col0 + r) * K + k0 + c8 * 8;
            *(uint4*)&Bhs[r * HSTR + c8 * 8] = *(const uint4*)(Bh + go);
        }
        __syncthreads();

#pragma unroll
        for (int kc = 0; kc < 2; kc++) {
            uint32_t bh[4][2];
#pragma unroll
            for (int tn = 0; tn < 4; tn++) {
                int n = warp_n * 32 + tn * 8 + g;
                int base = n * HSTR + kc * 16 + 2 * t;
                bh[tn][0] = *(const uint32_t*)&Bhs[base];
                bh[tn][1] = *(const uint32_t*)&Bhs[base + 8];
            }
#pragma unroll
            for (int tm = 0; tm < 4; tm++) {
                int row = warp_m * 64 + tm * 16 + g;
                int base = row * HSTR + kc * 16 + 2 * t;
                uint32_t a[4];
                a[0] = *(const uint32_t*)&As[base];
                a[1] = *(const uint32_t*)&As[base + 8 * HSTR];
                a[2] = *(const uint32_t*)&As[base + 8];
                a[3] = *(const uint32_t*)&As[base + 8 * HSTR + 8];
#pragma unroll
                for (int tn = 0; tn < 4; tn++) {
                    mma_f16(acc[tm][tn], a, bh[tn]);
                }
            }
        }
        __syncthreads();
    }

    float bv[4][2], gwv[4][2];
#pragma unroll
    for (int tn = 0; tn < 4; tn++) {
        int col = col0 + warp_n * 32 + tn * 8 + 2 * t;
        bv[tn][0] = bias[col];
        bv[tn][1] = bias[col + 1];
        if (gatew) { gwv[tn][0] = gatew[col]; gwv[tn][1] = gatew[col + 1]; }
    }
#pragma unroll
    for (int tm = 0; tm < 4; tm++) {
        int row = row0 + warp_m * 64 + tm * 16 + g;
        float p0 = 0.f, p1 = 0.f;
#pragma unroll
        for (int tn = 0; tn < 4; tn++) {
            int col = col0 + warp_n * 32 + tn * 8 + 2 * t;
            float v0 = fmaxf(acc[tm][tn][0] + bv[tn][0], 0.f);
            float v1 = fmaxf(acc[tm][tn][1] + bv[tn][1], 0.f);
            float v2 = fmaxf(acc[tm][tn][2] + bv[tn][0], 0.f);
            float v3 = fmaxf(acc[tm][tn][3] + bv[tn][1], 0.f);
            if (row < M)     *(__half2*)(Ch + (size_t)row * N + col)       = __floats2half2_rn(v0, v1);
            if (row + 8 < M) *(__half2*)(Ch + (size_t)(row + 8) * N + col) = __floats2half2_rn(v2, v3);
            if (gatew) {
                p0 += v0 * gwv[tn][0] + v1 * gwv[tn][1];
                p1 += v2 * gwv[tn][0] + v3 * gwv[tn][1];
            }
        }
        if (gatew) {
            p0 += __shfl_xor_sync(0xffffffffu, p0, 1);
            p0 += __shfl_xor_sync(0xffffffffu, p0, 2);
            p1 += __shfl_xor_sync(0xffffffffu, p1, 1);
            p1 += __shfl_xor_sync(0xffffffffu, p1, 2);
            if (t == 0) {
                int rl = warp_m * 64 + tm * 16 + g;
                atomicAdd(&sgate[rl], p0);
                atomicAdd(&sgate[rl + 8], p1);
            }
        }
    }
    if (gatew) {
        __syncthreads();
        if (tid < 128 && row0 + tid < M) atomicAdd(&g_gate[row0 + tid], sgate[tid]);
    }
}

// ------- segment softmax + weighted sum over fp16 x -> graph embeddings [G, 512] -------
__global__ void __launch_bounds__(256) softmax_emb_kernel(const __half* __restrict__ xh)
{
    __shared__ float red[8];
    __shared__ float salpha[256];
    __shared__ float bcast;
    int g = blockIdx.x, tid = threadIdx.x;
    int lane = tid & 31, wid = tid >> 5;
    int s = g_goffs[g], e = g_goffs[g + 1];

    float m = -INFINITY;
    for (int i = s + tid; i < e; i += 256) m = fmaxf(m, g_gate[i]);
#pragma unroll
    for (int o = 16; o > 0; o >>= 1) m = fmaxf(m, __shfl_xor_sync(0xffffffffu, m, o));
    if (lane == 0) red[wid] = m;
    __syncthreads();
    if (wid == 0) {
        float x = (lane < 8) ? red[lane] : -INFINITY;
#pragma unroll
        for (int o = 4; o > 0; o >>= 1) x = fmaxf(x, __shfl_xor_sync(0xffffffffu, x, o));
        if (lane == 0) bcast = x;
    }
    __syncthreads();
    m = bcast;

    float sum = 0.f;
    for (int i = s + tid; i < e; i += 256) sum += expf(g_gate[i] - m);
#pragma unroll
    for (int o = 16; o > 0; o >>= 1) sum += __shfl_xor_sync(0xffffffffu, sum, o);
    if (lane == 0) red[wid] = sum;
    __syncthreads();
    if (wid == 0) {
        float x = (lane < 8) ? red[lane] : 0.f;
#pragma unroll
        for (int o = 4; o > 0; o >>= 1) x += __shfl_xor_sync(0xffffffffu, x, o);
        if (lane == 0) bcast = x;
    }
    __syncthreads();
    float inv = (e > s) ? 1.f / bcast : 0.f;

    float acc0 = 0.f, acc1 = 0.f;
    for (int start = s; start < e; start += 256) {
        int i = start + tid;
        salpha[tid] = (i < e) ? expf(g_gate[i] - m) * inv : 0.f;
        __syncthreads();
        int cnt = min(256, e - start);
        for (int k = 0; k < cnt; k++) {
            float a = salpha[k];
            const __half* xr = xh + (size_t)(start + k) * 512;
            acc0 += __half2float(xr[tid]) * a;
            acc1 += __half2float(xr[tid + 256]) * a;
        }
        __syncthreads();
    }
    g_emb[g * 512 + tid] = acc0;
    g_emb[g * 512 + 256 + tid] = acc1;
}

// ---- small fp32 tiled GEMM: C[G,N] = A[G,K] @ W[N,K]^T + bias ----
#define SG_BM 32
#define SG_BN 64
#define SG_BK 16

__global__ void __launch_bounds__(256) sgemm_small_kernel(
    const float* __restrict__ A, const float* __restrict__ W,
    const float* __restrict__ bias, float* __restrict__ C,
    int G, int N, int K)
{
    __shared__ float As[SG_BK][SG_BM + 1];
    __shared__ float Ws[SG_BN][SG_BK + 1];
    int tid = threadIdx.x;
    int row0 = blockIdx.x * SG_BM;
    int col0 = blockIdx.y * SG_BN;
    int tn = tid & 15;
    int tm = tid >> 4;
    float acc[2][4] = {};

    for (int k0 = 0; k0 < K; k0 += SG_BK) {
#pragma unroll
        for (int l = 0; l < 2; l++) {
            int f = tid + l * 256;
            int r = f >> 4, c = f & 15;
            As[c][r] = A[(size_t)(row0 + r) * K + k0 + c];
        }
#pragma unroll
        for (int l = 0; l < 4; l++) {
            int f = tid + l * 256;
            int n = f >> 4, c = f & 15;
            Ws[n][c] = W[(size_t)(col0 + n) * K + k0 + c];
        }
        __syncthreads();
#pragma unroll
        for (int k = 0; k < SG_BK; k++) {
            float a0 = As[k][tm * 2];
            float a1 = As[k][tm * 2 + 1];
#pragma unroll
            for (int j = 0; j < 4; j++) {
                float b = Ws[tn * 4 + j][k];
                acc[0][j] += a0 * b;
                acc[1][j] += a1 * b;
            }
        }
        __syncthreads();
    }
#pragma unroll
    for (int i = 0; i < 2; i++) {
        int gg = row0 + tm * 2 + i;
#pragma unroll
        for (int j = 0; j < 4; j++) {
            int nn = col0 + tn * 4 + j;
            C[(size_t)gg * N + nn] = acc[i][j] + bias[nn];
        }
    }
}

// ---- GRU activation: h = (1-z)*n from gi (= x@wih^T + bih) and bhh; h0 = 0 ----
__global__ void gru_act_kernel(const float* __restrict__ gi,
                               const float* __restrict__ bhh,
                               float* __restrict__ h)
{
    int idx = blockIdx.x * blockDim.x + threadIdx.x;
    if (idx >= N_GRAPHS * GRUH) return;
    int g = idx >> 8, j = idx & 255;
    const float* row = gi + (size_t)g * 3 * GRUH;
    float r = 1.f / (1.f + expf(-(row[j] + bhh[j])));
    float z = 1.f / (1.f + expf(-(row[j + 256] + bhh[j + 256])));
    float n = tanhf(row[j + 512] + r * bhh[j + 512]);
    h[idx] = (1.f - z) * n;
}

// ---------------- launch ----------------
extern "C" void kernel_launch(void* const* d_in, const int* in_sizes, int n_in,
                              void* d_out, int out_size)
{
    const float* x       = (const float*)d_in[0];
    const void*  ei      = d_in[1];
    const void*  batch   = d_in[2];
    const float* w0 = (const float*)d_in[3];  const float* b0 = (const float*)d_in[4];
    const float* w1 = (const float*)d_in[5];  const float* b1 = (const float*)d_in[6];
    const float* w2 = (const float*)d_in[7];  const float* b2 = (const float*)d_in[8];
    const float* gate_w = (const float*)d_in[9];
    const float* gate_b = (const float*)d_in[10];
    const float* wih0 = (const float*)d_in[11];
    const float* bih0 = (const float*)d_in[13];
    const float* bhh0 = (const float*)d_in[14];
    const float* wih1 = (const float*)d_in[15];
    const float* bih1 = (const float*)d_in[17];
    const float* bhh1 = (const float*)d_in[18];
    const float* proj_w = (const float*)d_in[19];
    const float* proj_b = (const float*)d_in[20];
    float* out = (float*)d_out;

    __half *pH, *pA, *pWh;
    float *pEmb, *pGi, *pH1, *pH2;
    cudaGetSymbolAddress((void**)&pH,   g_hbuf);
    cudaGetSymbolAddress((void**)&pA,   g_abuf);
    cudaGetSymbolAddress((void**)&pWh,  g_bwh);
    cudaGetSymbolAddress((void**)&pEmb, g_emb);
    cudaGetSymbolAddress((void**)&pGi,  g_gi);
    cudaGetSymbolAddress((void**)&pH1,  g_h1);
    cudaGetSymbolAddress((void**)&pH2,  g_h2);

    // preprocessing (init also converts x -> fp16 into g_hbuf)
    init_kernel<<<256, 256>>>((const int*)ei, gate_b, x, pH);
    split_weights_kernel<<<(WTOT + 255) / 256, 256>>>(w0, w1, w2);
    count_kernel<<<1024, 256>>>(ei, batch);
    part_sum_kernel<<<NPART, 256>>>();
    scan_parts_kernel<<<1, 256>>>();
    final_scan_kernel<<<NPART, 256>>>();
    fill_kernel<<<1024, 256>>>(ei);

    int gM = (N_NODES + 127) / 128;
    int gAgg = (N_NODES + 7) / 8;

    // GCN layers (fp16 agg -> 1-term fp16 GEMM)
    agg64h_kernel<<<gAgg, 256>>>(pH, pA);
    gemm_f16_kernel<<<dim3(gM, 1), 256>>>(pA, pWh + WOFF0, b0, pH, nullptr,
                                          N_NODES, 128, 64);
    agg128h_kernel<<<gAgg, 256>>>(pH, pA);
    gemm_f16_kernel<<<dim3(gM, 2), 256>>>(pA, pWh + WOFF1, b1, pH, nullptr,
                                          N_NODES, 256, 128);
    agg256h_kernel<<<gAgg, 256>>>(pH, pA);
    gemm_f16_kernel<<<dim3(gM, 4), 256>>>(pA, pWh + WOFF2, b2, pH, gate_w,
                                          N_NODES, 512, 256);

    // attentional aggregation
    softmax_emb_kernel<<<N_GRAPHS, 256>>>(pH);

    // GRU layer 0 + activation
    sgemm_small_kernel<<<dim3(N_GRAPHS / SG_BM, 768 / SG_BN), 256>>>(pEmb, wih0, bih0, pGi,
                                                                     N_GRAPHS, 768, 512);
    gru_act_kernel<<<(N_GRAPHS * GRUH + 255) / 256, 256>>>(pGi, bhh0, pH1);
    // GRU layer 1 + activation
    sgemm_small_kernel<<<dim3(N_GRAPHS / SG_BM, 768 / SG_BN), 256>>>(pH1, wih1, bih1, pGi,
                                                                     N_GRAPHS, 768, 256);
    gru_act_kernel<<<(N_GRAPHS * GRUH + 255) / 256, 256>>>(pGi, bhh1, pH2);
    // projection
    sgemm_small_kernel<<<dim3(N_GRAPHS / SG_BM, 512 / SG_BN), 256>>>(pH2, proj_w, proj_b, out,
                                                                     N_GRAPHS, 512, 256);
}

// round 13
// speedup vs baseline: 1.5571x; 1.0761x over previous
#include <cuda_runtime.h>
#include <cuda_fp16.h>
#include <math.h>
#include <stdint.h>

#define N_NODES  50000
#define N_EDGES  800000
#define N_GRAPHS 256
#define DMAX     512
#define GRUH     256
#define NPART    196   // ceil(50000/256)

// weight segments (halves): L0 64x128, L1 128x256, L2 256x512
#define WOFF0 0
#define WOFF1 8192
#define WOFF2 40960
#define WTOT  172032

// ---------------- scratch (device globals; no allocation allowed) ----------------
__device__ __align__(16) __half g_hbuf[(size_t)N_NODES * DMAX];   // layer outputs / xh (fp16)
__device__ __align__(16) __half g_abuf[(size_t)N_NODES * 256];    // agg outputs / GEMM A (fp16)
__device__ __align__(16) __half g_bwh[WTOT];                      // weights fp16, [n][k]
__device__ float g_dinv[N_NODES];
__device__ int   g_counts[N_NODES];
__device__ int   g_rank[N_EDGES];
__device__ int   g_offs[N_NODES + 1];
__device__ int   g_part[NPART];
__device__ int   g_csrc[N_EDGES];
__device__ int   g_gcounts[N_GRAPHS];
__device__ int   g_goffs[N_GRAPHS + 1];
__device__ float g_gate[N_NODES];
__device__ __align__(16) float g_emb[N_GRAPHS * 512];
__device__ __align__(16) float g_gi[N_GRAPHS * 3 * GRUH];
__device__ float g_h1[N_GRAPHS * GRUH];
__device__ float g_h2[N_GRAPHS * GRUH];
__device__ int   g_is64;

__device__ __forceinline__ int load_idx(const void* p, long long i, int is64) {
    return is64 ? (int)((const long long*)p)[i] : ((const int*)p)[i];
}

// ------- init: detect index width, zero counters, seed gate bias, x -> fp16 -------
__global__ void init_kernel(const int* __restrict__ ei_raw, const float* __restrict__ gb,
                            const float* __restrict__ x, __half* __restrict__ xh) {
    int i = blockIdx.x * blockDim.x + threadIdx.x;
    int stride = gridDim.x * blockDim.x;
    if (blockIdx.x == 0 && threadIdx.x < 32) {
        int lane = threadIdx.x;
        int bad = 0;
#pragma unroll
        for (int k = 0; k < 4; k++) bad |= ei_raw[2 * (lane + k * 32) + 1];
        unsigned m = __ballot_sync(0xffffffffu, bad != 0);
        if (lane == 0) g_is64 = (m == 0) ? 1 : 0;
    }
    float gbias = gb[0];
    for (int k = i; k < N_NODES; k += stride) {
        g_counts[k] = 0; g_gate[k] = gbias;
    }
    for (int k = i; k < N_GRAPHS; k += stride) g_gcounts[k] = 0;
    int total2 = N_NODES * 32;   // float pairs
    const float2* x2 = (const float2*)x;
    __half2* xh2 = (__half2*)xh;
    for (int k = i; k < total2; k += stride) {
        float2 v = x2[k];
        xh2[k] = __floats2half2_rn(v.x, v.y);
    }
}

// -------- pre-convert all 3 weight matrices to fp16, transposed [n][k] --------
__global__ void split_weights_kernel(const float* __restrict__ w0,
                                     const float* __restrict__ w1,
                                     const float* __restrict__ w2) {
    int i = blockIdx.x * blockDim.x + threadIdx.x;
    if (i >= WTOT) return;
    const float* B; int K, N, idx;
    if (i < WOFF1)      { B = w0; K = 64;  N = 128; idx = i - WOFF0; }
    else if (i < WOFF2) { B = w1; K = 128; N = 256; idx = i - WOFF1; }
    else                { B = w2; K = 256; N = 512; idx = i - WOFF2; }
    int n = idx / K, k = idx - n * K;
    g_bwh[i] = __float2half_rn(B[(size_t)k * N + n]);
}

// ---------- count degrees; record each edge's rank within its dst bucket ----------
__global__ void count_kernel(const void* __restrict__ ei, const void* __restrict__ batch) {
    int is64 = g_is64;
    int i = blockIdx.x * blockDim.x + threadIdx.x;
    int stride = gridDim.x * blockDim.x;
    for (int e = i; e < N_EDGES; e += stride) {
        int d = load_idx(ei, (long long)N_EDGES + e, is64);   // dst = edge_index[1]
        g_rank[e] = atomicAdd(&g_counts[d], 1);
    }
    for (int v = i; v < N_NODES; v += stride) {
        int b = load_idx(batch, v, is64);
        atomicAdd(&g_gcounts[b], 1);
    }
}

// -------- hierarchical exclusive scan of g_counts -> g_offs (+ fused dinv) --------
__global__ void __launch_bounds__(256) part_sum_kernel() {
    __shared__ int red[8];
    int b = blockIdx.x, t = threadIdx.x;
    int i = b * 256 + t;
    int cnt = (i < N_NODES) ? g_counts[i] : 0;
    if (i < N_NODES) g_dinv[i] = rsqrtf((float)(cnt + 1));  // +1 self-loop
    int v = cnt;
#pragma unroll
    for (int o = 16; o > 0; o >>= 1) v += __shfl_xor_sync(0xffffffffu, v, o);
    if ((t & 31) == 0) red[t >> 5] = v;
    __syncthreads();
    if (t == 0) {
        int s = 0;
#pragma unroll
        for (int w = 0; w < 8; w++) s += red[w];
        g_part[b] = s;
    }
}

__global__ void __launch_bounds__(256) scan_parts_kernel() {
    __shared__ int sh[256];
    int t = threadIdx.x;
    int v = (t < NPART) ? g_part[t] : 0;
    sh[t] = v;
    __syncthreads();
    for (int d = 1; d < 256; d <<= 1) {
        int x = (t >= d) ? sh[t - d] : 0;
        __syncthreads();
        sh[t] += x;
        __syncthreads();
    }
    if (t < NPART) g_part[t] = sh[t] - v;
    __syncthreads();
    int gc = g_gcounts[t];
    sh[t] = gc;
    __syncthreads();
    for (int d = 1; d < 256; d <<= 1) {
        int x = (t >= d) ? sh[t - d] : 0;
        __syncthreads();
        sh[t] += x;
        __syncthreads();
    }
    g_goffs[t] = sh[t] - gc;
    if (t == 255) g_goffs[256] = sh[255];
}

__global__ void __launch_bounds__(256) final_scan_kernel() {
    __shared__ int sh[256];
    int b = blockIdx.x, t = threadIdx.x;
    int i = b * 256 + t;
    int v = (i < N_NODES) ? g_counts[i] : 0;
    sh[t] = v;
    __syncthreads();
    for (int d = 1; d < 256; d <<= 1) {
        int x = (t >= d) ? sh[t - d] : 0;
        __syncthreads();
        sh[t] += x;
        __syncthreads();
    }
    int base = g_part[b];
    if (i < N_NODES) g_offs[i] = base + sh[t] - v;
    if (i == N_NODES - 1) g_offs[N_NODES] = base + sh[t];
}

// ---------- CSR fill: atomic-free (uses precomputed ranks) ----------
__global__ void fill_kernel(const void* __restrict__ ei) {
    int is64 = g_is64;
    int i = blockIdx.x * blockDim.x + threadIdx.x;
    int stride = gridDim.x * blockDim.x;
    for (int e = i; e < N_EDGES; e += stride) {
        int d = load_idx(ei, (long long)N_EDGES + e, is64);
        int s = load_idx(ei, e, is64);
        g_csrc[g_offs[d] + g_rank[e]] = s;
    }
}

// ------------- GCN aggregation BEFORE transform; fp16 in / fp16 out; MLP=4 -------------
__global__ void __launch_bounds__(256) agg64h_kernel(const __half* __restrict__ h,
                                                     __half* __restrict__ out)
{
    int node = blockIdx.x * 8 + (threadIdx.x >> 5);
    if (node >= N_NODES) return;
    int lane = threadIdx.x & 31;
    float wd = g_dinv[node];
    float2 acc = __half22float2(*(const __half2*)(h + (size_t)node * 64 + lane * 2));
    float ws = wd * wd;
    acc.x *= ws; acc.y *= ws;
    int e = g_offs[node], e1 = g_offs[node + 1];
    for (; e + 4 <= e1; e += 4) {
        int s0 = g_csrc[e], s1 = g_csrc[e + 1], s2 = g_csrc[e + 2], s3 = g_csrc[e + 3];
        float w0 = g_dinv[s0] * wd, w1 = g_dinv[s1] * wd;
        float w2 = g_dinv[s2] * wd, w3 = g_dinv[s3] * wd;
        float2 v0 = __half22float2(*(const __half2*)(h + (size_t)s0 * 64 + lane * 2));
        float2 v1 = __half22float2(*(const __half2*)(h + (size_t)s1 * 64 + lane * 2));
        float2 v2 = __half22float2(*(const __half2*)(h + (size_t)s2 * 64 + lane * 2));
        float2 v3 = __half22float2(*(const __half2*)(h + (size_t)s3 * 64 + lane * 2));
        acc.x += v0.x * w0 + v1.x * w1 + v2.x * w2 + v3.x * w3;
        acc.y += v0.y * w0 + v1.y * w1 + v2.y * w2 + v3.y * w3;
    }
    for (; e < e1; e++) {
        int s0 = g_csrc[e];
        float w0 = g_dinv[s0] * wd;
        float2 v0 = __half22float2(*(const __half2*)(h + (size_t)s0 * 64 + lane * 2));
        acc.x += v0.x * w0; acc.y += v0.y * w0;
    }
    *(__half2*)(out + (size_t)node * 64 + lane * 2) = __floats2half2_rn(acc.x, acc.y);
}

__global__ void __launch_bounds__(256) agg128h_kernel(const __half* __restrict__ h,
                                                      __half* __restrict__ out)
{
    int node = blockIdx.x * 8 + (threadIdx.x >> 5);
    if (node >= N_NODES) return;
    int lane = threadIdx.x & 31;
    float wd = g_dinv[node];
    float acc[4];
    {
        uint2 sv = *(const uint2*)(h + (size_t)node * 128 + lane * 4);
        const __half2* hp = (const __half2*)&sv;
        float ws = wd * wd;
        float2 f0 = __half22float2(hp[0]), f1 = __half22float2(hp[1]);
        acc[0] = f0.x * ws; acc[1] = f0.y * ws; acc[2] = f1.x * ws; acc[3] = f1.y * ws;
    }
    int e = g_offs[node], e1 = g_offs[node + 1];
    for (; e + 4 <= e1; e += 4) {
        int s0 = g_csrc[e], s1 = g_csrc[e + 1], s2 = g_csrc[e + 2], s3 = g_csrc[e + 3];
        float w0 = g_dinv[s0] * wd, w1 = g_dinv[s1] * wd;
        float w2 = g_dinv[s2] * wd, w3 = g_dinv[s3] * wd;
        uint2 v0 = *(const uint2*)(h + (size_t)s0 * 128 + lane * 4);
        uint2 v1 = *(const uint2*)(h + (size_t)s1 * 128 + lane * 4);
        uint2 v2 = *(const uint2*)(h + (size_t)s2 * 128 + lane * 4);
        uint2 v3 = *(const uint2*)(h + (size_t)s3 * 128 + lane * 4);
        const __half2* p0 = (const __half2*)&v0;
        const __half2* p1 = (const __half2*)&v1;
        const __half2* p2 = (const __half2*)&v2;
        const __half2* p3 = (const __half2*)&v3;
#pragma unroll
        for (int q = 0; q < 2; q++) {
            float2 f0 = __half22float2(p0[q]);
            float2 f1 = __half22float2(p1[q]);
            float2 f2 = __half22float2(p2[q]);
            float2 f3 = __half22float2(p3[q]);
            acc[2 * q]     += f0.x * w0 + f1.x * w1 + f2.x * w2 + f3.x * w3;
            acc[2 * q + 1] += f0.y * w0 + f1.y * w1 + f2.y * w2 + f3.y * w3;
        }
    }
    for (; e < e1; e++) {
        int s0 = g_csrc[e];
        float w0 = g_dinv[s0] * wd;
        uint2 v0 = *(const uint2*)(h + (size_t)s0 * 128 + lane * 4);
        const __half2* p0 = (const __half2*)&v0;
#pragma unroll
        for (int q = 0; q < 2; q++) {
            float2 f0 = __half22float2(p0[q]);
            acc[2 * q] += f0.x * w0;
            acc[2 * q + 1] += f0.y * w0;
        }
    }
    __half2 o0 = __floats2half2_rn(acc[0], acc[1]);
    __half2 o1 = __floats2half2_rn(acc[2], acc[3]);
    uint2 ov = make_uint2(*(uint32_t*)&o0, *(uint32_t*)&o1);
    *(uint2*)(out + (size_t)node * 128 + lane * 4) = ov;
}

__global__ void __launch_bounds__(256) agg256h_kernel(const __half* __restrict__ h,
                                                      __half* __restrict__ out)
{
    int node = blockIdx.x * 8 + (threadIdx.x >> 5);
    if (node >= N_NODES) return;
    int lane = threadIdx.x & 31;
    float wd = g_dinv[node];
    float acc[8];
    {
        uint4 sv = *(const uint4*)(h + (size_t)node * 256 + lane * 8);
        const __half2* hp = (const __half2*)&sv;
        float ws = wd * wd;
#pragma unroll
        for (int q = 0; q < 4; q++) {
            float2 f = __half22float2(hp[q]);
            acc[2 * q] = f.x * ws;
            acc[2 * q + 1] = f.y * ws;
        }
    }
    int e = g_offs[node], e1 = g_offs[node + 1];
    for (; e + 4 <= e1; e += 4) {
        int s0 = g_csrc[e], s1 = g_csrc[e + 1], s2 = g_csrc[e + 2], s3 = g_csrc[e + 3];
        float w0 = g_dinv[s0] * wd, w1 = g_dinv[s1] * wd;
        float w2 = g_dinv[s2] * wd, w3 = g_dinv[s3] * wd;
        uint4 v0 = *(const uint4*)(h + (size_t)s0 * 256 + lane * 8);
        uint4 v1 = *(const uint4*)(h + (size_t)s1 * 256 + lane * 8);
        uint4 v2 = *(const uint4*)(h + (size_t)s2 * 256 + lane * 8);
        uint4 v3 = *(const uint4*)(h + (size_t)s3 * 256 + lane * 8);
        const __half2* p0 = (const __half2*)&v0;
        const __half2* p1 = (const __half2*)&v1;
        const __half2* p2 = (const __half2*)&v2;
        const __half2* p3 = (const __half2*)&v3;
#pragma unroll
        for (int q = 0; q < 4; q++) {
            float2 f0 = __half22float2(p0[q]);
            float2 f1 = __half22float2(p1[q]);
            float2 f2 = __half22float2(p2[q]);
            float2 f3 = __half22float2(p3[q]);
            acc[2 * q]     += f0.x * w0 + f1.x * w1 + f2.x * w2 + f3.x * w3;
            acc[2 * q + 1] += f0.y * w0 + f1.y * w1 + f2.y * w2 + f3.y * w3;
        }
    }
    for (; e < e1; e++) {
        int n0 = g_csrc[e];
        float w0 = g_dinv[n0] * wd;
        uint4 v0 = *(const uint4*)(h + (size_t)n0 * 256 + lane * 8);
        const __half2* p0 = (const __half2*)&v0;
#pragma unroll
        for (int q = 0; q < 4; q++) {
            float2 f0 = __half22float2(p0[q]);
            acc[2 * q]     += f0.x * w0;
            acc[2 * q + 1] += f0.y * w0;
        }
    }
    __half2 o0 = __floats2half2_rn(acc[0], acc[1]);
    __half2 o1 = __floats2half2_rn(acc[2], acc[3]);
    __half2 o2 = __floats2half2_rn(acc[4], acc[5]);
    __half2 o3 = __floats2half2_rn(acc[6], acc[7]);
    uint4 ov = make_uint4(*(uint32_t*)&o0, *(uint32_t*)&o1, *(uint32_t*)&o2, *(uint32_t*)&o3);
    *(uint4*)(out + (size_t)node * 256 + lane * 8) = ov;
}

// ---------------- fp16 mma ----------------
__device__ __forceinline__ void mma_f16(float* c, const uint32_t* a, const uint32_t* b) {
    asm volatile(
        "mma.sync.aligned.m16n8k16.row.col.f32.f16.f16.f32 "
        "{%0,%1,%2,%3}, {%4,%5,%6,%7}, {%8,%9}, {%0,%1,%2,%3};"
        : "+f"(c[0]), "+f"(c[1]), "+f"(c[2]), "+f"(c[3])
        : "r"(a[0]), "r"(a[1]), "r"(a[2]), "r"(a[3]), "r"(b[0]), "r"(b[1]));
}

// ---- GEMM + bias + ReLU, fp16 operands, fp32 accum; cp.async double-buffered ----
#define HSTR 40   // fp16 stride (halves); word stride 20 -> conflict-free frags

__global__ void __launch_bounds__(256) gemm_f16_kernel(
    const __half* __restrict__ A, const __half* __restrict__ Bh,
    const float* __restrict__ bias,
    __half* __restrict__ Ch, const float* __restrict__ gatew,
    int M, int N, int K)
{
    __shared__ __align__(16) __half As[2][128 * HSTR];
    __shared__ __align__(16) __half Bhs[2][128 * HSTR];
    __shared__ float sgate[128];

    int tid = threadIdx.x;
    int lane = tid & 31;
    int wid = tid >> 5;
    int warp_m = wid >> 2;         // 0..1
    int warp_n = wid & 3;          // 0..3
    int g = lane >> 2;             // group 0..7
    int t = lane & 3;              // thread-in-group 0..3
    int row0 = blockIdx.x * 128;
    int col0 = blockIdx.y * 128;

    if (gatew && tid < 128) sgate[tid] = 0.f;

    float acc[4][4][4];
#pragma unroll
    for (int i = 0; i < 4; i++)
#pragma unroll
        for (int j = 0; j < 4; j++)
#pragma unroll
            for (int r = 0; r < 4; r++) acc[i][j][r] = 0.f;

    // per-thread tile-load coordinates (fixed across stages)
    int f0 = tid, f1 = tid + 256;
    int ar0 = f0 >> 2, ac0 = (f0 & 3) * 8;
    int ar1 = f1 >> 2, ac1 = (f1 & 3) * 8;

    auto issue_tile = [&](int buf, int k0) {
        {
            int grow = row0 + ar0;
            uint32_t dst = (uint32_t)__cvta_generic_to_shared(&As[buf][ar0 * HSTR + ac0]);
            const __half* src = A + (size_t)grow * K + k0 + ac0;
            int p = (grow < M) ? 16 : 0;
            asm volatile("cp.async.cg.shared.global [%0], [%1], 16, %2;"
                         :: "r"(dst), "l"(src), "r"(p));
        }
        {
            int grow = row0 + ar1;
            uint32_t dst = (uint32_t)__cvta_generic_to_shared(&As[buf][ar1 * HSTR + ac1]);
            const __half* src = A + (size_t)grow * K + k0 + ac1;
            int p = (grow < M) ? 16 : 0;
            asm volatile("cp.async.cg.shared.global [%0], [%1], 16, %2;"
                         :: "r"(dst), "l"(src), "r"(p));
        }
        {
            uint32_t dst = (uint32_t)__cvta_generic_to_shared(&Bhs[buf][ar0 * HSTR + ac0]);
            const __half* src = Bh + (size_t)(col0 + ar0) * K + k0 + ac0;
            asm volatile("cp.async.cg.shared.global [%0], [%1], 16;"
                         :: "r"(dst), "l"(src));
        }
        {
            uint32_t dst = (uint32_t)__cvta_generic_to_shared(&Bhs[buf][ar1 * HSTR + ac1]);
            const __half* src = Bh + (size_t)(col0 + ar1) * K + k0 + ac1;
            asm volatile("cp.async.cg.shared.global [%0], [%1], 16;"
                         :: "r"(dst), "l"(src));
        }
        asm volatile("cp.async.commit_group;");
    };

    int nIter = K >> 5;
    issue_tile(0, 0);
    int buf = 0;
    for (int it = 0; it < nIter; it++) {
        if (it + 1 < nIter) {
            issue_tile(buf ^ 1, (it + 1) * 32);
            asm volatile("cp.async.wait_group 1;");
        } else {
            asm volatile("cp.async.wait_group 0;");
        }
        __syncthreads();

        const __half* Ab = As[buf];
        const __half* Bb = Bhs[buf];
#pragma unroll
        for (int kc = 0; kc < 2; kc++) {
            uint32_t bh[4][2];
#pragma unroll
            for (int tn = 0; tn < 4; tn++) {
                int n = warp_n * 32 + tn * 8 + g;
                int base = n * HSTR + kc * 16 + 2 * t;
                bh[tn][0] = *(const uint32_t*)&Bb[base];
                bh[tn][1] = *(const uint32_t*)&Bb[base + 8];
            }
#pragma unroll
            for (int tm = 0; tm < 4; tm++) {
                int row = warp_m * 64 + tm * 16 + g;
                int base = row * HSTR + kc * 16 + 2 * t;
                uint32_t a[4];
                a[0] = *(const uint32_t*)&Ab[base];
                a[1] = *(const uint32_t*)&Ab[base + 8 * HSTR];
                a[2] = *(const uint32_t*)&Ab[base + 8];
                a[3] = *(const uint32_t*)&Ab[base + 8 * HSTR + 8];
#pragma unroll
                for (int tn = 0; tn < 4; tn++) {
                    mma_f16(acc[tm][tn], a, bh[tn]);
                }
            }
        }
        __syncthreads();
        buf ^= 1;
    }

    float bv[4][2], gwv[4][2];
#pragma unroll
    for (int tn = 0; tn < 4; tn++) {
        int col = col0 + warp_n * 32 + tn * 8 + 2 * t;
        bv[tn][0] = bias[col];
        bv[tn][1] = bias[col + 1];
        if (gatew) { gwv[tn][0] = gatew[col]; gwv[tn][1] = gatew[col + 1]; }
    }
#pragma unroll
    for (int tm = 0; tm < 4; tm++) {
        int row = row0 + warp_m * 64 + tm * 16 + g;
        float p0 = 0.f, p1 = 0.f;
#pragma unroll
        for (int tn = 0; tn < 4; tn++) {
            int col = col0 + warp_n * 32 + tn * 8 + 2 * t;
            float v0 = fmaxf(acc[tm][tn][0] + bv[tn][0], 0.f);
            float v1 = fmaxf(acc[tm][tn][1] + bv[tn][1], 0.f);
            float v2 = fmaxf(acc[tm][tn][2] + bv[tn][0], 0.f);
            float v3 = fmaxf(acc[tm][tn][3] + bv[tn][1], 0.f);
            if (row < M)     *(__half2*)(Ch + (size_t)row * N + col)       = __floats2half2_rn(v0, v1);
            if (row + 8 < M) *(__half2*)(Ch + (size_t)(row + 8) * N + col) = __floats2half2_rn(v2, v3);
            if (gatew) {
                p0 += v0 * gwv[tn][0] + v1 * gwv[tn][1];
                p1 += v2 * gwv[tn][0] + v3 * gwv[tn][1];
            }
        }
        if (gatew) {
            p0 += __shfl_xor_sync(0xffffffffu, p0, 1);
            p0 += __shfl_xor_sync(0xffffffffu, p0, 2);
            p1 += __shfl_xor_sync(0xffffffffu, p1, 1);
            p1 += __shfl_xor_sync(0xffffffffu, p1, 2);
            if (t == 0) {
                int rl = warp_m * 64 + tm * 16 + g;
                atomicAdd(&sgate[rl], p0);
                atomicAdd(&sgate[rl + 8], p1);
            }
        }
    }
    if (gatew) {
        __syncthreads();
        if (tid < 128 && row0 + tid < M) atomicAdd(&g_gate[row0 + tid], sgate[tid]);
    }
}

// ------- segment softmax + weighted sum over fp16 x -> graph embeddings [G, 512] -------
__global__ void __launch_bounds__(256) softmax_emb_kernel(const __half* __restrict__ xh)
{
    __shared__ float red[8];
    __shared__ float salpha[256];
    __shared__ float bcast;
    int g = blockIdx.x, tid = threadIdx.x;
    int lane = tid & 31, wid = tid >> 5;
    int s = g_goffs[g], e = g_goffs[g + 1];

    float m = -INFINITY;
    for (int i = s + tid; i < e; i += 256) m = fmaxf(m, g_gate[i]);
#pragma unroll
    for (int o = 16; o > 0; o >>= 1) m = fmaxf(m, __shfl_xor_sync(0xffffffffu, m, o));
    if (lane == 0) red[wid] = m;
    __syncthreads();
    if (wid == 0) {
        float x = (lane < 8) ? red[lane] : -INFINITY;
#pragma unroll
        for (int o = 4; o > 0; o >>= 1) x = fmaxf(x, __shfl_xor_sync(0xffffffffu, x, o));
        if (lane == 0) bcast = x;
    }
    __syncthreads();
    m = bcast;

    float sum = 0.f;
    for (int i = s + tid; i < e; i += 256) sum += expf(g_gate[i] - m);
#pragma unroll
    for (int o = 16; o > 0; o >>= 1) sum += __shfl_xor_sync(0xffffffffu, sum, o);
    if (lane == 0) red[wid] = sum;
    __syncthreads();
    if (wid == 0) {
        float x = (lane < 8) ? red[lane] : 0.f;
#pragma unroll
        for (int o = 4; o > 0; o >>= 1) x += __shfl_xor_sync(0xffffffffu, x, o);
        if (lane == 0) bcast = x;
    }
    __syncthreads();
    float inv = (e > s) ? 1.f / bcast : 0.f;

    // thread owns columns 2*tid and 2*tid+1 (one half2 load per row)
    float2 acc = make_float2(0.f, 0.f);
    for (int start = s; start < e; start += 256) {
        int i = start + tid;
        salpha[tid] = (i < e) ? expf(g_gate[i] - m) * inv : 0.f;
        __syncthreads();
        int cnt = min(256, e - start);
        const __half2* base = (const __half2*)(xh + (size_t)start * 512);
        for (int k = 0; k < cnt; k++) {
            float a = salpha[k];
            float2 f = __half22float2(base[(size_t)k * 256 + tid]);
            acc.x += f.x * a;
            acc.y += f.y * a;
        }
        __syncthreads();
    }
    g_emb[g * 512 + 2 * tid]     = acc.x;
    g_emb[g * 512 + 2 * tid + 1] = acc.y;
}

// ---- small fp32 tiled GEMM: C[G,N] = A[G,K] @ W[N,K]^T + bias ----
#define SG_BM 32
#define SG_BN 64
#define SG_BK 16

__global__ void __launch_bounds__(256) sgemm_small_kernel(
    const float* __restrict__ A, const float* __restrict__ W,
    const float* __restrict__ bias, float* __restrict__ C,
    int G, int N, int K)
{
    __shared__ float As[SG_BK][SG_BM + 1];
    __shared__ float Ws[SG_BN][SG_BK + 1];
    int tid = threadIdx.x;
    int row0 = blockIdx.x * SG_BM;
    int col0 = blockIdx.y * SG_BN;
    int tn = tid & 15;
    int tm = tid >> 4;
    float acc[2][4] = {};

    for (int k0 = 0; k0 < K; k0 += SG_BK) {
#pragma unroll
        for (int l = 0; l < 2; l++) {
            int f = tid + l * 256;
            int r = f >> 4, c = f & 15;
            As[c][r] = A[(size_t)(row0 + r) * K + k0 + c];
        }
#pragma unroll
        for (int l = 0; l < 4; l++) {
            int f = tid + l * 256;
            int n = f >> 4, c = f & 15;
            Ws[n][c] = W[(size_t)(col0 + n) * K + k0 + c];
        }
        __syncthreads();
#pragma unroll
        for (int k = 0; k < SG_BK; k++) {
            float a0 = As[k][tm * 2];
            float a1 = As[k][tm * 2 + 1];
#pragma unroll
            for (int j = 0; j < 4; j++) {
                float b = Ws[tn * 4 + j][k];
                acc[0][j] += a0 * b;
                acc[1][j] += a1 * b;
            }
        }
        __syncthreads();
    }
#pragma unroll
    for (int i = 0; i < 2; i++) {
        int gg = row0 + tm * 2 + i;
#pragma unroll
        for (int j = 0; j < 4; j++) {
            int nn = col0 + tn * 4 + j;
            C[(size_t)gg * N + nn] = acc[i][j] + bias[nn];
        }
    }
}

// ---- GRU activation: h = (1-z)*n from gi (= x@wih^T + bih) and bhh; h0 = 0 ----
__global__ void gru_act_kernel(const float* __restrict__ gi,
                               const float* __restrict__ bhh,
                               float* __restrict__ h)
{
    int idx = blockIdx.x * blockDim.x + threadIdx.x;
    if (idx >= N_GRAPHS * GRUH) return;
    int g = idx >> 8, j = idx & 255;
    const float* row = gi + (size_t)g * 3 * GRUH;
    float r = 1.f / (1.f + expf(-(row[j] + bhh[j])));
    float z = 1.f / (1.f + expf(-(row[j + 256] + bhh[j + 256])));
    float n = tanhf(row[j + 512] + r * bhh[j + 512]);
    h[idx] = (1.f - z) * n;
}

// ---------------- launch ----------------
extern "C" void kernel_launch(void* const* d_in, const int* in_sizes, int n_in,
                              void* d_out, int out_size)
{
    const float* x       = (const float*)d_in[0];
    const void*  ei      = d_in[1];
    const void*  batch   = d_in[2];
    const float* w0 = (const float*)d_in[3];  const float* b0 = (const float*)d_in[4];
    const float* w1 = (const float*)d_in[5];  const float* b1 = (const float*)d_in[6];
    const float* w2 = (const float*)d_in[7];  const float* b2 = (const float*)d_in[8];
    const float* gate_w = (const float*)d_in[9];
    const float* gate_b = (const float*)d_in[10];
    const float* wih0 = (const float*)d_in[11];
    const float* bih0 = (const float*)d_in[13];
    const float* bhh0 = (const float*)d_in[14];
    const float* wih1 = (const float*)d_in[15];
    const float* bih1 = (const float*)d_in[17];
    const float* bhh1 = (const float*)d_in[18];
    const float* proj_w = (const float*)d_in[19];
    const float* proj_b = (const float*)d_in[20];
    float* out = (float*)d_out;

    __half *pH, *pA, *pWh;
    float *pEmb, *pGi, *pH1, *pH2;
    cudaGetSymbolAddress((void**)&pH,   g_hbuf);
    cudaGetSymbolAddress((void**)&pA,   g_abuf);
    cudaGetSymbolAddress((void**)&pWh,  g_bwh);
    cudaGetSymbolAddress((void**)&pEmb, g_emb);
    cudaGetSymbolAddress((void**)&pGi,  g_gi);
    cudaGetSymbolAddress((void**)&pH1,  g_h1);
    cudaGetSymbolAddress((void**)&pH2,  g_h2);

    // preprocessing (init also converts x -> fp16 into g_hbuf)
    init_kernel<<<256, 256>>>((const int*)ei, gate_b, x, pH);
    split_weights_kernel<<<(WTOT + 255) / 256, 256>>>(w0, w1, w2);
    count_kernel<<<1024, 256>>>(ei, batch);
    part_sum_kernel<<<NPART, 256>>>();
    scan_parts_kernel<<<1, 256>>>();
    final_scan_kernel<<<NPART, 256>>>();
    fill_kernel<<<1024, 256>>>(ei);

    int gM = (N_NODES + 127) / 128;
    int gAgg = (N_NODES + 7) / 8;

    // GCN layers (fp16 agg -> fp16 GEMM, cp.async pipelined)
    agg64h_kernel<<<gAgg, 256>>>(pH, pA);
    gemm_f16_kernel<<<dim3(gM, 1), 256>>>(pA, pWh + WOFF0, b0, pH, nullptr,
                                          N_NODES, 128, 64);
    agg128h_kernel<<<gAgg, 256>>>(pH, pA);
    gemm_f16_kernel<<<dim3(gM, 2), 256>>>(pA, pWh + WOFF1, b1, pH, nullptr,
                                          N_NODES, 256, 128);
    agg256h_kernel<<<gAgg, 256>>>(pH, pA);
    gemm_f16_kernel<<<dim3(gM, 4), 256>>>(pA, pWh + WOFF2, b2, pH, gate_w,
                                          N_NODES, 512, 256);

    // attentional aggregation
    softmax_emb_kernel<<<N_GRAPHS, 256>>>(pH);

    // GRU layer 0 + activation
    sgemm_small_kernel<<<dim3(N_GRAPHS / SG_BM, 768 / SG_BN), 256>>>(pEmb, wih0, bih0, pGi,
                                                                     N_GRAPHS, 768, 512);
    gru_act_kernel<<<(N_GRAPHS * GRUH + 255) / 256, 256>>>(pGi, bhh0, pH1);
    // GRU layer 1 + activation
    sgemm_small_kernel<<<dim3(N_GRAPHS / SG_BM, 768 / SG_BN), 256>>>(pH1, wih1, bih1, pGi,
                                                                     N_GRAPHS, 768, 256);
    gru_act_kernel<<<(N_GRAPHS * GRUH + 255) / 256, 256>>>(pGi, bhh1, pH2);
    // projection
    sgemm_small_kernel<<<dim3(N_GRAPHS / SG_BM, 512 / SG_BN), 256>>>(pH2, proj_w, proj_b, out,
                                                                     N_GRAPHS, 512, 256);
}

// round 14
// speedup vs baseline: 1.6985x; 1.0908x over previous
#include <cuda_runtime.h>
#include <cuda_fp16.h>
#include <math.h>
#include <stdint.h>

#define N_NODES  50000
#define N_EDGES  800000
#define N_GRAPHS 256
#define DMAX     512
#define GRUH     256
#define NPART    196   // ceil(50000/256)

// weight segments (halves): L0 64x128, L1 128x256, L2 256x512
#define WOFF0 0
#define WOFF1 8192
#define WOFF2 40960
#define WTOT  172032

// ---------------- scratch (device globals; no allocation allowed) ----------------
__device__ __align__(16) __half g_hbuf[(size_t)N_NODES * DMAX];   // layer outputs / xh (fp16)
__device__ __align__(16) __half g_abuf[(size_t)N_NODES * 256];    // agg outputs / GEMM A (fp16)
__device__ __align__(16) __half g_bwh[WTOT];                      // weights fp16, [n][k]
__device__ float g_dinv[N_NODES];
__device__ int   g_counts[N_NODES];
__device__ int   g_rank[N_EDGES];
__device__ int   g_offs[N_NODES + 1];
__device__ int   g_part[NPART];
__device__ int   g_csrc[N_EDGES];
__device__ int   g_gcounts[N_GRAPHS];
__device__ int   g_goffs[N_GRAPHS + 1];
__device__ float g_gate[N_NODES];
__device__ __align__(16) float g_emb[N_GRAPHS * 512];
__device__ float g_h1[N_GRAPHS * GRUH];
__device__ float g_h2[N_GRAPHS * GRUH];
__device__ int   g_is64;

__device__ __forceinline__ int load_idx(const void* p, long long i, int is64) {
    return is64 ? (int)((const long long*)p)[i] : ((const int*)p)[i];
}

// ------- init: detect width (per block), zero counters, seed gate bias,
//         x -> fp16, convert weights, count batch sizes — one launch -------
__global__ void init_kernel(const int* __restrict__ ei_raw, const float* __restrict__ gb,
                            const float* __restrict__ x, __half* __restrict__ xh,
                            const void* __restrict__ batch,
                            const float* __restrict__ w0, const float* __restrict__ w1,
                            const float* __restrict__ w2) {
    __shared__ int s_is64;
    // every block computes is64 from the same 128 ints (L2-broadcast, cheap)
    if (threadIdx.x < 32) {
        int lane = threadIdx.x;
        int bad = 0;
#pragma unroll
        for (int k = 0; k < 4; k++) bad |= ei_raw[2 * (lane + k * 32) + 1];
        unsigned m = __ballot_sync(0xffffffffu, bad != 0);
        if (lane == 0) {
            s_is64 = (m == 0) ? 1 : 0;
            if (blockIdx.x == 0) g_is64 = s_is64;
        }
    }
    __syncthreads();
    int is64 = s_is64;

    int i = blockIdx.x * blockDim.x + threadIdx.x;
    int stride = gridDim.x * blockDim.x;
    float gbias = gb[0];
    for (int k = i; k < N_NODES; k += stride) {
        g_counts[k] = 0; g_gate[k] = gbias;
    }
    for (int k = i; k < N_GRAPHS; k += stride) g_gcounts[k] = 0;
    // batch histogram (needs is64)
    for (int v = i; v < N_NODES; v += stride) {
        int b = load_idx(batch, v, is64);
        atomicAdd(&g_gcounts[b], 1);
    }
    // x (50000x64 fp32) -> fp16
    int total2 = N_NODES * 32;
    const float2* x2 = (const float2*)x;
    __half2* xh2 = (__half2*)xh;
    for (int k = i; k < total2; k += stride) {
        float2 v = x2[k];
        xh2[k] = __floats2half2_rn(v.x, v.y);
    }
    // weights -> fp16 transposed [n][k]
    for (int k = i; k < WTOT; k += stride) {
        const float* B; int K, N, idx;
        if (k < WOFF1)      { B = w0; K = 64;  N = 128; idx = k - WOFF0; }
        else if (k < WOFF2) { B = w1; K = 128; N = 256; idx = k - WOFF1; }
        else                { B = w2; K = 256; N = 512; idx = k - WOFF2; }
        int n = idx / K, kk = idx - n * K;
        g_bwh[k] = __float2half_rn(B[(size_t)kk * N + n]);
    }
}

// ---------- count degrees; record each edge's rank within its dst bucket ----------
__global__ void count_kernel(const void* __restrict__ ei) {
    int is64 = g_is64;
    int i = blockIdx.x * blockDim.x + threadIdx.x;
    int stride = gridDim.x * blockDim.x;
    for (int e = i; e < N_EDGES; e += stride) {
        int d = load_idx(ei, (long long)N_EDGES + e, is64);   // dst = edge_index[1]
        g_rank[e] = atomicAdd(&g_counts[d], 1);
    }
}

// -------- hierarchical exclusive scan of g_counts -> g_offs (+ fused dinv) --------
__global__ void __launch_bounds__(256) part_sum_kernel() {
    __shared__ int red[8];
    int b = blockIdx.x, t = threadIdx.x;
    int i = b * 256 + t;
    int cnt = (i < N_NODES) ? g_counts[i] : 0;
    if (i < N_NODES) g_dinv[i] = rsqrtf((float)(cnt + 1));  // +1 self-loop
    int v = cnt;
#pragma unroll
    for (int o = 16; o > 0; o >>= 1) v += __shfl_xor_sync(0xffffffffu, v, o);
    if ((t & 31) == 0) red[t >> 5] = v;
    __syncthreads();
    if (t == 0) {
        int s = 0;
#pragma unroll
        for (int w = 0; w < 8; w++) s += red[w];
        g_part[b] = s;
    }
}

__global__ void __launch_bounds__(256) scan_parts_kernel() {
    __shared__ int sh[256];
    int t = threadIdx.x;
    int v = (t < NPART) ? g_part[t] : 0;
    sh[t] = v;
    __syncthreads();
    for (int d = 1; d < 256; d <<= 1) {
        int x = (t >= d) ? sh[t - d] : 0;
        __syncthreads();
        sh[t] += x;
        __syncthreads();
    }
    if (t < NPART) g_part[t] = sh[t] - v;
    __syncthreads();
    int gc = g_gcounts[t];
    sh[t] = gc;
    __syncthreads();
    for (int d = 1; d < 256; d <<= 1) {
        int x = (t >= d) ? sh[t - d] : 0;
        __syncthreads();
        sh[t] += x;
        __syncthreads();
    }
    g_goffs[t] = sh[t] - gc;
    if (t == 255) g_goffs[256] = sh[255];
}

__global__ void __launch_bounds__(256) final_scan_kernel() {
    __shared__ int sh[256];
    int b = blockIdx.x, t = threadIdx.x;
    int i = b * 256 + t;
    int v = (i < N_NODES) ? g_counts[i] : 0;
    sh[t] = v;
    __syncthreads();
    for (int d = 1; d < 256; d <<= 1) {
        int x = (t >= d) ? sh[t - d] : 0;
        __syncthreads();
        sh[t] += x;
        __syncthreads();
    }
    int base = g_part[b];
    if (i < N_NODES) g_offs[i] = base + sh[t] - v;
    if (i == N_NODES - 1) g_offs[N_NODES] = base + sh[t];
}

// ---------- CSR fill: atomic-free (uses precomputed ranks) ----------
__global__ void fill_kernel(const void* __restrict__ ei) {
    int is64 = g_is64;
    int i = blockIdx.x * blockDim.x + threadIdx.x;
    int stride = gridDim.x * blockDim.x;
    for (int e = i; e < N_EDGES; e += stride) {
        int d = load_idx(ei, (long long)N_EDGES + e, is64);
        int s = load_idx(ei, e, is64);
        g_csrc[g_offs[d] + g_rank[e]] = s;
    }
}

// ------------- GCN aggregation BEFORE transform; fp16 in / fp16 out; MLP=4 -------------
__global__ void __launch_bounds__(256) agg64h_kernel(const __half* __restrict__ h,
                                                     __half* __restrict__ out)
{
    int node = blockIdx.x * 8 + (threadIdx.x >> 5);
    if (node >= N_NODES) return;
    int lane = threadIdx.x & 31;
    float wd = g_dinv[node];
    float2 acc = __half22float2(*(const __half2*)(h + (size_t)node * 64 + lane * 2));
    float ws = wd * wd;
    acc.x *= ws; acc.y *= ws;
    int e = g_offs[node], e1 = g_offs[node + 1];
    for (; e + 4 <= e1; e += 4) {
        int s0 = g_csrc[e], s1 = g_csrc[e + 1], s2 = g_csrc[e + 2], s3 = g_csrc[e + 3];
        float w0 = g_dinv[s0] * wd, w1 = g_dinv[s1] * wd;
        float w2 = g_dinv[s2] * wd, w3 = g_dinv[s3] * wd;
        float2 v0 = __half22float2(*(const __half2*)(h + (size_t)s0 * 64 + lane * 2));
        float2 v1 = __half22float2(*(const __half2*)(h + (size_t)s1 * 64 + lane * 2));
        float2 v2 = __half22float2(*(const __half2*)(h + (size_t)s2 * 64 + lane * 2));
        float2 v3 = __half22float2(*(const __half2*)(h + (size_t)s3 * 64 + lane * 2));
        acc.x += v0.x * w0 + v1.x * w1 + v2.x * w2 + v3.x * w3;
        acc.y += v0.y * w0 + v1.y * w1 + v2.y * w2 + v3.y * w3;
    }
    for (; e < e1; e++) {
        int s0 = g_csrc[e];
        float w0 = g_dinv[s0] * wd;
        float2 v0 = __half22float2(*(const __half2*)(h + (size_t)s0 * 64 + lane * 2));
        acc.x += v0.x * w0; acc.y += v0.y * w0;
    }
    *(__half2*)(out + (size_t)node * 64 + lane * 2) = __floats2half2_rn(acc.x, acc.y);
}

__global__ void __launch_bounds__(256) agg128h_kernel(const __half* __restrict__ h,
                                                      __half* __restrict__ out)
{
    int node = blockIdx.x * 8 + (threadIdx.x >> 5);
    if (node >= N_NODES) return;
    int lane = threadIdx.x & 31;
    float wd = g_dinv[node];
    float acc[4];
    {
        uint2 sv = *(const uint2*)(h + (size_t)node * 128 + lane * 4);
        const __half2* hp = (const __half2*)&sv;
        float ws = wd * wd;
        float2 f0 = __half22float2(hp[0]), f1 = __half22float2(hp[1]);
        acc[0] = f0.x * ws; acc[1] = f0.y * ws; acc[2] = f1.x * ws; acc[3] = f1.y * ws;
    }
    int e = g_offs[node], e1 = g_offs[node + 1];
    for (; e + 4 <= e1; e += 4) {
        int s0 = g_csrc[e], s1 = g_csrc[e + 1], s2 = g_csrc[e + 2], s3 = g_csrc[e + 3];
        float w0 = g_dinv[s0] * wd, w1 = g_dinv[s1] * wd;
        float w2 = g_dinv[s2] * wd, w3 = g_dinv[s3] * wd;
        uint2 v0 = *(const uint2*)(h + (size_t)s0 * 128 + lane * 4);
        uint2 v1 = *(const uint2*)(h + (size_t)s1 * 128 + lane * 4);
        uint2 v2 = *(const uint2*)(h + (size_t)s2 * 128 + lane * 4);
        uint2 v3 = *(const uint2*)(h + (size_t)s3 * 128 + lane * 4);
        const __half2* p0 = (const __half2*)&v0;
        const __half2* p1 = (const __half2*)&v1;
        const __half2* p2 = (const __half2*)&v2;
        const __half2* p3 = (const __half2*)&v3;
#pragma unroll
        for (int q = 0; q < 2; q++) {
            float2 f0 = __half22float2(p0[q]);
            float2 f1 = __half22float2(p1[q]);
            float2 f2 = __half22float2(p2[q]);
            float2 f3 = __half22float2(p3[q]);
            acc[2 * q]     += f0.x * w0 + f1.x * w1 + f2.x * w2 + f3.x * w3;
            acc[2 * q + 1] += f0.y * w0 + f1.y * w1 + f2.y * w2 + f3.y * w3;
        }
    }
    for (; e < e1; e++) {
        int s0 = g_csrc[e];
        float w0 = g_dinv[s0] * wd;
        uint2 v0 = *(const uint2*)(h + (size_t)s0 * 128 + lane * 4);
        const __half2* p0 = (const __half2*)&v0;
#pragma unroll
        for (int q = 0; q < 2; q++) {
            float2 f0 = __half22float2(p0[q]);
            acc[2 * q] += f0.x * w0;
            acc[2 * q + 1] += f0.y * w0;
        }
    }
    __half2 o0 = __floats2half2_rn(acc[0], acc[1]);
    __half2 o1 = __floats2half2_rn(acc[2], acc[3]);
    uint2 ov = make_uint2(*(uint32_t*)&o0, *(uint32_t*)&o1);
    *(uint2*)(out + (size_t)node * 128 + lane * 4) = ov;
}

__global__ void __launch_bounds__(256) agg256h_kernel(const __half* __restrict__ h,
                                                      __half* __restrict__ out)
{
    int node = blockIdx.x * 8 + (threadIdx.x >> 5);
    if (node >= N_NODES) return;
    int lane = threadIdx.x & 31;
    float wd = g_dinv[node];
    float acc[8];
    {
        uint4 sv = *(const uint4*)(h + (size_t)node * 256 + lane * 8);
        const __half2* hp = (const __half2*)&sv;
        float ws = wd * wd;
#pragma unroll
        for (int q = 0; q < 4; q++) {
            float2 f = __half22float2(hp[q]);
            acc[2 * q] = f.x * ws;
            acc[2 * q + 1] = f.y * ws;
        }
    }
    int e = g_offs[node], e1 = g_offs[node + 1];
    for (; e + 4 <= e1; e += 4) {
        int s0 = g_csrc[e], s1 = g_csrc[e + 1], s2 = g_csrc[e + 2], s3 = g_csrc[e + 3];
        float w0 = g_dinv[s0] * wd, w1 = g_dinv[s1] * wd;
        float w2 = g_dinv[s2] * wd, w3 = g_dinv[s3] * wd;
        uint4 v0 = *(const uint4*)(h + (size_t)s0 * 256 + lane * 8);
        uint4 v1 = *(const uint4*)(h + (size_t)s1 * 256 + lane * 8);
        uint4 v2 = *(const uint4*)(h + (size_t)s2 * 256 + lane * 8);
        uint4 v3 = *(const uint4*)(h + (size_t)s3 * 256 + lane * 8);
        const __half2* p0 = (const __half2*)&v0;
        const __half2* p1 = (const __half2*)&v1;
        const __half2* p2 = (const __half2*)&v2;
        const __half2* p3 = (const __half2*)&v3;
#pragma unroll
        for (int q = 0; q < 4; q++) {
            float2 f0 = __half22float2(p0[q]);
            float2 f1 = __half22float2(p1[q]);
            float2 f2 = __half22float2(p2[q]);
            float2 f3 = __half22float2(p3[q]);
            acc[2 * q]     += f0.x * w0 + f1.x * w1 + f2.x * w2 + f3.x * w3;
            acc[2 * q + 1] += f0.y * w0 + f1.y * w1 + f2.y * w2 + f3.y * w3;
        }
    }
    for (; e < e1; e++) {
        int n0 = g_csrc[e];
        float w0 = g_dinv[n0] * wd;
        uint4 v0 = *(const uint4*)(h + (size_t)n0 * 256 + lane * 8);
        const __half2* p0 = (const __half2*)&v0;
#pragma unroll
        for (int q = 0; q < 4; q++) {
            float2 f0 = __half22float2(p0[q]);
            acc[2 * q]     += f0.x * w0;
            acc[2 * q + 1] += f0.y * w0;
        }
    }
    __half2 o0 = __floats2half2_rn(acc[0], acc[1]);
    __half2 o1 = __floats2half2_rn(acc[2], acc[3]);
    __half2 o2 = __floats2half2_rn(acc[4], acc[5]);
    __half2 o3 = __floats2half2_rn(acc[6], acc[7]);
    uint4 ov = make_uint4(*(uint32_t*)&o0, *(uint32_t*)&o1, *(uint32_t*)&o2, *(uint32_t*)&o3);
    *(uint4*)(out + (size_t)node * 256 + lane * 8) = ov;
}

// ---------------- fp16 mma ----------------
__device__ __forceinline__ void mma_f16(float* c, const uint32_t* a, const uint32_t* b) {
    asm volatile(
        "mma.sync.aligned.m16n8k16.row.col.f32.f16.f16.f32 "
        "{%0,%1,%2,%3}, {%4,%5,%6,%7}, {%8,%9}, {%0,%1,%2,%3};"
        : "+f"(c[0]), "+f"(c[1]), "+f"(c[2]), "+f"(c[3])
        : "r"(a[0]), "r"(a[1]), "r"(a[2]), "r"(a[3]), "r"(b[0]), "r"(b[1]));
}

// ---- GEMM + bias + ReLU, fp16 operands, fp32 accum; cp.async double-buffered ----
#define HSTR 40

__global__ void __launch_bounds__(256) gemm_f16_kernel(
    const __half* __restrict__ A, const __half* __restrict__ Bh,
    const float* __restrict__ bias,
    __half* __restrict__ Ch, const float* __restrict__ gatew,
    int M, int N, int K)
{
    __shared__ __align__(16) __half As[2][128 * HSTR];
    __shared__ __align__(16) __half Bhs[2][128 * HSTR];
    __shared__ float sgate[128];

    int tid = threadIdx.x;
    int lane = tid & 31;
    int wid = tid >> 5;
    int warp_m = wid >> 2;
    int warp_n = wid & 3;
    int g = lane >> 2;
    int t = lane & 3;
    int row0 = blockIdx.x * 128;
    int col0 = blockIdx.y * 128;

    if (gatew && tid < 128) sgate[tid] = 0.f;

    float acc[4][4][4];
#pragma unroll
    for (int i = 0; i < 4; i++)
#pragma unroll
        for (int j = 0; j < 4; j++)
#pragma unroll
            for (int r = 0; r < 4; r++) acc[i][j][r] = 0.f;

    int f0 = tid, f1 = tid + 256;
    int ar0 = f0 >> 2, ac0 = (f0 & 3) * 8;
    int ar1 = f1 >> 2, ac1 = (f1 & 3) * 8;

    auto issue_tile = [&](int buf, int k0) {
        {
            int grow = row0 + ar0;
            uint32_t dst = (uint32_t)__cvta_generic_to_shared(&As[buf][ar0 * HSTR + ac0]);
            const __half* src = A + (size_t)grow * K + k0 + ac0;
            int p = (grow < M) ? 16 : 0;
            asm volatile("cp.async.cg.shared.global [%0], [%1], 16, %2;"
                         :: "r"(dst), "l"(src), "r"(p));
        }
        {
            int grow = row0 + ar1;
            uint32_t dst = (uint32_t)__cvta_generic_to_shared(&As[buf][ar1 * HSTR + ac1]);
            const __half* src = A + (size_t)grow * K + k0 + ac1;
            int p = (grow < M) ? 16 : 0;
            asm volatile("cp.async.cg.shared.global [%0], [%1], 16, %2;"
                         :: "r"(dst), "l"(src), "r"(p));
        }
        {
            uint32_t dst = (uint32_t)__cvta_generic_to_shared(&Bhs[buf][ar0 * HSTR + ac0]);
            const __half* src = Bh + (size_t)(col0 + ar0) * K + k0 + ac0;
            asm volatile("cp.async.cg.shared.global [%0], [%1], 16;"
                         :: "r"(dst), "l"(src));
        }
        {
            uint32_t dst = (uint32_t)__cvta_generic_to_shared(&Bhs[buf][ar1 * HSTR + ac1]);
            const __half* src = Bh + (size_t)(col0 + ar1) * K + k0 + ac1;
            asm volatile("cp.async.cg.shared.global [%0], [%1], 16;"
                         :: "r"(dst), "l"(src));
        }
        asm volatile("cp.async.commit_group;");
    };

    int nIter = K >> 5;
    issue_tile(0, 0);
    int buf = 0;
    for (int it = 0; it < nIter; it++) {
        if (it + 1 < nIter) {
            issue_tile(buf ^ 1, (it + 1) * 32);
            asm volatile("cp.async.wait_group 1;");
        } else {
            asm volatile("cp.async.wait_group 0;");
        }
        __syncthreads();

        const __half* Ab = As[buf];
        const __half* Bb = Bhs[buf];
#pragma unroll
        for (int kc = 0; kc < 2; kc++) {
            uint32_t bh[4][2];
#pragma unroll
            for (int tn = 0; tn < 4; tn++) {
                int n = warp_n * 32 + tn * 8 + g;
                int base = n * HSTR + kc * 16 + 2 * t;
                bh[tn][0] = *(const uint32_t*)&Bb[base];
                bh[tn][1] = *(const uint32_t*)&Bb[base + 8];
            }
#pragma unroll
            for (int tm = 0; tm < 4; tm++) {
                int row = warp_m * 64 + tm * 16 + g;
                int base = row * HSTR + kc * 16 + 2 * t;
                uint32_t a[4];
                a[0] = *(const uint32_t*)&Ab[base];
                a[1] = *(const uint32_t*)&Ab[base + 8 * HSTR];
                a[2] = *(const uint32_t*)&Ab[base + 8];
                a[3] = *(const uint32_t*)&Ab[base + 8 * HSTR + 8];
#pragma unroll
                for (int tn = 0; tn < 4; tn++) {
                    mma_f16(acc[tm][tn], a, bh[tn]);
                }
            }
        }
        __syncthreads();
        buf ^= 1;
    }

    float bv[4][2], gwv[4][2];
#pragma unroll
    for (int tn = 0; tn < 4; tn++) {
        int col = col0 + warp_n * 32 + tn * 8 + 2 * t;
        bv[tn][0] = bias[col];
        bv[tn][1] = bias[col + 1];
        if (gatew) { gwv[tn][0] = gatew[col]; gwv[tn][1] = gatew[col + 1]; }
    }
#pragma unroll
    for (int tm = 0; tm < 4; tm++) {
        int row = row0 + warp_m * 64 + tm * 16 + g;
        float p0 = 0.f, p1 = 0.f;
#pragma unroll
        for (int tn = 0; tn < 4; tn++) {
            int col = col0 + warp_n * 32 + tn * 8 + 2 * t;
            float v0 = fmaxf(acc[tm][tn][0] + bv[tn][0], 0.f);
            float v1 = fmaxf(acc[tm][tn][1] + bv[tn][1], 0.f);
            float v2 = fmaxf(acc[tm][tn][2] + bv[tn][0], 0.f);
            float v3 = fmaxf(acc[tm][tn][3] + bv[tn][1], 0.f);
            if (row < M)     *(__half2*)(Ch + (size_t)row * N + col)       = __floats2half2_rn(v0, v1);
            if (row + 8 < M) *(__half2*)(Ch + (size_t)(row + 8) * N + col) = __floats2half2_rn(v2, v3);
            if (gatew) {
                p0 += v0 * gwv[tn][0] + v1 * gwv[tn][1];
                p1 += v2 * gwv[tn][0] + v3 * gwv[tn][1];
            }
        }
        if (gatew) {
            p0 += __shfl_xor_sync(0xffffffffu, p0, 1);
            p0 += __shfl_xor_sync(0xffffffffu, p0, 2);
            p1 += __shfl_xor_sync(0xffffffffu, p1, 1);
            p1 += __shfl_xor_sync(0xffffffffu, p1, 2);
            if (t == 0) {
                int rl = warp_m * 64 + tm * 16 + g;
                atomicAdd(&sgate[rl], p0);
                atomicAdd(&sgate[rl + 8], p1);
            }
        }
    }
    if (gatew) {
        __syncthreads();
        if (tid < 128 && row0 + tid < M) atomicAdd(&g_gate[row0 + tid], sgate[tid]);
    }
}

// ------- segment softmax + weighted sum over fp16 x -> graph embeddings [G, 512] -------
__global__ void __launch_bounds__(256) softmax_emb_kernel(const __half* __restrict__ xh)
{
    __shared__ float red[8];
    __shared__ float salpha[256];
    __shared__ float bcast;
    int g = blockIdx.x, tid = threadIdx.x;
    int lane = tid & 31, wid = tid >> 5;
    int s = g_goffs[g], e = g_goffs[g + 1];

    float m = -INFINITY;
    for (int i = s + tid; i < e; i += 256) m = fmaxf(m, g_gate[i]);
#pragma unroll
    for (int o = 16; o > 0; o >>= 1) m = fmaxf(m, __shfl_xor_sync(0xffffffffu, m, o));
    if (lane == 0) red[wid] = m;
    __syncthreads();
    if (wid == 0) {
        float x = (lane < 8) ? red[lane] : -INFINITY;
#pragma unroll
        for (int o = 4; o > 0; o >>= 1) x = fmaxf(x, __shfl_xor_sync(0xffffffffu, x, o));
        if (lane == 0) bcast = x;
    }
    __syncthreads();
    m = bcast;

    float sum = 0.f;
    for (int i = s + tid; i < e; i += 256) sum += expf(g_gate[i] - m);
#pragma unroll
    for (int o = 16; o > 0; o >>= 1) sum += __shfl_xor_sync(0xffffffffu, sum, o);
    if (lane == 0) red[wid] = sum;
    __syncthreads();
    if (wid == 0) {
        float x = (lane < 8) ? red[lane] : 0.f;
#pragma unroll
        for (int o = 4; o > 0; o >>= 1) x += __shfl_xor_sync(0xffffffffu, x, o);
        if (lane == 0) bcast = x;
    }
    __syncthreads();
    float inv = (e > s) ? 1.f / bcast : 0.f;

    float2 acc = make_float2(0.f, 0.f);
    for (int start = s; start < e; start += 256) {
        int i = start + tid;
        salpha[tid] = (i < e) ? expf(g_gate[i] - m) * inv : 0.f;
        __syncthreads();
        int cnt = min(256, e - start);
        const __half2* base = (const __half2*)(xh + (size_t)start * 512);
        for (int k = 0; k < cnt; k++) {
            float a = salpha[k];
            float2 f = __half22float2(base[(size_t)k * 256 + tid]);
            acc.x += f.x * a;
            acc.y += f.y * a;
        }
        __syncthreads();
    }
    g_emb[g * 512 + 2 * tid]     = acc.x;
    g_emb[g * 512 + 2 * tid + 1] = acc.y;
}

// ---- fused GRU layer: h[g,c] = (1-z)*n, gi = A@wih^T (+bih), gh bias = bhh; h0=0 ----
// tiles: 32 graphs x 16 units; CTA computes all 3 gates for its 16 units. BK=32.
#define GF_BK 32

__global__ void __launch_bounds__(256) gru_fused_kernel(
    const float* __restrict__ A, const float* __restrict__ W,
    const float* __restrict__ bih, const float* __restrict__ bhh,
    float* __restrict__ hout, int K)
{
    __shared__ float As[GF_BK][33];
    __shared__ float Ws[3][16][GF_BK + 1];
    int tid = threadIdx.x;
    int row0 = blockIdx.x * 32;
    int c0 = blockIdx.y * 16;
    int tn = tid & 15, tm = tid >> 4;
    float acc[3][2] = {};

    for (int k0 = 0; k0 < K; k0 += GF_BK) {
        // A tile: 32 rows x 32 k
#pragma unroll
        for (int l = 0; l < 4; l++) {
            int f = tid + l * 256;
            int r = f >> 5, c = f & 31;
            As[c][r] = A[(size_t)(row0 + r) * K + k0 + c];
        }
        // W tiles: 3 gates x 16 rows x 32 k
#pragma unroll
        for (int l = 0; l < 6; l++) {
            int f = tid + l * 256;
            int gate = f >> 9;
            int rem = f & 511;
            int n = rem >> 5, c = rem & 31;
            Ws[gate][n][c] = W[(size_t)(gate * 256 + c0 + n) * K + k0 + c];
        }
        __syncthreads();
#pragma unroll
        for (int k = 0; k < GF_BK; k++) {
            float a0 = As[k][tm * 2];
            float a1 = As[k][tm * 2 + 1];
            float wr = Ws[0][tn][k], wz = Ws[1][tn][k], wn = Ws[2][tn][k];
            acc[0][0] += a0 * wr; acc[0][1] += a1 * wr;
            acc[1][0] += a0 * wz; acc[1][1] += a1 * wz;
            acc[2][0] += a0 * wn; acc[2][1] += a1 * wn;
        }
        __syncthreads();
    }

    int c = c0 + tn;
    float br = bih[c] + bhh[c];
    float bz = bih[c + 256] + bhh[c + 256];
    float bn_i = bih[c + 512];
    float bn_h = bhh[c + 512];
#pragma unroll
    for (int i = 0; i < 2; i++) {
        int g = row0 + tm * 2 + i;
        float r = 1.f / (1.f + expf(-(acc[0][i] + br)));
        float z = 1.f / (1.f + expf(-(acc[1][i] + bz)));
        float n = tanhf(acc[2][i] + bn_i + r * bn_h);
        hout[g * GRUH + c] = (1.f - z) * n;
    }
}

// ---- projection GEMM: out[G,N] = A[G,K] @ W[N,K]^T + bias; tiles 32x64, BK=32 ----
__global__ void __launch_bounds__(256) proj_gemm_kernel(
    const float* __restrict__ A, const float* __restrict__ W,
    const float* __restrict__ bias, float* __restrict__ C,
    int N, int K)
{
    __shared__ float As[32][33];
    __shared__ float Ws[64][33];
    int tid = threadIdx.x;
    int row0 = blockIdx.x * 32;
    int col0 = blockIdx.y * 64;
    int tn = tid & 15, tm = tid >> 4;
    float acc[2][4] = {};

    for (int k0 = 0; k0 < K; k0 += 32) {
#pragma unroll
        for (int l = 0; l < 4; l++) {
            int f = tid + l * 256;
            int r = f >> 5, c = f & 31;
            As[c][r] = A[(size_t)(row0 + r) * K + k0 + c];
        }
#pragma unroll
        for (int l = 0; l < 8; l++) {
            int f = tid + l * 256;
            int n = f >> 5, c = f & 31;
            Ws[n][c] = W[(size_t)(col0 + n) * K + k0 + c];
        }
        __syncthreads();
#pragma unroll
        for (int k = 0; k < 32; k++) {
            float a0 = As[k][tm * 2];
            float a1 = As[k][tm * 2 + 1];
#pragma unroll
            for (int j = 0; j < 4; j++) {
                float b = Ws[tn * 4 + j][k];
                acc[0][j] += a0 * b;
                acc[1][j] += a1 * b;
            }
        }
        __syncthreads();
    }
#pragma unroll
    for (int i = 0; i < 2; i++) {
        int gg = row0 + tm * 2 + i;
#pragma unroll
        for (int j = 0; j < 4; j++) {
            int nn = col0 + tn * 4 + j;
            C[(size_t)gg * N + nn] = acc[i][j] + bias[nn];
        }
    }
}

// ---------------- launch ----------------
extern "C" void kernel_launch(void* const* d_in, const int* in_sizes, int n_in,
                              void* d_out, int out_size)
{
    const float* x       = (const float*)d_in[0];
    const void*  ei      = d_in[1];
    const void*  batch   = d_in[2];
    const float* w0 = (const float*)d_in[3];  const float* b0 = (const float*)d_in[4];
    const float* w1 = (const float*)d_in[5];  const float* b1 = (const float*)d_in[6];
    const float* w2 = (const float*)d_in[7];  const float* b2 = (const float*)d_in[8];
    const float* gate_w = (const float*)d_in[9];
    const float* gate_b = (const float*)d_in[10];
    const float* wih0 = (const float*)d_in[11];
    const float* bih0 = (const float*)d_in[13];
    const float* bhh0 = (const float*)d_in[14];
    const float* wih1 = (const float*)d_in[15];
    const float* bih1 = (const float*)d_in[17];
    const float* bhh1 = (const float*)d_in[18];
    const float* proj_w = (const float*)d_in[19];
    const float* proj_b = (const float*)d_in[20];
    float* out = (float*)d_out;

    __half *pH, *pA, *pWh;
    float *pEmb, *pH1, *pH2;
    cudaGetSymbolAddress((void**)&pH,   g_hbuf);
    cudaGetSymbolAddress((void**)&pA,   g_abuf);
    cudaGetSymbolAddress((void**)&pWh,  g_bwh);
    cudaGetSymbolAddress((void**)&pEmb, g_emb);
    cudaGetSymbolAddress((void**)&pH1,  g_h1);
    cudaGetSymbolAddress((void**)&pH2,  g_h2);

    // preprocessing (init: detect + clears + gate seed + x->fp16 + weights + batch hist)
    init_kernel<<<256, 256>>>((const int*)ei, gate_b, x, pH, batch, w0, w1, w2);
    count_kernel<<<1024, 256>>>(ei);
    part_sum_kernel<<<NPART, 256>>>();
    scan_parts_kernel<<<1, 256>>>();
    final_scan_kernel<<<NPART, 256>>>();
    fill_kernel<<<1024, 256>>>(ei);

    int gM = (N_NODES + 127) / 128;
    int gAgg = (N_NODES + 7) / 8;

    // GCN layers (fp16 agg -> fp16 GEMM, cp.async pipelined)
    agg64h_kernel<<<gAgg, 256>>>(pH, pA);
    gemm_f16_kernel<<<dim3(gM, 1), 256>>>(pA, pWh + WOFF0, b0, pH, nullptr,
                                          N_NODES, 128, 64);
    agg128h_kernel<<<gAgg, 256>>>(pH, pA);
    gemm_f16_kernel<<<dim3(gM, 2), 256>>>(pA, pWh + WOFF1, b1, pH, nullptr,
                                          N_NODES, 256, 128);
    agg256h_kernel<<<gAgg, 256>>>(pH, pA);
    gemm_f16_kernel<<<dim3(gM, 4), 256>>>(pA, pWh + WOFF2, b2, pH, gate_w,
                                          N_NODES, 512, 256);

    // attentional aggregation
    softmax_emb_kernel<<<N_GRAPHS, 256>>>(pH);

    // fused GRU layers + projection
    gru_fused_kernel<<<dim3(N_GRAPHS / 32, GRUH / 16), 256>>>(pEmb, wih0, bih0, bhh0, pH1, 512);
    gru_fused_kernel<<<dim3(N_GRAPHS / 32, GRUH / 16), 256>>>(pH1, wih1, bih1, bhh1, pH2, 256);
    proj_gemm_kernel<<<dim3(N_GRAPHS / 32, 512 / 64), 256>>>(pH2, proj_w, proj_b, out, 512, 256);
}